// round 6
// baseline (speedup 1.0000x reference)
#include <cuda_runtime.h>
#include <cuda_bf16.h>
#include <math.h>
#include <stdint.h>

#define BB 64
#define TT 2048
#define HH 512
#define EE 256
#define VV 50000
#define G4H 2048   /* 4*H  */
#define K2H 1024   /* 2*H  */

// ---------------- scratch (device globals; no allocation) ----------------
__device__ float g_dec[BB * HH];          // h @ W_dec.T          (B,H)
__device__ float g_scores[BB * TT];       // attention scores     (B,T)
__device__ float g_attn[BB * TT];         // softmax(scores)      (B,T)
__device__ float g_ctxp[8 * BB * HH];     // context partials     (8,B,H)
__device__ float g_ctx[BB * HH];          // context              (B,H)
__device__ float g_gates[BB * G4H];       // LSTM gates           (B,4H)
// split-bf16 operands for the scores GEMM
__device__ __nv_bfloat16 g_Ah[(size_t)BB * TT * HH];  // 128 MB
__device__ __nv_bfloat16 g_Al[(size_t)BB * TT * HH];  // 128 MB
__device__ __nv_bfloat16 g_Wh[HH * HH];
__device__ __nv_bfloat16 g_Wl[HH * HH];
// split-bf16 operands for the logits GEMM
__device__ __nv_bfloat16 g_Wouth[(size_t)VV * K2H];   // 102.4 MB
__device__ __nv_bfloat16 g_Woutl[(size_t)VV * K2H];   // 102.4 MB
__device__ __nv_bfloat16 g_Xh[BB * K2H];              // [h_new, ctx] hi
__device__ __nv_bfloat16 g_Xl[BB * K2H];              // [h_new, ctx] lo

// ---------------- packed f32x2 helpers (FFMA2 path, small GEMMs) ----------------
__device__ __forceinline__ unsigned long long pk2(float lo, float hi) {
    unsigned long long r;
    asm("mov.b64 %0, {%1, %2};" : "=l"(r)
        : "r"(__float_as_uint(lo)), "r"(__float_as_uint(hi)));
    return r;
}
__device__ __forceinline__ unsigned long long pkdup(float v) {
    unsigned long long r;
    asm("mov.b64 %0, {%1, %1};" : "=l"(r) : "r"(__float_as_uint(v)));
    return r;
}
__device__ __forceinline__ void fma2(unsigned long long& d,
                                     unsigned long long a,
                                     unsigned long long b) {
    asm("fma.rn.f32x2 %0, %1, %2, %0;" : "+l"(d) : "l"(a), "l"(b));
}
__device__ __forceinline__ float2 upk2(unsigned long long v) {
    unsigned int lo, hi;
    asm("mov.b64 {%0, %1}, %2;" : "=r"(lo), "=r"(hi) : "l"(v));
    return make_float2(__uint_as_float(lo), __uint_as_float(hi));
}
__device__ __forceinline__ float sigf(float x) { return 1.f / (1.f + expf(-x)); }

// ---------------- smem / async / mma helpers (baseline PTX, sm_80+) ----------------
__device__ __forceinline__ uint32_t smem_u32(const void* p) {
    uint32_t a;
    asm("{ .reg .u64 t; cvta.to.shared.u64 t, %1; cvt.u32.u64 %0, t; }"
        : "=r"(a) : "l"(p));
    return a;
}
__device__ __forceinline__ void cpa16(uint32_t dst, const void* src) {
    asm volatile("cp.async.cg.shared.global [%0], [%1], 16;" :: "r"(dst), "l"(src));
}
#define CPA_COMMIT() asm volatile("cp.async.commit_group;" ::: "memory")
#define CPA_WAIT1()  asm volatile("cp.async.wait_group 1;" ::: "memory")
__device__ __forceinline__ uint32_t swz(uint32_t off) { return off ^ ((off >> 3) & 0x70); }

__device__ __forceinline__ void ldm4(uint32_t& r0, uint32_t& r1,
                                     uint32_t& r2, uint32_t& r3, uint32_t addr) {
    asm volatile("ldmatrix.sync.aligned.m8n8.x4.shared.b16 {%0,%1,%2,%3}, [%4];"
        : "=r"(r0), "=r"(r1), "=r"(r2), "=r"(r3) : "r"(addr));
}
__device__ __forceinline__ void mma16816(float* d, const uint32_t* a,
                                         const uint32_t* bf) {
    asm volatile("mma.sync.aligned.m16n8k16.row.col.f32.bf16.bf16.f32 "
        "{%0,%1,%2,%3}, {%4,%5,%6,%7}, {%8,%9}, {%0,%1,%2,%3};"
        : "+f"(d[0]), "+f"(d[1]), "+f"(d[2]), "+f"(d[3])
        : "r"(a[0]), "r"(a[1]), "r"(a[2]), "r"(a[3]), "r"(bf[0]), "r"(bf[1]));
}
__device__ __forceinline__ float tanhx(float x) {
    float e2 = __expf(2.f * x);
    return 1.f - __fdividef(2.f, e2 + 1.f);
}

// ================= prep: split fp32 -> (hi, lo) bf16 =================
__global__ void k_split_w(const float* __restrict__ W) {
    int i = blockIdx.x * 256 + threadIdx.x;
    if (i < HH * HH) {
        float x = W[i];
        __nv_bfloat16 h = __float2bfloat16(x);
        g_Wh[i] = h;
        g_Wl[i] = __float2bfloat16(x - __bfloat162float(h));
    }
}
__global__ void k_split_enc(const float* __restrict__ enc) {
    size_t i = (size_t)blockIdx.x * 256 + threadIdx.x;  // x4 vectorized
    float4 v = ((const float4*)enc)[i];
    __nv_bfloat16 h0 = __float2bfloat16(v.x), h1 = __float2bfloat16(v.y);
    __nv_bfloat16 h2 = __float2bfloat16(v.z), h3 = __float2bfloat16(v.w);
    __nv_bfloat162 hp0; hp0.x = h0; hp0.y = h1;
    __nv_bfloat162 hp1; hp1.x = h2; hp1.y = h3;
    ((__nv_bfloat162*)g_Ah)[i * 2 + 0] = hp0;
    ((__nv_bfloat162*)g_Ah)[i * 2 + 1] = hp1;
    __nv_bfloat162 lp0, lp1;
    lp0.x = __float2bfloat16(v.x - __bfloat162float(h0));
    lp0.y = __float2bfloat16(v.y - __bfloat162float(h1));
    lp1.x = __float2bfloat16(v.z - __bfloat162float(h2));
    lp1.y = __float2bfloat16(v.w - __bfloat162float(h3));
    ((__nv_bfloat162*)g_Al)[i * 2 + 0] = lp0;
    ((__nv_bfloat162*)g_Al)[i * 2 + 1] = lp1;
}
__global__ void k_split_wout(const float* __restrict__ W) {
    size_t i = (size_t)blockIdx.x * 256 + threadIdx.x;  // x4 vectorized, exact
    float4 v = ((const float4*)W)[i];
    __nv_bfloat16 h0 = __float2bfloat16(v.x), h1 = __float2bfloat16(v.y);
    __nv_bfloat16 h2 = __float2bfloat16(v.z), h3 = __float2bfloat16(v.w);
    __nv_bfloat162 hp0; hp0.x = h0; hp0.y = h1;
    __nv_bfloat162 hp1; hp1.x = h2; hp1.y = h3;
    ((__nv_bfloat162*)g_Wouth)[i * 2 + 0] = hp0;
    ((__nv_bfloat162*)g_Wouth)[i * 2 + 1] = hp1;
    __nv_bfloat162 lp0, lp1;
    lp0.x = __float2bfloat16(v.x - __bfloat162float(h0));
    lp0.y = __float2bfloat16(v.y - __bfloat162float(h1));
    lp1.x = __float2bfloat16(v.z - __bfloat162float(h2));
    lp1.y = __float2bfloat16(v.w - __bfloat162float(h3));
    ((__nv_bfloat162*)g_Woutl)[i * 2 + 0] = lp0;
    ((__nv_bfloat162*)g_Woutl)[i * 2 + 1] = lp1;
}

// ================= K1: dec = h @ W_dec.T =================
__global__ void k_dec(const float* __restrict__ hid,
                      const float* __restrict__ Wdec) {
    __shared__ float hs[HH];
    int b = blockIdx.x;
    for (int i = threadIdx.x; i < HH; i += blockDim.x) hs[i] = hid[b * HH + i];
    __syncthreads();
    for (int h = threadIdx.x; h < HH; h += blockDim.x) {
        const float4* w = (const float4*)(Wdec + (size_t)h * HH);
        float a0 = 0.f, a1 = 0.f, a2 = 0.f, a3 = 0.f;
#pragma unroll 4
        for (int k4 = 0; k4 < HH / 4; ++k4) {
            float4 wv = w[k4];
            a0 += hs[k4 * 4 + 0] * wv.x;
            a1 += hs[k4 * 4 + 1] * wv.y;
            a2 += hs[k4 * 4 + 2] * wv.z;
            a3 += hs[k4 * 4 + 3] * wv.w;
        }
        g_dec[b * HH + h] = (a0 + a1) + (a2 + a3);
    }
}

// ================= K2: scores via mma.sync (HMMA) split-bf16 =================
#define SC_SA   0                      // A stages: 2 x 16384
#define SC_SB   32768                  // B stages: 2 x 16384
#define SC_DEC  65536                  // dec row  (2048 B)
#define SC_V    67584                  // v_attn   (2048 B)
#define SC_SC   69632                  // score buf 2x128 floats (1024 B)
#define SC_TOT  70656

__global__ void __launch_bounds__(256, 2)
k_scores_mma(const float* __restrict__ vat) {
    extern __shared__ __align__(1024) char smem[];
    const uint32_t sb = smem_u32(smem);
    float* decs = (float*)(smem + SC_DEC);
    float* vs   = (float*)(smem + SC_V);
    float* sbuf = (float*)(smem + SC_SC);
    const int tid = threadIdx.x, lane = tid & 31, wid = tid >> 5;
    const int wm = wid & 3, wn = wid >> 2;       // warp tile (32 m) x (64 n)
    const int b = blockIdx.x >> 4;
    const int t0 = (blockIdx.x & 15) * 128;

    for (int i = tid; i < HH; i += 256) {
        decs[i] = g_dec[b * HH + i];
        vs[i]   = vat[i];
    }
    __syncthreads();

    auto fill = [&](int st, int it, int n0) {
        const int part = it >> 3, kbase = (it & 7) * 64;
        const __nv_bfloat16* As = (part < 2 ? g_Ah : g_Al) +
            ((size_t)(b * TT + t0)) * HH + kbase;
        const __nv_bfloat16* Bs = (part == 1 ? g_Wl : g_Wh) +
            (size_t)n0 * HH + kbase;
#pragma unroll
        for (int l = 0; l < 4; ++l) {            // A: 128 rows x 8 segs
            int idx = tid + l * 256;
            int r = idx >> 3, sg = idx & 7;
            cpa16(sb + SC_SA + st * 16384 + swz(r * 128 + sg * 16),
                  (const char*)(As + (size_t)r * HH) + sg * 16);
        }
#pragma unroll
        for (int l = 0; l < 4; ++l) {            // B: 128 h-cols x 8 segs
            int idx = tid + l * 256;
            int r = idx >> 3, sg = idx & 7;
            cpa16(sb + SC_SB + st * 16384 + swz(r * 128 + sg * 16),
                  (const char*)(Bs + (size_t)r * HH) + sg * 16);
        }
    };

    float rsc[4] = {0.f, 0.f, 0.f, 0.f};         // 4 owned rows (i x h)

    for (int n = 0; n < 4; ++n) {
        const int n0 = n * 128;
        float d[2][8][4];
#pragma unroll
        for (int i = 0; i < 2; ++i)
#pragma unroll
            for (int j = 0; j < 8; ++j)
#pragma unroll
                for (int q = 0; q < 4; ++q) d[i][j][q] = 0.f;

        fill(0, 0, n0); CPA_COMMIT();
        fill(1, 1, n0); CPA_COMMIT();

        for (int it = 0; it < 24; ++it) {
            const int st = it & 1;
            CPA_WAIT1();
            __syncthreads();
            const uint32_t abase = sb + SC_SA + st * 16384;
            const uint32_t bbase = sb + SC_SB + st * 16384;
#pragma unroll
            for (int ks = 0; ks < 4; ++ks) {     // 4 x k16 per 64-chunk
                uint32_t a[2][4];
#pragma unroll
                for (int i = 0; i < 2; ++i) {
                    int row = wm * 32 + i * 16 + (lane & 15);
                    int off = row * 128 + ks * 32 + (lane >> 4) * 16;
                    ldm4(a[i][0], a[i][1], a[i][2], a[i][3], abase + swz(off));
                }
                uint32_t bf[4][4];
#pragma unroll
                for (int p = 0; p < 4; ++p) {    // 2 n8-tiles per ldmatrix.x4
                    int row = wn * 64 + p * 16 + (lane & 7) + (lane >> 4) * 8;
                    int off = row * 128 + ks * 32 + ((lane >> 3) & 1) * 16;
                    ldm4(bf[p][0], bf[p][1], bf[p][2], bf[p][3], bbase + swz(off));
                }
#pragma unroll
                for (int i = 0; i < 2; ++i)
#pragma unroll
                    for (int j = 0; j < 8; ++j)
                        mma16816(d[i][j], a[i], &bf[j >> 1][(j & 1) * 2]);
            }
            __syncthreads();
            if (it + 2 < 24) fill(st, it + 2, n0);
            CPA_COMMIT();
        }
        // epilogue: tanh(+dec)·v into per-row partials
#pragma unroll
        for (int i = 0; i < 2; ++i)
#pragma unroll
            for (int j = 0; j < 8; ++j) {
                int c = n0 + wn * 64 + j * 8 + (lane & 3) * 2;
                float v0 = vs[c], v1 = vs[c + 1];
                float dc0 = decs[c], dc1 = decs[c + 1];
                rsc[i * 2 + 0] += tanhx(d[i][j][0] + dc0) * v0
                                + tanhx(d[i][j][1] + dc1) * v1;
                rsc[i * 2 + 1] += tanhx(d[i][j][2] + dc0) * v0
                                + tanhx(d[i][j][3] + dc1) * v1;
            }
    }

    // reduce over the 4 lanes of each quad (they share rows, own disjoint cols)
#pragma unroll
    for (int r = 0; r < 4; ++r) {
        rsc[r] += __shfl_xor_sync(0xffffffffu, rsc[r], 1);
        rsc[r] += __shfl_xor_sync(0xffffffffu, rsc[r], 2);
    }
    if ((lane & 3) == 0) {
        int g = lane >> 2;
#pragma unroll
        for (int i = 0; i < 2; ++i)
#pragma unroll
            for (int h = 0; h < 2; ++h)
                sbuf[wn * 128 + wm * 32 + i * 16 + h * 8 + g] = rsc[i * 2 + h];
    }
    __syncthreads();
    if (tid < 128)
        g_scores[b * TT + t0 + tid] = sbuf[tid] + sbuf[128 + tid];
}

// ================= K3: softmax over T per batch =================
__global__ void k_softmax(float* __restrict__ attn_out) {
    __shared__ float red[256];
    int b = blockIdx.x, tid = threadIdx.x;
    const float* s = g_scores + b * TT;
    float m = -3.4e38f;
    for (int i = tid; i < TT; i += 256) m = fmaxf(m, s[i]);
    red[tid] = m; __syncthreads();
    for (int st = 128; st > 0; st >>= 1) {
        if (tid < st) red[tid] = fmaxf(red[tid], red[tid + st]);
        __syncthreads();
    }
    float M = red[0]; __syncthreads();
    float sum = 0.f;
    for (int i = tid; i < TT; i += 256) {
        float e = expf(s[i] - M);
        g_attn[b * TT + i] = e;
        sum += e;
    }
    red[tid] = sum; __syncthreads();
    for (int st = 128; st > 0; st >>= 1) {
        if (tid < st) red[tid] += red[tid + st];
        __syncthreads();
    }
    float inv = 1.f / red[0];
    for (int i = tid; i < TT; i += 256) {
        float a = g_attn[b * TT + i] * inv;
        g_attn[b * TT + i] = a;
        if (attn_out) attn_out[b * TT + i] = a;
    }
}

// ================= K4: context partials (split-8 over T) =================
__global__ void k_ctx(const float* __restrict__ enc) {
    __shared__ float as_[256];
    int s = blockIdx.x, b = blockIdx.y;
    int h = threadIdx.x;  // 512 threads
    if (h < 256) as_[h] = g_attn[b * TT + s * 256 + h];
    __syncthreads();
    const float* ep = enc + ((size_t)b * TT + s * 256) * HH + h;
    float a0 = 0.f, a1 = 0.f, a2 = 0.f, a3 = 0.f;
#pragma unroll 4
    for (int t = 0; t < 256; t += 4) {
        a0 += as_[t + 0] * ep[(size_t)(t + 0) * HH];
        a1 += as_[t + 1] * ep[(size_t)(t + 1) * HH];
        a2 += as_[t + 2] * ep[(size_t)(t + 2) * HH];
        a3 += as_[t + 3] * ep[(size_t)(t + 3) * HH];
    }
    g_ctxp[(s * BB + b) * HH + h] = (a0 + a1) + (a2 + a3);
}

__global__ void k_ctxred() {
    int i = blockIdx.x * blockDim.x + threadIdx.x;  // 32768
    float s = 0.f;
#pragma unroll
    for (int p = 0; p < 8; ++p) s += g_ctxp[p * BB * HH + i];
    g_ctx[i] = s;
}

// ================= K5: gates GEMM =================
__global__ void __launch_bounds__(256) k_gates(const int* __restrict__ tok,
                                               const float* __restrict__ emb,
                                               const float* __restrict__ hid,
                                               const float* __restrict__ Wih,
                                               const float* __restrict__ Whh,
                                               const float* __restrict__ bih,
                                               const float* __restrict__ bhh) {
    __shared__ float Ws[32][68];
    __shared__ float Xs[32][68];
    const int tid = threadIdx.x;
    const int g0 = blockIdx.x * 64;
    const int tx = tid & 15, ty = tid >> 4;
    const int r0 = ty * 4, c0 = tx * 4;
    unsigned long long acc[4][2];
#pragma unroll
    for (int i = 0; i < 4; ++i) { acc[i][0] = 0ull; acc[i][1] = 0ull; }

    for (int kt = 0; kt < 40; ++kt) {
        int kbase = kt * 32;
#pragma unroll
        for (int l = 0; l < 2; ++l) {
            int idx = tid + l * 256;
            int row = idx >> 3, kv = (idx & 7) * 4;
            int k = kbase + kv;
            const float* src = (k < 768)
                ? (Wih + (size_t)(g0 + row) * 768 + k)
                : (Whh + (size_t)(g0 + row) * 512 + (k - 768));
            float4 v = *(const float4*)src;
            Ws[kv + 0][row] = v.x; Ws[kv + 1][row] = v.y;
            Ws[kv + 2][row] = v.z; Ws[kv + 3][row] = v.w;
        }
#pragma unroll
        for (int l = 0; l < 2; ++l) {
            int idx = tid + l * 256;
            int bc = idx >> 3, kv = (idx & 7) * 4;
            int k = kbase + kv;
            const float* src;
            if (k < 256)      src = emb + (size_t)tok[bc] * EE + k;
            else if (k < 768) src = g_ctx + bc * HH + (k - 256);
            else              src = hid + bc * HH + (k - 768);
            float4 v = *(const float4*)src;
            Xs[kv + 0][bc] = v.x; Xs[kv + 1][bc] = v.y;
            Xs[kv + 2][bc] = v.z; Xs[kv + 3][bc] = v.w;
        }
        __syncthreads();
#pragma unroll 8
        for (int kk = 0; kk < 32; ++kk) {
            float4 av = *(const float4*)&Ws[kk][r0];
            float4 xv = *(const float4*)&Xs[kk][c0];
            unsigned long long X0 = pk2(xv.x, xv.y);
            unsigned long long X1 = pk2(xv.z, xv.w);
            unsigned long long Ad0 = pkdup(av.x);
            unsigned long long Ad1 = pkdup(av.y);
            unsigned long long Ad2 = pkdup(av.z);
            unsigned long long Ad3 = pkdup(av.w);
            fma2(acc[0][0], Ad0, X0); fma2(acc[0][1], Ad0, X1);
            fma2(acc[1][0], Ad1, X0); fma2(acc[1][1], Ad1, X1);
            fma2(acc[2][0], Ad2, X0); fma2(acc[2][1], Ad2, X1);
            fma2(acc[3][0], Ad3, X0); fma2(acc[3][1], Ad3, X1);
        }
        __syncthreads();
    }
#pragma unroll
    for (int i = 0; i < 4; ++i) {
        int g = g0 + r0 + i;
        float bias = bih[g] + bhh[g];
#pragma unroll
        for (int p = 0; p < 2; ++p) {
            float2 e = upk2(acc[i][p]);
            int bc = c0 + 2 * p;
            g_gates[bc * G4H + g]       = e.x + bias;
            g_gates[(bc + 1) * G4H + g] = e.y + bias;
        }
    }
}

// ================= K6: LSTM pointwise; emit split-bf16 xout =================
__global__ void k_lstm(const float* __restrict__ cell,
                       float* __restrict__ hout, float* __restrict__ cout) {
    int i = blockIdx.x * blockDim.x + threadIdx.x;  // 32768
    int b = i >> 9, h = i & 511;
    float ig = g_gates[b * G4H + h];
    float fg = g_gates[b * G4H + 512 + h];
    float gg = g_gates[b * G4H + 1024 + h];
    float og = g_gates[b * G4H + 1536 + h];
    float c = sigf(fg) * cell[i] + sigf(ig) * tanhf(gg);
    float hn = sigf(og) * tanhf(c);
    if (hout) { hout[i] = hn; cout[i] = c; }
    float cx = g_ctx[i];
    __nv_bfloat16 hh = __float2bfloat16(hn);
    __nv_bfloat16 ch = __float2bfloat16(cx);
    g_Xh[b * K2H + h]        = hh;
    g_Xl[b * K2H + h]        = __float2bfloat16(hn - __bfloat162float(hh));
    g_Xh[b * K2H + 512 + h]  = ch;
    g_Xl[b * K2H + 512 + h]  = __float2bfloat16(cx - __bfloat162float(ch));
}

// ================= K7: logits via mma.sync (HMMA) split-bf16 =================
// Per CTA: 128 v-rows x 64 batch; D = Wh·Xh + Wh·Xl + Wl·Xh, K=1024
// in 16 chunks of 64, double-buffered cp.async, SW128 swizzle.
#define LG_SA   0                      // Wh/Wl stages: 2 x 32768
#define LG_SB   65536                  // Xh/Xl stages: 2 x 16384
#define LG_TOT  98304
// epilogue transpose buffer overlays LG_SA region: float [64][132]

__global__ void __launch_bounds__(256, 2)
k_logits_mma(const float* __restrict__ bout, float* __restrict__ out) {
    extern __shared__ __align__(1024) char smem[];
    const uint32_t sb = smem_u32(smem);
    const int tid = threadIdx.x, lane = tid & 31, wid = tid >> 5;
    const int wm = wid & 3, wn = wid >> 2;       // warp tile (32 m) x (32 n)
    const int v0 = blockIdx.x * 128;

    auto fill = [&](int st, int kt) {
        const int kbase = kt * 64;
#pragma unroll
        for (int l = 0; l < 4; ++l) {            // A: 128 rows x 8 segs (h & l)
            int idx = tid + l * 256;
            int r = idx >> 3, sg = idx & 7;
            int vr = v0 + r; if (vr >= VV) vr = VV - 1;
            uint32_t so = swz(r * 128 + sg * 16);
            cpa16(sb + LG_SA + st * 32768 + so,
                  (const char*)(g_Wouth + (size_t)vr * K2H + kbase) + sg * 16);
            cpa16(sb + LG_SA + st * 32768 + 16384 + so,
                  (const char*)(g_Woutl + (size_t)vr * K2H + kbase) + sg * 16);
        }
#pragma unroll
        for (int l = 0; l < 2; ++l) {            // B: 64 rows x 8 segs (h & l)
            int idx = tid + l * 256;
            int r = idx >> 3, sg = idx & 7;
            uint32_t so = swz(r * 128 + sg * 16);
            cpa16(sb + LG_SB + st * 16384 + so,
                  (const char*)(g_Xh + (size_t)r * K2H + kbase) + sg * 16);
            cpa16(sb + LG_SB + st * 16384 + 8192 + so,
                  (const char*)(g_Xl + (size_t)r * K2H + kbase) + sg * 16);
        }
    };

    float d[2][4][4];
#pragma unroll
    for (int i = 0; i < 2; ++i)
#pragma unroll
        for (int j = 0; j < 4; ++j)
#pragma unroll
            for (int q = 0; q < 4; ++q) d[i][j][q] = 0.f;

    fill(0, 0); CPA_COMMIT();
    fill(1, 1); CPA_COMMIT();

    for (int kt = 0; kt < 16; ++kt) {
        const int st = kt & 1;
        CPA_WAIT1();
        __syncthreads();
        const uint32_t ahb = sb + LG_SA + st * 32768;
        const uint32_t alb = ahb + 16384;
        const uint32_t bhb = sb + LG_SB + st * 16384;
        const uint32_t blb = bhb + 8192;
#pragma unroll
        for (int ks = 0; ks < 4; ++ks) {
            uint32_t ah[2][4], al[2][4];
#pragma unroll
            for (int i = 0; i < 2; ++i) {
                int row = wm * 32 + i * 16 + (lane & 15);
                uint32_t so = swz(row * 128 + ks * 32 + (lane >> 4) * 16);
                ldm4(ah[i][0], ah[i][1], ah[i][2], ah[i][3], ahb + so);
                ldm4(al[i][0], al[i][1], al[i][2], al[i][3], alb + so);
            }
            uint32_t bh[2][4], bl[2][4];
#pragma unroll
            for (int p = 0; p < 2; ++p) {
                int row = wn * 32 + p * 16 + (lane & 7) + (lane >> 4) * 8;
                uint32_t so = swz(row * 128 + ks * 32 + ((lane >> 3) & 1) * 16);
                ldm4(bh[p][0], bh[p][1], bh[p][2], bh[p][3], bhb + so);
                ldm4(bl[p][0], bl[p][1], bl[p][2], bl[p][3], blb + so);
            }
#pragma unroll
            for (int i = 0; i < 2; ++i)
#pragma unroll
                for (int j = 0; j < 4; ++j) {
                    mma16816(d[i][j], ah[i], &bh[j >> 1][(j & 1) * 2]);
                    mma16816(d[i][j], ah[i], &bl[j >> 1][(j & 1) * 2]);
                    mma16816(d[i][j], al[i], &bh[j >> 1][(j & 1) * 2]);
                }
        }
        __syncthreads();
        if (kt + 2 < 16) fill(st, kt + 2);
        CPA_COMMIT();
    }

    // epilogue: transpose through smem (overlays stage A), bias, coalesced write
    __syncthreads();
    float* sbuf = (float*)smem;   // [64][132]
#pragma unroll
    for (int i = 0; i < 2; ++i)
#pragma unroll
        for (int j = 0; j < 4; ++j)
#pragma unroll
            for (int q = 0; q < 4; ++q) {
                int r = wm * 32 + i * 16 + (lane >> 2) + (q >> 1) * 8;
                int c = wn * 32 + j * 8 + (lane & 3) * 2 + (q & 1);
                sbuf[c * 132 + r] = d[i][j][q];
            }
    __syncthreads();
#pragma unroll
    for (int l = 0; l < 32; ++l) {
        int idx = tid + l * 256;
        int bc = idx >> 7, r = idx & 127;
        int v = v0 + r;
        if (v < VV) out[(size_t)bc * VV + v] = sbuf[bc * 132 + r] + bout[v];
    }
}

// ================= host launcher =================
extern "C" void kernel_launch(void* const* d_in, const int* in_sizes, int n_in,
                              void* d_out, int out_size) {
    const int*   tok  = (const int*)d_in[0];
    const float* hid  = (const float*)d_in[1];
    const float* cell = (const float*)d_in[2];
    const float* enc  = (const float*)d_in[3];
    const float* emb  = (const float*)d_in[4];
    const float* Wenc = (const float*)d_in[5];
    const float* Wdec = (const float*)d_in[6];
    const float* vat  = (const float*)d_in[7];
    const float* Wih  = (const float*)d_in[8];
    const float* Whh  = (const float*)d_in[9];
    const float* bih  = (const float*)d_in[10];
    const float* bhh  = (const float*)d_in[11];
    const float* Wout = (const float*)d_in[12];
    const float* bout = (const float*)d_in[13];
    float* out = (float*)d_out;

    const long long full = (long long)BB * VV + 2LL * BB * HH + (long long)BB * TT;
    bool has_aux = ((long long)out_size >= full);
    float* out_h = has_aux ? out + (size_t)BB * VV : nullptr;
    float* out_c = has_aux ? out + (size_t)BB * VV + BB * HH : nullptr;
    float* out_a = has_aux ? out + (size_t)BB * VV + 2 * BB * HH : nullptr;

    cudaFuncSetAttribute(k_scores_mma,
                         cudaFuncAttributeMaxDynamicSharedMemorySize, SC_TOT);
    cudaFuncSetAttribute(k_logits_mma,
                         cudaFuncAttributeMaxDynamicSharedMemorySize, LG_TOT);

    k_split_w<<<(HH * HH + 255) / 256, 256>>>(Wenc);
    k_split_enc<<<(int)(((size_t)BB * TT * HH / 4) / 256), 256>>>(enc);
    k_split_wout<<<(int)(((size_t)VV * K2H / 4) / 256), 256>>>(Wout);
    k_dec<<<BB, 256>>>(hid, Wdec);
    k_scores_mma<<<BB * (TT / 128), 256, SC_TOT>>>(vat);
    k_softmax<<<BB, 256>>>(out_a);
    k_ctx<<<dim3(8, BB), 512>>>(enc);
    k_ctxred<<<32, 1024>>>();
    k_gates<<<G4H / 64, 256>>>(tok, emb, hid, Wih, Whh, bih, bhh);
    k_lstm<<<32, 1024>>>(cell, out_h, out_c);
    k_logits_mma<<<(VV + 127) / 128, 256, LG_TOT>>>(bout, out);
}

// round 9
// speedup vs baseline: 1.0388x; 1.0388x over previous
#include <cuda_runtime.h>
#include <cuda_bf16.h>
#include <math.h>
#include <stdint.h>

#define BB 64
#define TT 2048
#define HH 512
#define EE 256
#define VV 50000
#define G4H 2048   /* 4*H  */
#define K2H 1024   /* 2*H  */

// ---------------- scratch (device globals; no allocation) ----------------
__device__ float g_dec[BB * HH];          // h @ W_dec.T          (B,H)
__device__ float g_scores[BB * TT];       // attention scores     (B,T)
__device__ float g_attn[BB * TT];         // softmax(scores)      (B,T)
__device__ float g_ctxp[8 * BB * HH];     // context partials     (8,B,H)
__device__ float g_ctx[BB * HH];          // context              (B,H)
__device__ float g_gates[BB * G4H];       // LSTM gates           (B,4H)
// split-bf16 operands for the scores GEMM
__device__ __nv_bfloat16 g_Ah[(size_t)BB * TT * HH];  // 128 MB
__device__ __nv_bfloat16 g_Al[(size_t)BB * TT * HH];  // 128 MB
__device__ __nv_bfloat16 g_Wh[HH * HH];
__device__ __nv_bfloat16 g_Wl[HH * HH];
// split-bf16 operands for the logits GEMM
__device__ __nv_bfloat16 g_Wouth[(size_t)VV * K2H];   // 102.4 MB
__device__ __nv_bfloat16 g_Woutl[(size_t)VV * K2H];   // 102.4 MB
__device__ __nv_bfloat16 g_Xh[BB * K2H];              // [h_new, ctx] hi
__device__ __nv_bfloat16 g_Xl[BB * K2H];              // [h_new, ctx] lo

// ---------------- packed f32x2 helpers (FFMA2 path, small GEMMs) ----------------
__device__ __forceinline__ unsigned long long pk2(float lo, float hi) {
    unsigned long long r;
    asm("mov.b64 %0, {%1, %2};" : "=l"(r)
        : "r"(__float_as_uint(lo)), "r"(__float_as_uint(hi)));
    return r;
}
__device__ __forceinline__ unsigned long long pkdup(float v) {
    unsigned long long r;
    asm("mov.b64 %0, {%1, %1};" : "=l"(r) : "r"(__float_as_uint(v)));
    return r;
}
__device__ __forceinline__ void fma2(unsigned long long& d,
                                     unsigned long long a,
                                     unsigned long long b) {
    asm("fma.rn.f32x2 %0, %1, %2, %0;" : "+l"(d) : "l"(a), "l"(b));
}
__device__ __forceinline__ float2 upk2(unsigned long long v) {
    unsigned int lo, hi;
    asm("mov.b64 {%0, %1}, %2;" : "=r"(lo), "=r"(hi) : "l"(v));
    return make_float2(__uint_as_float(lo), __uint_as_float(hi));
}
__device__ __forceinline__ float sigf(float x) { return 1.f / (1.f + expf(-x)); }

// ---------------- smem / async / mma helpers (baseline PTX, sm_80+) ----------------
__device__ __forceinline__ uint32_t smem_u32(const void* p) {
    uint32_t a;
    asm("{ .reg .u64 t; cvta.to.shared.u64 t, %1; cvt.u32.u64 %0, t; }"
        : "=r"(a) : "l"(p));
    return a;
}
__device__ __forceinline__ void cpa16(uint32_t dst, const void* src) {
    asm volatile("cp.async.cg.shared.global [%0], [%1], 16;" :: "r"(dst), "l"(src));
}
#define CPA_COMMIT() asm volatile("cp.async.commit_group;" ::: "memory")
#define CPA_WAIT1()  asm volatile("cp.async.wait_group 1;" ::: "memory")
__device__ __forceinline__ uint32_t swz(uint32_t off) { return off ^ ((off >> 3) & 0x70); }

__device__ __forceinline__ void ldm4(uint32_t& r0, uint32_t& r1,
                                     uint32_t& r2, uint32_t& r3, uint32_t addr) {
    asm volatile("ldmatrix.sync.aligned.m8n8.x4.shared.b16 {%0,%1,%2,%3}, [%4];"
        : "=r"(r0), "=r"(r1), "=r"(r2), "=r"(r3) : "r"(addr));
}
__device__ __forceinline__ void mma16816(float* d, const uint32_t* a,
                                         const uint32_t* bf) {
    asm volatile("mma.sync.aligned.m16n8k16.row.col.f32.bf16.bf16.f32 "
        "{%0,%1,%2,%3}, {%4,%5,%6,%7}, {%8,%9}, {%0,%1,%2,%3};"
        : "+f"(d[0]), "+f"(d[1]), "+f"(d[2]), "+f"(d[3])
        : "r"(a[0]), "r"(a[1]), "r"(a[2]), "r"(a[3]), "r"(bf[0]), "r"(bf[1]));
}
__device__ __forceinline__ float tanhx(float x) {
    float e2 = __expf(2.f * x);
    return 1.f - __fdividef(2.f, e2 + 1.f);
}

// ================= prep: split fp32 -> (hi, lo) bf16 =================
__global__ void k_split_w(const float* __restrict__ W) {
    int i = blockIdx.x * 256 + threadIdx.x;
    if (i < HH * HH) {
        float x = W[i];
        __nv_bfloat16 h = __float2bfloat16(x);
        g_Wh[i] = h;
        g_Wl[i] = __float2bfloat16(x - __bfloat162float(h));
    }
}
__global__ void k_split_enc(const float* __restrict__ enc) {
    size_t i = (size_t)blockIdx.x * 256 + threadIdx.x;  // x4 vectorized
    float4 v = ((const float4*)enc)[i];
    __nv_bfloat16 h0 = __float2bfloat16(v.x), h1 = __float2bfloat16(v.y);
    __nv_bfloat16 h2 = __float2bfloat16(v.z), h3 = __float2bfloat16(v.w);
    __nv_bfloat162 hp0; hp0.x = h0; hp0.y = h1;
    __nv_bfloat162 hp1; hp1.x = h2; hp1.y = h3;
    ((__nv_bfloat162*)g_Ah)[i * 2 + 0] = hp0;
    ((__nv_bfloat162*)g_Ah)[i * 2 + 1] = hp1;
    __nv_bfloat162 lp0, lp1;
    lp0.x = __float2bfloat16(v.x - __bfloat162float(h0));
    lp0.y = __float2bfloat16(v.y - __bfloat162float(h1));
    lp1.x = __float2bfloat16(v.z - __bfloat162float(h2));
    lp1.y = __float2bfloat16(v.w - __bfloat162float(h3));
    ((__nv_bfloat162*)g_Al)[i * 2 + 0] = lp0;
    ((__nv_bfloat162*)g_Al)[i * 2 + 1] = lp1;
}
__global__ void k_split_wout(const float* __restrict__ W) {
    size_t i = (size_t)blockIdx.x * 256 + threadIdx.x;  // x4 vectorized, exact
    float4 v = ((const float4*)W)[i];
    __nv_bfloat16 h0 = __float2bfloat16(v.x), h1 = __float2bfloat16(v.y);
    __nv_bfloat16 h2 = __float2bfloat16(v.z), h3 = __float2bfloat16(v.w);
    __nv_bfloat162 hp0; hp0.x = h0; hp0.y = h1;
    __nv_bfloat162 hp1; hp1.x = h2; hp1.y = h3;
    ((__nv_bfloat162*)g_Wouth)[i * 2 + 0] = hp0;
    ((__nv_bfloat162*)g_Wouth)[i * 2 + 1] = hp1;
    __nv_bfloat162 lp0, lp1;
    lp0.x = __float2bfloat16(v.x - __bfloat162float(h0));
    lp0.y = __float2bfloat16(v.y - __bfloat162float(h1));
    lp1.x = __float2bfloat16(v.z - __bfloat162float(h2));
    lp1.y = __float2bfloat16(v.w - __bfloat162float(h3));
    ((__nv_bfloat162*)g_Woutl)[i * 2 + 0] = lp0;
    ((__nv_bfloat162*)g_Woutl)[i * 2 + 1] = lp1;
}

// ================= K1: dec = h @ W_dec.T  (one warp per output) =================
__global__ void k_dec(const float* __restrict__ hid,
                      const float* __restrict__ Wdec) {
    __shared__ float hs[HH];
    const int b = blockIdx.y;
    const int tid = threadIdx.x, wid = tid >> 5, lane = tid & 31;
    for (int i = tid; i < HH; i += 256) hs[i] = hid[b * HH + i];
    __syncthreads();
#pragma unroll
    for (int j = 0; j < 8; ++j) {                 // 8 warps x 8 h each
        int h = blockIdx.x * 64 + wid * 8 + j;
        const float4* w = (const float4*)(Wdec + (size_t)h * HH);
        float s = 0.f;
#pragma unroll
        for (int i = 0; i < 4; ++i) {
            int k4 = lane + i * 32;
            float4 wv = w[k4];
            s += wv.x * hs[k4 * 4 + 0] + wv.y * hs[k4 * 4 + 1]
               + wv.z * hs[k4 * 4 + 2] + wv.w * hs[k4 * 4 + 3];
        }
#pragma unroll
        for (int m = 16; m >= 1; m >>= 1)
            s += __shfl_xor_sync(0xffffffffu, s, m);
        if (lane == 0) g_dec[b * HH + h] = s;
    }
}

// ================= K2: scores via mma.sync (HMMA) split-bf16 =================
#define SC_SA   0                      // A stages: 2 x 16384
#define SC_SB   32768                  // B stages: 2 x 16384
#define SC_DEC  65536                  // dec row  (2048 B)
#define SC_V    67584                  // v_attn   (2048 B)
#define SC_SC   69632                  // score buf 2x128 floats (1024 B)
#define SC_TOT  70656

__global__ void __launch_bounds__(256, 2)
k_scores_mma(const float* __restrict__ vat) {
    extern __shared__ __align__(1024) char smem[];
    const uint32_t sb = smem_u32(smem);
    float* decs = (float*)(smem + SC_DEC);
    float* vs   = (float*)(smem + SC_V);
    float* sbuf = (float*)(smem + SC_SC);
    const int tid = threadIdx.x, lane = tid & 31, wid = tid >> 5;
    const int wm = wid & 3, wn = wid >> 2;       // warp tile (32 m) x (64 n)
    const int b = blockIdx.x >> 4;
    const int t0 = (blockIdx.x & 15) * 128;

    for (int i = tid; i < HH; i += 256) {
        decs[i] = g_dec[b * HH + i];
        vs[i]   = vat[i];
    }
    __syncthreads();

    auto fill = [&](int st, int it, int n0) {
        const int part = it >> 3, kbase = (it & 7) * 64;
        const __nv_bfloat16* As = (part < 2 ? g_Ah : g_Al) +
            ((size_t)(b * TT + t0)) * HH + kbase;
        const __nv_bfloat16* Bs = (part == 1 ? g_Wl : g_Wh) +
            (size_t)n0 * HH + kbase;
#pragma unroll
        for (int l = 0; l < 4; ++l) {            // A: 128 rows x 8 segs
            int idx = tid + l * 256;
            int r = idx >> 3, sg = idx & 7;
            cpa16(sb + SC_SA + st * 16384 + swz(r * 128 + sg * 16),
                  (const char*)(As + (size_t)r * HH) + sg * 16);
        }
#pragma unroll
        for (int l = 0; l < 4; ++l) {            // B: 128 h-cols x 8 segs
            int idx = tid + l * 256;
            int r = idx >> 3, sg = idx & 7;
            cpa16(sb + SC_SB + st * 16384 + swz(r * 128 + sg * 16),
                  (const char*)(Bs + (size_t)r * HH) + sg * 16);
        }
    };

    float rsc[4] = {0.f, 0.f, 0.f, 0.f};         // 4 owned rows (i x h)

    for (int n = 0; n < 4; ++n) {
        const int n0 = n * 128;
        float d[2][8][4];
#pragma unroll
        for (int i = 0; i < 2; ++i)
#pragma unroll
            for (int j = 0; j < 8; ++j)
#pragma unroll
                for (int q = 0; q < 4; ++q) d[i][j][q] = 0.f;

        fill(0, 0, n0); CPA_COMMIT();
        fill(1, 1, n0); CPA_COMMIT();

        for (int it = 0; it < 24; ++it) {
            const int st = it & 1;
            CPA_WAIT1();
            __syncthreads();
            const uint32_t abase = sb + SC_SA + st * 16384;
            const uint32_t bbase = sb + SC_SB + st * 16384;
#pragma unroll
            for (int ks = 0; ks < 4; ++ks) {     // 4 x k16 per 64-chunk
                uint32_t a[2][4];
#pragma unroll
                for (int i = 0; i < 2; ++i) {
                    int row = wm * 32 + i * 16 + (lane & 15);
                    int off = row * 128 + ks * 32 + (lane >> 4) * 16;
                    ldm4(a[i][0], a[i][1], a[i][2], a[i][3], abase + swz(off));
                }
                uint32_t bf[4][4];
#pragma unroll
                for (int p = 0; p < 4; ++p) {    // 2 n8-tiles per ldmatrix.x4
                    int row = wn * 64 + p * 16 + (lane & 7) + (lane >> 4) * 8;
                    int off = row * 128 + ks * 32 + ((lane >> 3) & 1) * 16;
                    ldm4(bf[p][0], bf[p][1], bf[p][2], bf[p][3], bbase + swz(off));
                }
#pragma unroll
                for (int i = 0; i < 2; ++i)
#pragma unroll
                    for (int j = 0; j < 8; ++j)
                        mma16816(d[i][j], a[i], &bf[j >> 1][(j & 1) * 2]);
            }
            __syncthreads();
            if (it + 2 < 24) fill(st, it + 2, n0);
            CPA_COMMIT();
        }
        // epilogue: tanh(+dec)·v into per-row partials
#pragma unroll
        for (int i = 0; i < 2; ++i)
#pragma unroll
            for (int j = 0; j < 8; ++j) {
                int c = n0 + wn * 64 + j * 8 + (lane & 3) * 2;
                float v0 = vs[c], v1 = vs[c + 1];
                float dc0 = decs[c], dc1 = decs[c + 1];
                rsc[i * 2 + 0] += tanhx(d[i][j][0] + dc0) * v0
                                + tanhx(d[i][j][1] + dc1) * v1;
                rsc[i * 2 + 1] += tanhx(d[i][j][2] + dc0) * v0
                                + tanhx(d[i][j][3] + dc1) * v1;
            }
    }

    // reduce over the 4 lanes of each quad (they share rows, own disjoint cols)
#pragma unroll
    for (int r = 0; r < 4; ++r) {
        rsc[r] += __shfl_xor_sync(0xffffffffu, rsc[r], 1);
        rsc[r] += __shfl_xor_sync(0xffffffffu, rsc[r], 2);
    }
    if ((lane & 3) == 0) {
        int g = lane >> 2;
#pragma unroll
        for (int i = 0; i < 2; ++i)
#pragma unroll
            for (int h = 0; h < 2; ++h)
                sbuf[wn * 128 + wm * 32 + i * 16 + h * 8 + g] = rsc[i * 2 + h];
    }
    __syncthreads();
    if (tid < 128)
        g_scores[b * TT + t0 + tid] = sbuf[tid] + sbuf[128 + tid];
}

// ================= K3: softmax over T per batch =================
__global__ void k_softmax(float* __restrict__ attn_out) {
    __shared__ float red[256];
    int b = blockIdx.x, tid = threadIdx.x;
    const float* s = g_scores + b * TT;
    float m = -3.4e38f;
    for (int i = tid; i < TT; i += 256) m = fmaxf(m, s[i]);
    red[tid] = m; __syncthreads();
    for (int st = 128; st > 0; st >>= 1) {
        if (tid < st) red[tid] = fmaxf(red[tid], red[tid + st]);
        __syncthreads();
    }
    float M = red[0]; __syncthreads();
    float sum = 0.f;
    for (int i = tid; i < TT; i += 256) {
        float e = expf(s[i] - M);
        g_attn[b * TT + i] = e;
        sum += e;
    }
    red[tid] = sum; __syncthreads();
    for (int st = 128; st > 0; st >>= 1) {
        if (tid < st) red[tid] += red[tid + st];
        __syncthreads();
    }
    float inv = 1.f / red[0];
    for (int i = tid; i < TT; i += 256) {
        float a = g_attn[b * TT + i] * inv;
        g_attn[b * TT + i] = a;
        if (attn_out) attn_out[b * TT + i] = a;
    }
}

// ================= K4: context partials (split-8 over T) =================
__global__ void k_ctx(const float* __restrict__ enc) {
    __shared__ float as_[256];
    int s = blockIdx.x, b = blockIdx.y;
    int h = threadIdx.x;  // 512 threads
    if (h < 256) as_[h] = g_attn[b * TT + s * 256 + h];
    __syncthreads();
    const float* ep = enc + ((size_t)b * TT + s * 256) * HH + h;
    float a0 = 0.f, a1 = 0.f, a2 = 0.f, a3 = 0.f;
#pragma unroll 4
    for (int t = 0; t < 256; t += 4) {
        a0 += as_[t + 0] * ep[(size_t)(t + 0) * HH];
        a1 += as_[t + 1] * ep[(size_t)(t + 1) * HH];
        a2 += as_[t + 2] * ep[(size_t)(t + 2) * HH];
        a3 += as_[t + 3] * ep[(size_t)(t + 3) * HH];
    }
    g_ctxp[(s * BB + b) * HH + h] = (a0 + a1) + (a2 + a3);
}

__global__ void k_ctxred() {
    int i = blockIdx.x * blockDim.x + threadIdx.x;  // 32768
    float s = 0.f;
#pragma unroll
    for (int p = 0; p < 8; ++p) s += g_ctxp[p * BB * HH + i];
    g_ctx[i] = s;
}

// ================= K5: gates GEMM =================
__global__ void __launch_bounds__(256) k_gates(const int* __restrict__ tok,
                                               const float* __restrict__ emb,
                                               const float* __restrict__ hid,
                                               const float* __restrict__ Wih,
                                               const float* __restrict__ Whh,
                                               const float* __restrict__ bih,
                                               const float* __restrict__ bhh) {
    __shared__ float Ws[32][68];
    __shared__ float Xs[32][68];
    const int tid = threadIdx.x;
    const int g0 = blockIdx.x * 64;
    const int tx = tid & 15, ty = tid >> 4;
    const int r0 = ty * 4, c0 = tx * 4;
    unsigned long long acc[4][2];
#pragma unroll
    for (int i = 0; i < 4; ++i) { acc[i][0] = 0ull; acc[i][1] = 0ull; }

    for (int kt = 0; kt < 40; ++kt) {
        int kbase = kt * 32;
#pragma unroll
        for (int l = 0; l < 2; ++l) {
            int idx = tid + l * 256;
            int row = idx >> 3, kv = (idx & 7) * 4;
            int k = kbase + kv;
            const float* src = (k < 768)
                ? (Wih + (size_t)(g0 + row) * 768 + k)
                : (Whh + (size_t)(g0 + row) * 512 + (k - 768));
            float4 v = *(const float4*)src;
            Ws[kv + 0][row] = v.x; Ws[kv + 1][row] = v.y;
            Ws[kv + 2][row] = v.z; Ws[kv + 3][row] = v.w;
        }
#pragma unroll
        for (int l = 0; l < 2; ++l) {
            int idx = tid + l * 256;
            int bc = idx >> 3, kv = (idx & 7) * 4;
            int k = kbase + kv;
            const float* src;
            if (k < 256)      src = emb + (size_t)tok[bc] * EE + k;
            else if (k < 768) src = g_ctx + bc * HH + (k - 256);
            else              src = hid + bc * HH + (k - 768);
            float4 v = *(const float4*)src;
            Xs[kv + 0][bc] = v.x; Xs[kv + 1][bc] = v.y;
            Xs[kv + 2][bc] = v.z; Xs[kv + 3][bc] = v.w;
        }
        __syncthreads();
#pragma unroll 8
        for (int kk = 0; kk < 32; ++kk) {
            float4 av = *(const float4*)&Ws[kk][r0];
            float4 xv = *(const float4*)&Xs[kk][c0];
            unsigned long long X0 = pk2(xv.x, xv.y);
            unsigned long long X1 = pk2(xv.z, xv.w);
            unsigned long long Ad0 = pkdup(av.x);
            unsigned long long Ad1 = pkdup(av.y);
            unsigned long long Ad2 = pkdup(av.z);
            unsigned long long Ad3 = pkdup(av.w);
            fma2(acc[0][0], Ad0, X0); fma2(acc[0][1], Ad0, X1);
            fma2(acc[1][0], Ad1, X0); fma2(acc[1][1], Ad1, X1);
            fma2(acc[2][0], Ad2, X0); fma2(acc[2][1], Ad2, X1);
            fma2(acc[3][0], Ad3, X0); fma2(acc[3][1], Ad3, X1);
        }
        __syncthreads();
    }
#pragma unroll
    for (int i = 0; i < 4; ++i) {
        int g = g0 + r0 + i;
        float bias = bih[g] + bhh[g];
#pragma unroll
        for (int p = 0; p < 2; ++p) {
            float2 e = upk2(acc[i][p]);
            int bc = c0 + 2 * p;
            g_gates[bc * G4H + g]       = e.x + bias;
            g_gates[(bc + 1) * G4H + g] = e.y + bias;
        }
    }
}

// ================= K6: LSTM pointwise; emit split-bf16 xout =================
__global__ void k_lstm(const float* __restrict__ cell,
                       float* __restrict__ hout, float* __restrict__ cout) {
    int i = blockIdx.x * blockDim.x + threadIdx.x;  // 32768
    int b = i >> 9, h = i & 511;
    float ig = g_gates[b * G4H + h];
    float fg = g_gates[b * G4H + 512 + h];
    float gg = g_gates[b * G4H + 1024 + h];
    float og = g_gates[b * G4H + 1536 + h];
    float c = sigf(fg) * cell[i] + sigf(ig) * tanhf(gg);
    float hn = sigf(og) * tanhf(c);
    if (hout) { hout[i] = hn; cout[i] = c; }
    float cx = g_ctx[i];
    __nv_bfloat16 hh = __float2bfloat16(hn);
    __nv_bfloat16 ch = __float2bfloat16(cx);
    g_Xh[b * K2H + h]        = hh;
    g_Xl[b * K2H + h]        = __float2bfloat16(hn - __bfloat162float(hh));
    g_Xh[b * K2H + 512 + h]  = ch;
    g_Xl[b * K2H + 512 + h]  = __float2bfloat16(cx - __bfloat162float(ch));
}

// ================= K7: logits via mma.sync (HMMA) split-bf16 =================
#define LG_SA   0                      // Wh/Wl stages: 2 x 32768
#define LG_SB   65536                  // Xh/Xl stages: 2 x 16384
#define LG_TOT  98304

__global__ void __launch_bounds__(256, 2)
k_logits_mma(const float* __restrict__ bout, float* __restrict__ out) {
    extern __shared__ __align__(1024) char smem[];
    const uint32_t sb = smem_u32(smem);
    const int tid = threadIdx.x, lane = tid & 31, wid = tid >> 5;
    const int wm = wid & 3, wn = wid >> 2;       // warp tile (32 m) x (32 n)
    const int v0 = blockIdx.x * 128;

    auto fill = [&](int st, int kt) {
        const int kbase = kt * 64;
#pragma unroll
        for (int l = 0; l < 4; ++l) {            // A: 128 rows x 8 segs (h & l)
            int idx = tid + l * 256;
            int r = idx >> 3, sg = idx & 7;
            int vr = v0 + r; if (vr >= VV) vr = VV - 1;
            uint32_t so = swz(r * 128 + sg * 16);
            cpa16(sb + LG_SA + st * 32768 + so,
                  (const char*)(g_Wouth + (size_t)vr * K2H + kbase) + sg * 16);
            cpa16(sb + LG_SA + st * 32768 + 16384 + so,
                  (const char*)(g_Woutl + (size_t)vr * K2H + kbase) + sg * 16);
        }
#pragma unroll
        for (int l = 0; l < 2; ++l) {            // B: 64 rows x 8 segs (h & l)
            int idx = tid + l * 256;
            int r = idx >> 3, sg = idx & 7;
            uint32_t so = swz(r * 128 + sg * 16);
            cpa16(sb + LG_SB + st * 16384 + so,
                  (const char*)(g_Xh + (size_t)r * K2H + kbase) + sg * 16);
            cpa16(sb + LG_SB + st * 16384 + 8192 + so,
                  (const char*)(g_Xl + (size_t)r * K2H + kbase) + sg * 16);
        }
    };

    float d[2][4][4];
#pragma unroll
    for (int i = 0; i < 2; ++i)
#pragma unroll
        for (int j = 0; j < 4; ++j)
#pragma unroll
            for (int q = 0; q < 4; ++q) d[i][j][q] = 0.f;

    fill(0, 0); CPA_COMMIT();
    fill(1, 1); CPA_COMMIT();

    for (int kt = 0; kt < 16; ++kt) {
        const int st = kt & 1;
        CPA_WAIT1();
        __syncthreads();
        const uint32_t ahb = sb + LG_SA + st * 32768;
        const uint32_t alb = ahb + 16384;
        const uint32_t bhb = sb + LG_SB + st * 16384;
        const uint32_t blb = bhb + 8192;
#pragma unroll
        for (int ks = 0; ks < 4; ++ks) {
            uint32_t ah[2][4], al[2][4];
#pragma unroll
            for (int i = 0; i < 2; ++i) {
                int row = wm * 32 + i * 16 + (lane & 15);
                uint32_t so = swz(row * 128 + ks * 32 + (lane >> 4) * 16);
                ldm4(ah[i][0], ah[i][1], ah[i][2], ah[i][3], ahb + so);
                ldm4(al[i][0], al[i][1], al[i][2], al[i][3], alb + so);
            }
            uint32_t bh[2][4], bl[2][4];
#pragma unroll
            for (int p = 0; p < 2; ++p) {
                int row = wn * 32 + p * 16 + (lane & 7) + (lane >> 4) * 8;
                uint32_t so = swz(row * 128 + ks * 32 + ((lane >> 3) & 1) * 16);
                ldm4(bh[p][0], bh[p][1], bh[p][2], bh[p][3], bhb + so);
                ldm4(bl[p][0], bl[p][1], bl[p][2], bl[p][3], blb + so);
            }
#pragma unroll
            for (int i = 0; i < 2; ++i)
#pragma unroll
                for (int j = 0; j < 4; ++j) {
                    mma16816(d[i][j], ah[i], &bh[j >> 1][(j & 1) * 2]);
                    mma16816(d[i][j], ah[i], &bl[j >> 1][(j & 1) * 2]);
                    mma16816(d[i][j], al[i], &bh[j >> 1][(j & 1) * 2]);
                }
        }
        __syncthreads();
        if (kt + 2 < 16) fill(st, kt + 2);
        CPA_COMMIT();
    }

    // epilogue: transpose through smem (overlays stage A), bias, coalesced write
    __syncthreads();
    float* sbuf = (float*)smem;   // [64][132]
#pragma unroll
    for (int i = 0; i < 2; ++i)
#pragma unroll
        for (int j = 0; j < 4; ++j)
#pragma unroll
            for (int q = 0; q < 4; ++q) {
                int r = wm * 32 + i * 16 + (lane >> 2) + (q >> 1) * 8;
                int c = wn * 32 + j * 8 + (lane & 3) * 2 + (q & 1);
                sbuf[c * 132 + r] = d[i][j][q];
            }
    __syncthreads();
#pragma unroll
    for (int l = 0; l < 32; ++l) {
        int idx = tid + l * 256;
        int bc = idx >> 7, r = idx & 127;
        int v = v0 + r;
        if (v < VV) out[(size_t)bc * VV + v] = sbuf[bc * 132 + r] + bout[v];
    }
}

// ================= host launcher (fork/join graph) =================
extern "C" void kernel_launch(void* const* d_in, const int* in_sizes, int n_in,
                              void* d_out, int out_size) {
    const int*   tok  = (const int*)d_in[0];
    const float* hid  = (const float*)d_in[1];
    const float* cell = (const float*)d_in[2];
    const float* enc  = (const float*)d_in[3];
    const float* emb  = (const float*)d_in[4];
    const float* Wenc = (const float*)d_in[5];
    const float* Wdec = (const float*)d_in[6];
    const float* vat  = (const float*)d_in[7];
    const float* Wih  = (const float*)d_in[8];
    const float* Whh  = (const float*)d_in[9];
    const float* bih  = (const float*)d_in[10];
    const float* bhh  = (const float*)d_in[11];
    const float* Wout = (const float*)d_in[12];
    const float* bout = (const float*)d_in[13];
    float* out = (float*)d_out;

    const long long full = (long long)BB * VV + 2LL * BB * HH + (long long)BB * TT;
    bool has_aux = ((long long)out_size >= full);
    float* out_h = has_aux ? out + (size_t)BB * VV : nullptr;
    float* out_c = has_aux ? out + (size_t)BB * VV + BB * HH : nullptr;
    float* out_a = has_aux ? out + (size_t)BB * VV + 2 * BB * HH : nullptr;

    cudaFuncSetAttribute(k_scores_mma,
                         cudaFuncAttributeMaxDynamicSharedMemorySize, SC_TOT);
    cudaFuncSetAttribute(k_logits_mma,
                         cudaFuncAttributeMaxDynamicSharedMemorySize, LG_TOT);

    // side stream for DRAM work overlapped with the tensor-bound scores kernel
    cudaStream_t s2;
    cudaStreamCreateWithFlags(&s2, cudaStreamNonBlocking);
    cudaEvent_t ev0, ev2, ev3;
    cudaEventCreateWithFlags(&ev0, cudaEventDisableTiming);
    cudaEventCreateWithFlags(&ev2, cudaEventDisableTiming);
    cudaEventCreateWithFlags(&ev3, cudaEventDisableTiming);

    // fork
    cudaEventRecord(ev0, 0);
    cudaStreamWaitEvent(s2, ev0, 0);

    // branch (s2): small prereqs for scores, then the big Wout split
    k_split_w<<<(HH * HH + 255) / 256, 256, 0, s2>>>(Wenc);
    k_dec<<<dim3(8, BB), 256, 0, s2>>>(hid, Wdec);
    cudaEventRecord(ev2, s2);
    k_split_wout<<<(int)(((size_t)VV * K2H / 4) / 256), 256, 0, s2>>>(Wout);
    cudaEventRecord(ev3, s2);

    // main chain (stream 0)
    k_split_enc<<<(int)(((size_t)BB * TT * HH / 4) / 256), 256>>>(enc);
    cudaStreamWaitEvent(0, ev2, 0);          // dec + Wenc split ready
    k_scores_mma<<<BB * (TT / 128), 256, SC_TOT>>>(vat);
    k_softmax<<<BB, 256>>>(out_a);
    k_ctx<<<dim3(8, BB), 512>>>(enc);
    k_ctxred<<<32, 1024>>>();
    k_gates<<<G4H / 64, 256>>>(tok, emb, hid, Wih, Whh, bih, bhh);
    k_lstm<<<32, 1024>>>(cell, out_h, out_c);
    cudaStreamWaitEvent(0, ev3, 0);          // Wout split ready
    k_logits_mma<<<(VV + 127) / 128, 256, LG_TOT>>>(bout, out);
}

// round 11
// speedup vs baseline: 1.0666x; 1.0268x over previous
#include <cuda_runtime.h>
#include <cuda_bf16.h>
#include <math.h>
#include <stdint.h>

#define BB 64
#define TT 2048
#define HH 512
#define EE 256
#define VV 50000
#define G4H 2048   /* 4*H  */
#define K2H 1024   /* 2*H  */

// ---------------- scratch (device globals; no allocation) ----------------
__device__ float g_dec[BB * HH];          // h @ W_dec.T          (B,H)
__device__ float g_scores[BB * TT];       // attention scores     (B,T)
__device__ float g_attn[BB * TT];         // softmax(scores)      (B,T)
__device__ float g_ctxp[8 * BB * HH];     // context partials     (8,B,H)
__device__ float g_ctx[BB * HH];          // context              (B,H)
__device__ float g_gates[BB * G4H];       // LSTM gates           (B,4H)
// split-bf16 operands for the scores GEMM
__device__ __nv_bfloat16 g_Ah[(size_t)BB * TT * HH];  // 128 MB
__device__ __nv_bfloat16 g_Al[(size_t)BB * TT * HH];  // 128 MB
__device__ __nv_bfloat16 g_Wh[HH * HH];
__device__ __nv_bfloat16 g_Wl[HH * HH];
// split-bf16 operands for the logits GEMM
__device__ __nv_bfloat16 g_Wouth[(size_t)VV * K2H];   // 102.4 MB
__device__ __nv_bfloat16 g_Woutl[(size_t)VV * K2H];   // 102.4 MB
__device__ __nv_bfloat16 g_Xh[BB * K2H];              // [h_new, ctx] hi
__device__ __nv_bfloat16 g_Xl[BB * K2H];              // [h_new, ctx] lo

// ---------------- packed f32x2 helpers (FFMA2 path, small GEMMs) ----------------
__device__ __forceinline__ unsigned long long pk2(float lo, float hi) {
    unsigned long long r;
    asm("mov.b64 %0, {%1, %2};" : "=l"(r)
        : "r"(__float_as_uint(lo)), "r"(__float_as_uint(hi)));
    return r;
}
__device__ __forceinline__ unsigned long long pkdup(float v) {
    unsigned long long r;
    asm("mov.b64 %0, {%1, %1};" : "=l"(r) : "r"(__float_as_uint(v)));
    return r;
}
__device__ __forceinline__ void fma2(unsigned long long& d,
                                     unsigned long long a,
                                     unsigned long long b) {
    asm("fma.rn.f32x2 %0, %1, %2, %0;" : "+l"(d) : "l"(a), "l"(b));
}
__device__ __forceinline__ float2 upk2(unsigned long long v) {
    unsigned int lo, hi;
    asm("mov.b64 {%0, %1}, %2;" : "=r"(lo), "=r"(hi) : "l"(v));
    return make_float2(__uint_as_float(lo), __uint_as_float(hi));
}
__device__ __forceinline__ float sigf(float x) { return 1.f / (1.f + expf(-x)); }

// ---------------- smem / async / mma helpers (baseline PTX, sm_80+) ----------------
__device__ __forceinline__ uint32_t smem_u32(const void* p) {
    uint32_t a;
    asm("{ .reg .u64 t; cvta.to.shared.u64 t, %1; cvt.u32.u64 %0, t; }"
        : "=r"(a) : "l"(p));
    return a;
}
__device__ __forceinline__ void cpa16(uint32_t dst, const void* src) {
    asm volatile("cp.async.cg.shared.global [%0], [%1], 16;" :: "r"(dst), "l"(src));
}
#define CPA_COMMIT() asm volatile("cp.async.commit_group;" ::: "memory")
#define CPA_WAIT1()  asm volatile("cp.async.wait_group 1;" ::: "memory")
__device__ __forceinline__ uint32_t swz(uint32_t off) { return off ^ ((off >> 3) & 0x70); }

__device__ __forceinline__ void ldm4(uint32_t& r0, uint32_t& r1,
                                     uint32_t& r2, uint32_t& r3, uint32_t addr) {
    asm volatile("ldmatrix.sync.aligned.m8n8.x4.shared.b16 {%0,%1,%2,%3}, [%4];"
        : "=r"(r0), "=r"(r1), "=r"(r2), "=r"(r3) : "r"(addr));
}
__device__ __forceinline__ void mma16816(float* d, const uint32_t* a,
                                         const uint32_t* bf) {
    asm volatile("mma.sync.aligned.m16n8k16.row.col.f32.bf16.bf16.f32 "
        "{%0,%1,%2,%3}, {%4,%5,%6,%7}, {%8,%9}, {%0,%1,%2,%3};"
        : "+f"(d[0]), "+f"(d[1]), "+f"(d[2]), "+f"(d[3])
        : "r"(a[0]), "r"(a[1]), "r"(a[2]), "r"(a[3]), "r"(bf[0]), "r"(bf[1]));
}
__device__ __forceinline__ float tanhx(float x) {
    float e2 = __expf(2.f * x);
    return 1.f - __fdividef(2.f, e2 + 1.f);
}

// ================= prep: split fp32 -> (hi, lo) bf16 =================
__global__ void k_split_w(const float* __restrict__ W) {
    int i = blockIdx.x * 256 + threadIdx.x;
    if (i < HH * HH) {
        float x = W[i];
        __nv_bfloat16 h = __float2bfloat16(x);
        g_Wh[i] = h;
        g_Wl[i] = __float2bfloat16(x - __bfloat162float(h));
    }
}
__global__ void k_split_enc(const float* __restrict__ enc, size_t i0) {
    size_t i = i0 + (size_t)blockIdx.x * 256 + threadIdx.x;  // x4 vectorized
    float4 v = ((const float4*)enc)[i];
    __nv_bfloat16 h0 = __float2bfloat16(v.x), h1 = __float2bfloat16(v.y);
    __nv_bfloat16 h2 = __float2bfloat16(v.z), h3 = __float2bfloat16(v.w);
    __nv_bfloat162 hp0; hp0.x = h0; hp0.y = h1;
    __nv_bfloat162 hp1; hp1.x = h2; hp1.y = h3;
    ((__nv_bfloat162*)g_Ah)[i * 2 + 0] = hp0;
    ((__nv_bfloat162*)g_Ah)[i * 2 + 1] = hp1;
    __nv_bfloat162 lp0, lp1;
    lp0.x = __float2bfloat16(v.x - __bfloat162float(h0));
    lp0.y = __float2bfloat16(v.y - __bfloat162float(h1));
    lp1.x = __float2bfloat16(v.z - __bfloat162float(h2));
    lp1.y = __float2bfloat16(v.w - __bfloat162float(h3));
    ((__nv_bfloat162*)g_Al)[i * 2 + 0] = lp0;
    ((__nv_bfloat162*)g_Al)[i * 2 + 1] = lp1;
}
__global__ void k_split_wout(const float* __restrict__ W) {
    size_t i = (size_t)blockIdx.x * 256 + threadIdx.x;  // x4 vectorized, exact
    float4 v = ((const float4*)W)[i];
    __nv_bfloat16 h0 = __float2bfloat16(v.x), h1 = __float2bfloat16(v.y);
    __nv_bfloat16 h2 = __float2bfloat16(v.z), h3 = __float2bfloat16(v.w);
    __nv_bfloat162 hp0; hp0.x = h0; hp0.y = h1;
    __nv_bfloat162 hp1; hp1.x = h2; hp1.y = h3;
    ((__nv_bfloat162*)g_Wouth)[i * 2 + 0] = hp0;
    ((__nv_bfloat162*)g_Wouth)[i * 2 + 1] = hp1;
    __nv_bfloat162 lp0, lp1;
    lp0.x = __float2bfloat16(v.x - __bfloat162float(h0));
    lp0.y = __float2bfloat16(v.y - __bfloat162float(h1));
    lp1.x = __float2bfloat16(v.z - __bfloat162float(h2));
    lp1.y = __float2bfloat16(v.w - __bfloat162float(h3));
    ((__nv_bfloat162*)g_Woutl)[i * 2 + 0] = lp0;
    ((__nv_bfloat162*)g_Woutl)[i * 2 + 1] = lp1;
}

// ================= K1: dec = h @ W_dec.T  (one warp per output) =================
__global__ void k_dec(const float* __restrict__ hid,
                      const float* __restrict__ Wdec) {
    __shared__ float hs[HH];
    const int b = blockIdx.y;
    const int tid = threadIdx.x, wid = tid >> 5, lane = tid & 31;
    for (int i = tid; i < HH; i += 256) hs[i] = hid[b * HH + i];
    __syncthreads();
#pragma unroll
    for (int j = 0; j < 8; ++j) {                 // 8 warps x 8 h each
        int h = blockIdx.x * 64 + wid * 8 + j;
        const float4* w = (const float4*)(Wdec + (size_t)h * HH);
        float s = 0.f;
#pragma unroll
        for (int i = 0; i < 4; ++i) {
            int k4 = lane + i * 32;
            float4 wv = w[k4];
            s += wv.x * hs[k4 * 4 + 0] + wv.y * hs[k4 * 4 + 1]
               + wv.z * hs[k4 * 4 + 2] + wv.w * hs[k4 * 4 + 3];
        }
#pragma unroll
        for (int m = 16; m >= 1; m >>= 1)
            s += __shfl_xor_sync(0xffffffffu, s, m);
        if (lane == 0) g_dec[b * HH + h] = s;
    }
}

// ================= K2: scores via mma.sync (HMMA) split-bf16 =================
#define SC_SA   0                      // A stages: 2 x 16384
#define SC_SB   32768                  // B stages: 2 x 16384
#define SC_DEC  65536                  // dec row  (2048 B)
#define SC_V    67584                  // v_attn   (2048 B)
#define SC_SC   69632                  // score buf 2x128 floats (1024 B)
#define SC_TOT  70656

__global__ void __launch_bounds__(256, 2)
k_scores_mma(const float* __restrict__ vat, int boff) {
    extern __shared__ __align__(1024) char smem[];
    const uint32_t sb = smem_u32(smem);
    float* decs = (float*)(smem + SC_DEC);
    float* vs   = (float*)(smem + SC_V);
    float* sbuf = (float*)(smem + SC_SC);
    const int tid = threadIdx.x, lane = tid & 31, wid = tid >> 5;
    const int wm = wid & 3, wn = wid >> 2;       // warp tile (32 m) x (64 n)
    const int b = (blockIdx.x >> 4) + boff;
    const int t0 = (blockIdx.x & 15) * 128;

    for (int i = tid; i < HH; i += 256) {
        decs[i] = g_dec[b * HH + i];
        vs[i]   = vat[i];
    }
    __syncthreads();

    auto fill = [&](int st, int it, int n0) {
        const int part = it >> 3, kbase = (it & 7) * 64;
        const __nv_bfloat16* As = (part < 2 ? g_Ah : g_Al) +
            ((size_t)(b * TT + t0)) * HH + kbase;
        const __nv_bfloat16* Bs = (part == 1 ? g_Wl : g_Wh) +
            (size_t)n0 * HH + kbase;
#pragma unroll
        for (int l = 0; l < 4; ++l) {            // A: 128 rows x 8 segs
            int idx = tid + l * 256;
            int r = idx >> 3, sg = idx & 7;
            cpa16(sb + SC_SA + st * 16384 + swz(r * 128 + sg * 16),
                  (const char*)(As + (size_t)r * HH) + sg * 16);
        }
#pragma unroll
        for (int l = 0; l < 4; ++l) {            // B: 128 h-cols x 8 segs
            int idx = tid + l * 256;
            int r = idx >> 3, sg = idx & 7;
            cpa16(sb + SC_SB + st * 16384 + swz(r * 128 + sg * 16),
                  (const char*)(Bs + (size_t)r * HH) + sg * 16);
        }
    };

    float rsc[4] = {0.f, 0.f, 0.f, 0.f};         // 4 owned rows (i x h)

    for (int n = 0; n < 4; ++n) {
        const int n0 = n * 128;
        float d[2][8][4];
#pragma unroll
        for (int i = 0; i < 2; ++i)
#pragma unroll
            for (int j = 0; j < 8; ++j)
#pragma unroll
                for (int q = 0; q < 4; ++q) d[i][j][q] = 0.f;

        fill(0, 0, n0); CPA_COMMIT();
        fill(1, 1, n0); CPA_COMMIT();

        for (int it = 0; it < 24; ++it) {
            const int st = it & 1;
            CPA_WAIT1();
            __syncthreads();
            const uint32_t abase = sb + SC_SA + st * 16384;
            const uint32_t bbase = sb + SC_SB + st * 16384;
#pragma unroll
            for (int ks = 0; ks < 4; ++ks) {     // 4 x k16 per 64-chunk
                uint32_t a[2][4];
#pragma unroll
                for (int i = 0; i < 2; ++i) {
                    int row = wm * 32 + i * 16 + (lane & 15);
                    int off = row * 128 + ks * 32 + (lane >> 4) * 16;
                    ldm4(a[i][0], a[i][1], a[i][2], a[i][3], abase + swz(off));
                }
                uint32_t bf[4][4];
#pragma unroll
                for (int p = 0; p < 4; ++p) {    // 2 n8-tiles per ldmatrix.x4
                    int row = wn * 64 + p * 16 + (lane & 7) + (lane >> 4) * 8;
                    int off = row * 128 + ks * 32 + ((lane >> 3) & 1) * 16;
                    ldm4(bf[p][0], bf[p][1], bf[p][2], bf[p][3], bbase + swz(off));
                }
#pragma unroll
                for (int i = 0; i < 2; ++i)
#pragma unroll
                    for (int j = 0; j < 8; ++j)
                        mma16816(d[i][j], a[i], &bf[j >> 1][(j & 1) * 2]);
            }
            __syncthreads();
            if (it + 2 < 24) fill(st, it + 2, n0);
            CPA_COMMIT();
        }
        // epilogue: tanh(+dec)·v into per-row partials
#pragma unroll
        for (int i = 0; i < 2; ++i)
#pragma unroll
            for (int j = 0; j < 8; ++j) {
                int c = n0 + wn * 64 + j * 8 + (lane & 3) * 2;
                float v0 = vs[c], v1 = vs[c + 1];
                float dc0 = decs[c], dc1 = decs[c + 1];
                rsc[i * 2 + 0] += tanhx(d[i][j][0] + dc0) * v0
                                + tanhx(d[i][j][1] + dc1) * v1;
                rsc[i * 2 + 1] += tanhx(d[i][j][2] + dc0) * v0
                                + tanhx(d[i][j][3] + dc1) * v1;
            }
    }

    // reduce over the 4 lanes of each quad (they share rows, own disjoint cols)
#pragma unroll
    for (int r = 0; r < 4; ++r) {
        rsc[r] += __shfl_xor_sync(0xffffffffu, rsc[r], 1);
        rsc[r] += __shfl_xor_sync(0xffffffffu, rsc[r], 2);
    }
    if ((lane & 3) == 0) {
        int g = lane >> 2;
#pragma unroll
        for (int i = 0; i < 2; ++i)
#pragma unroll
            for (int h = 0; h < 2; ++h)
                sbuf[wn * 128 + wm * 32 + i * 16 + h * 8 + g] = rsc[i * 2 + h];
    }
    __syncthreads();
    if (tid < 128)
        g_scores[b * TT + t0 + tid] = sbuf[tid] + sbuf[128 + tid];
}

// ================= K3: softmax over T per batch =================
__global__ void k_softmax(float* __restrict__ attn_out, int boff) {
    __shared__ float red[256];
    int b = blockIdx.x + boff, tid = threadIdx.x;
    const float* s = g_scores + b * TT;
    float m = -3.4e38f;
    for (int i = tid; i < TT; i += 256) m = fmaxf(m, s[i]);
    red[tid] = m; __syncthreads();
    for (int st = 128; st > 0; st >>= 1) {
        if (tid < st) red[tid] = fmaxf(red[tid], red[tid + st]);
        __syncthreads();
    }
    float M = red[0]; __syncthreads();
    float sum = 0.f;
    for (int i = tid; i < TT; i += 256) {
        float e = expf(s[i] - M);
        g_attn[b * TT + i] = e;
        sum += e;
    }
    red[tid] = sum; __syncthreads();
    for (int st = 128; st > 0; st >>= 1) {
        if (tid < st) red[tid] += red[tid + st];
        __syncthreads();
    }
    float inv = 1.f / red[0];
    for (int i = tid; i < TT; i += 256) {
        float a = g_attn[b * TT + i] * inv;
        g_attn[b * TT + i] = a;
        if (attn_out) attn_out[b * TT + i] = a;
    }
}

// ================= K4: context partials (split-8 over T) =================
__global__ void k_ctx(const float* __restrict__ enc, int boff) {
    __shared__ float as_[256];
    int s = blockIdx.x, b = blockIdx.y + boff;
    int h = threadIdx.x;  // 512 threads
    if (h < 256) as_[h] = g_attn[b * TT + s * 256 + h];
    __syncthreads();
    const float* ep = enc + ((size_t)b * TT + s * 256) * HH + h;
    float a0 = 0.f, a1 = 0.f, a2 = 0.f, a3 = 0.f;
#pragma unroll 4
    for (int t = 0; t < 256; t += 4) {
        a0 += as_[t + 0] * ep[(size_t)(t + 0) * HH];
        a1 += as_[t + 1] * ep[(size_t)(t + 1) * HH];
        a2 += as_[t + 2] * ep[(size_t)(t + 2) * HH];
        a3 += as_[t + 3] * ep[(size_t)(t + 3) * HH];
    }
    g_ctxp[(s * BB + b) * HH + h] = (a0 + a1) + (a2 + a3);
}

__global__ void k_ctxred() {
    int i = blockIdx.x * blockDim.x + threadIdx.x;  // 32768
    float s = 0.f;
#pragma unroll
    for (int p = 0; p < 8; ++p) s += g_ctxp[p * BB * HH + i];
    g_ctx[i] = s;
}

// ================= K5: gates GEMM =================
__global__ void __launch_bounds__(256) k_gates(const int* __restrict__ tok,
                                               const float* __restrict__ emb,
                                               const float* __restrict__ hid,
                                               const float* __restrict__ Wih,
                                               const float* __restrict__ Whh,
                                               const float* __restrict__ bih,
                                               const float* __restrict__ bhh) {
    __shared__ float Ws[32][68];
    __shared__ float Xs[32][68];
    const int tid = threadIdx.x;
    const int g0 = blockIdx.x * 64;
    const int tx = tid & 15, ty = tid >> 4;
    const int r0 = ty * 4, c0 = tx * 4;
    unsigned long long acc[4][2];
#pragma unroll
    for (int i = 0; i < 4; ++i) { acc[i][0] = 0ull; acc[i][1] = 0ull; }

    for (int kt = 0; kt < 40; ++kt) {
        int kbase = kt * 32;
#pragma unroll
        for (int l = 0; l < 2; ++l) {
            int idx = tid + l * 256;
            int row = idx >> 3, kv = (idx & 7) * 4;
            int k = kbase + kv;
            const float* src = (k < 768)
                ? (Wih + (size_t)(g0 + row) * 768 + k)
                : (Whh + (size_t)(g0 + row) * 512 + (k - 768));
            float4 v = *(const float4*)src;
            Ws[kv + 0][row] = v.x; Ws[kv + 1][row] = v.y;
            Ws[kv + 2][row] = v.z; Ws[kv + 3][row] = v.w;
        }
#pragma unroll
        for (int l = 0; l < 2; ++l) {
            int idx = tid + l * 256;
            int bc = idx >> 3, kv = (idx & 7) * 4;
            int k = kbase + kv;
            const float* src;
            if (k < 256)      src = emb + (size_t)tok[bc] * EE + k;
            else if (k < 768) src = g_ctx + bc * HH + (k - 256);
            else              src = hid + bc * HH + (k - 768);
            float4 v = *(const float4*)src;
            Xs[kv + 0][bc] = v.x; Xs[kv + 1][bc] = v.y;
            Xs[kv + 2][bc] = v.z; Xs[kv + 3][bc] = v.w;
        }
        __syncthreads();
#pragma unroll 8
        for (int kk = 0; kk < 32; ++kk) {
            float4 av = *(const float4*)&Ws[kk][r0];
            float4 xv = *(const float4*)&Xs[kk][c0];
            unsigned long long X0 = pk2(xv.x, xv.y);
            unsigned long long X1 = pk2(xv.z, xv.w);
            unsigned long long Ad0 = pkdup(av.x);
            unsigned long long Ad1 = pkdup(av.y);
            unsigned long long Ad2 = pkdup(av.z);
            unsigned long long Ad3 = pkdup(av.w);
            fma2(acc[0][0], Ad0, X0); fma2(acc[0][1], Ad0, X1);
            fma2(acc[1][0], Ad1, X0); fma2(acc[1][1], Ad1, X1);
            fma2(acc[2][0], Ad2, X0); fma2(acc[2][1], Ad2, X1);
            fma2(acc[3][0], Ad3, X0); fma2(acc[3][1], Ad3, X1);
        }
        __syncthreads();
    }
#pragma unroll
    for (int i = 0; i < 4; ++i) {
        int g = g0 + r0 + i;
        float bias = bih[g] + bhh[g];
#pragma unroll
        for (int p = 0; p < 2; ++p) {
            float2 e = upk2(acc[i][p]);
            int bc = c0 + 2 * p;
            g_gates[bc * G4H + g]       = e.x + bias;
            g_gates[(bc + 1) * G4H + g] = e.y + bias;
        }
    }
}

// ================= K6: LSTM pointwise; emit split-bf16 xout =================
__global__ void k_lstm(const float* __restrict__ cell,
                       float* __restrict__ hout, float* __restrict__ cout) {
    int i = blockIdx.x * blockDim.x + threadIdx.x;  // 32768
    int b = i >> 9, h = i & 511;
    float ig = g_gates[b * G4H + h];
    float fg = g_gates[b * G4H + 512 + h];
    float gg = g_gates[b * G4H + 1024 + h];
    float og = g_gates[b * G4H + 1536 + h];
    float c = sigf(fg) * cell[i] + sigf(ig) * tanhf(gg);
    float hn = sigf(og) * tanhf(c);
    if (hout) { hout[i] = hn; cout[i] = c; }
    float cx = g_ctx[i];
    __nv_bfloat16 hh = __float2bfloat16(hn);
    __nv_bfloat16 ch = __float2bfloat16(cx);
    g_Xh[b * K2H + h]        = hh;
    g_Xl[b * K2H + h]        = __float2bfloat16(hn - __bfloat162float(hh));
    g_Xh[b * K2H + 512 + h]  = ch;
    g_Xl[b * K2H + 512 + h]  = __float2bfloat16(cx - __bfloat162float(ch));
}

// ================= K7: logits via mma.sync (HMMA) split-bf16 =================
#define LG_SA   0                      // Wh/Wl stages: 2 x 32768
#define LG_SB   65536                  // Xh/Xl stages: 2 x 16384
#define LG_TOT  98304

__global__ void __launch_bounds__(256, 2)
k_logits_mma(const float* __restrict__ bout, float* __restrict__ out) {
    extern __shared__ __align__(1024) char smem[];
    const uint32_t sb = smem_u32(smem);
    const int tid = threadIdx.x, lane = tid & 31, wid = tid >> 5;
    const int wm = wid & 3, wn = wid >> 2;       // warp tile (32 m) x (32 n)
    const int v0 = blockIdx.x * 128;

    auto fill = [&](int st, int kt) {
        const int kbase = kt * 64;
#pragma unroll
        for (int l = 0; l < 4; ++l) {            // A: 128 rows x 8 segs (h & l)
            int idx = tid + l * 256;
            int r = idx >> 3, sg = idx & 7;
            int vr = v0 + r; if (vr >= VV) vr = VV - 1;
            uint32_t so = swz(r * 128 + sg * 16);
            cpa16(sb + LG_SA + st * 32768 + so,
                  (const char*)(g_Wouth + (size_t)vr * K2H + kbase) + sg * 16);
            cpa16(sb + LG_SA + st * 32768 + 16384 + so,
                  (const char*)(g_Woutl + (size_t)vr * K2H + kbase) + sg * 16);
        }
#pragma unroll
        for (int l = 0; l < 2; ++l) {            // B: 64 rows x 8 segs (h & l)
            int idx = tid + l * 256;
            int r = idx >> 3, sg = idx & 7;
            uint32_t so = swz(r * 128 + sg * 16);
            cpa16(sb + LG_SB + st * 16384 + so,
                  (const char*)(g_Xh + (size_t)r * K2H + kbase) + sg * 16);
            cpa16(sb + LG_SB + st * 16384 + 8192 + so,
                  (const char*)(g_Xl + (size_t)r * K2H + kbase) + sg * 16);
        }
    };

    float d[2][4][4];
#pragma unroll
    for (int i = 0; i < 2; ++i)
#pragma unroll
        for (int j = 0; j < 4; ++j)
#pragma unroll
            for (int q = 0; q < 4; ++q) d[i][j][q] = 0.f;

    fill(0, 0); CPA_COMMIT();
    fill(1, 1); CPA_COMMIT();

    for (int kt = 0; kt < 16; ++kt) {
        const int st = kt & 1;
        CPA_WAIT1();
        __syncthreads();
        const uint32_t ahb = sb + LG_SA + st * 32768;
        const uint32_t alb = ahb + 16384;
        const uint32_t bhb = sb + LG_SB + st * 16384;
        const uint32_t blb = bhb + 8192;
#pragma unroll
        for (int ks = 0; ks < 4; ++ks) {
            uint32_t ah[2][4], al[2][4];
#pragma unroll
            for (int i = 0; i < 2; ++i) {
                int row = wm * 32 + i * 16 + (lane & 15);
                uint32_t so = swz(row * 128 + ks * 32 + (lane >> 4) * 16);
                ldm4(ah[i][0], ah[i][1], ah[i][2], ah[i][3], ahb + so);
                ldm4(al[i][0], al[i][1], al[i][2], al[i][3], alb + so);
            }
            uint32_t bh[2][4], bl[2][4];
#pragma unroll
            for (int p = 0; p < 2; ++p) {
                int row = wn * 32 + p * 16 + (lane & 7) + (lane >> 4) * 8;
                uint32_t so = swz(row * 128 + ks * 32 + ((lane >> 3) & 1) * 16);
                ldm4(bh[p][0], bh[p][1], bh[p][2], bh[p][3], bhb + so);
                ldm4(bl[p][0], bl[p][1], bl[p][2], bl[p][3], blb + so);
            }
#pragma unroll
            for (int i = 0; i < 2; ++i)
#pragma unroll
                for (int j = 0; j < 4; ++j) {
                    mma16816(d[i][j], ah[i], &bh[j >> 1][(j & 1) * 2]);
                    mma16816(d[i][j], ah[i], &bl[j >> 1][(j & 1) * 2]);
                    mma16816(d[i][j], al[i], &bh[j >> 1][(j & 1) * 2]);
                }
        }
        __syncthreads();
        if (kt + 2 < 16) fill(st, kt + 2);
        CPA_COMMIT();
    }

    // epilogue: transpose through smem (overlays stage A), bias, coalesced write
    __syncthreads();
    float* sbuf = (float*)smem;   // [64][132]
#pragma unroll
    for (int i = 0; i < 2; ++i)
#pragma unroll
        for (int j = 0; j < 4; ++j)
#pragma unroll
            for (int q = 0; q < 4; ++q) {
                int r = wm * 32 + i * 16 + (lane >> 2) + (q >> 1) * 8;
                int c = wn * 32 + j * 8 + (lane & 3) * 2 + (q & 1);
                sbuf[c * 132 + r] = d[i][j][q];
            }
    __syncthreads();
#pragma unroll
    for (int l = 0; l < 32; ++l) {
        int idx = tid + l * 256;
        int bc = idx >> 7, r = idx & 127;
        int v = v0 + r;
        if (v < VV) out[(size_t)bc * VV + v] = sbuf[bc * 132 + r] + bout[v];
    }
}

// ================= host launcher (halved pipeline, static resources) =================
extern "C" void kernel_launch(void* const* d_in, const int* in_sizes, int n_in,
                              void* d_out, int out_size) {
    const int*   tok  = (const int*)d_in[0];
    const float* hid  = (const float*)d_in[1];
    const float* cell = (const float*)d_in[2];
    const float* enc  = (const float*)d_in[3];
    const float* emb  = (const float*)d_in[4];
    const float* Wenc = (const float*)d_in[5];
    const float* Wdec = (const float*)d_in[6];
    const float* vat  = (const float*)d_in[7];
    const float* Wih  = (const float*)d_in[8];
    const float* Whh  = (const float*)d_in[9];
    const float* bih  = (const float*)d_in[10];
    const float* bhh  = (const float*)d_in[11];
    const float* Wout = (const float*)d_in[12];
    const float* bout = (const float*)d_in[13];
    float* out = (float*)d_out;

    const long long full = (long long)BB * VV + 2LL * BB * HH + (long long)BB * TT;
    bool has_aux = ((long long)out_size >= full);
    float* out_h = has_aux ? out + (size_t)BB * VV : nullptr;
    float* out_c = has_aux ? out + (size_t)BB * VV + BB * HH : nullptr;
    float* out_a = has_aux ? out + (size_t)BB * VV + 2 * BB * HH : nullptr;

    // Create streams/events ONCE (before the pre-capture memory baseline is
    // taken) so graph capture/teardown sees no allocation delta.
    static bool s_init = false;
    static cudaStream_t s2, s3;
    static cudaEvent_t evF, evDec, evE1, evW, evS0, evS1, evC;
    if (!s_init) {
        s_init = true;
        cudaStreamCreateWithFlags(&s2, cudaStreamNonBlocking);
        cudaStreamCreateWithFlags(&s3, cudaStreamNonBlocking);
        cudaEventCreateWithFlags(&evF,   cudaEventDisableTiming);
        cudaEventCreateWithFlags(&evDec, cudaEventDisableTiming);
        cudaEventCreateWithFlags(&evE1,  cudaEventDisableTiming);
        cudaEventCreateWithFlags(&evW,   cudaEventDisableTiming);
        cudaEventCreateWithFlags(&evS0,  cudaEventDisableTiming);
        cudaEventCreateWithFlags(&evS1,  cudaEventDisableTiming);
        cudaEventCreateWithFlags(&evC,   cudaEventDisableTiming);
        cudaFuncSetAttribute(k_scores_mma,
                             cudaFuncAttributeMaxDynamicSharedMemorySize, SC_TOT);
        cudaFuncSetAttribute(k_logits_mma,
                             cudaFuncAttributeMaxDynamicSharedMemorySize, LG_TOT);
    }

    const size_t HE = (size_t)32 * TT * HH / 4;     // float4 elems per 32 batches
    const int HG = (int)(HE / 256);                 // split_enc blocks per half

    // fork
    cudaEventRecord(evF, 0);
    cudaStreamWaitEvent(s2, evF, 0);

    // s2: scores prereqs, enc half 1, then Wout split (hidden under scores)
    k_split_w<<<(HH * HH + 255) / 256, 256, 0, s2>>>(Wenc);
    k_dec<<<dim3(8, BB), 256, 0, s2>>>(hid, Wdec);
    cudaEventRecord(evDec, s2);
    k_split_enc<<<HG, 256, 0, s2>>>(enc, HE);       // half 1
    cudaEventRecord(evE1, s2);
    k_split_wout<<<(int)(((size_t)VV * K2H / 4) / 256), 256, 0, s2>>>(Wout);
    cudaEventRecord(evW, s2);

    // stream 0: enc half 0, scores half 0 (512 CTAs)
    k_split_enc<<<HG, 256>>>(enc, 0);               // half 0
    cudaStreamWaitEvent(0, evDec, 0);
    k_scores_mma<<<32 * 16, 256, SC_TOT>>>(vat, 0);
    cudaEventRecord(evS0, 0);

    // s3: scores half 1 — overlaps half 0's drain (continuous CTA pool)
    cudaStreamWaitEvent(s3, evE1, 0);               // implies dec done (s2 order)
    k_scores_mma<<<32 * 16, 256, SC_TOT, s3>>>(vat, 32);
    cudaEventRecord(evS1, s3);

    // s2: softmax + ctx for half 0, hidden under scores half 1
    cudaStreamWaitEvent(s2, evS0, 0);
    k_softmax<<<32, 256, 0, s2>>>(out_a, 0);
    k_ctx<<<dim3(8, 32), 512, 0, s2>>>(enc, 0);
    cudaEventRecord(evC, s2);

    // stream 0: half 1 softmax/ctx + tail
    cudaStreamWaitEvent(0, evS1, 0);
    k_softmax<<<32, 256>>>(out_a, 32);
    k_ctx<<<dim3(8, 32), 512>>>(enc, 32);
    cudaStreamWaitEvent(0, evC, 0);
    k_ctxred<<<32, 1024>>>();
    k_gates<<<G4H / 64, 256>>>(tok, emb, hid, Wih, Whh, bih, bhh);
    k_lstm<<<32, 1024>>>(cell, out_h, out_c);
    cudaStreamWaitEvent(0, evW, 0);
    k_logits_mma<<<(VV + 127) / 128, 256, LG_TOT>>>(bout, out);
}

// round 13
// speedup vs baseline: 1.2840x; 1.2038x over previous
#include <cuda_runtime.h>
#include <cuda_bf16.h>
#include <cuda_fp16.h>
#include <math.h>
#include <stdint.h>

#define BB 64
#define TT 2048
#define HH 512
#define EE 256
#define VV 50000
#define G4H 2048   /* 4*H  */
#define K2H 1024   /* 2*H  */

// ---------------- scratch (device globals; no allocation) ----------------
__device__ float g_dec[BB * HH];          // h @ W_dec.T          (B,H)
__device__ float g_scores[BB * TT];       // attention scores     (B,T)
__device__ float g_attn[BB * TT];         // softmax(scores)      (B,T)
__device__ float g_ctxp[8 * BB * HH];     // context partials     (8,B,H)
__device__ float g_ctx[BB * HH];          // context              (B,H)
__device__ float g_gates[BB * G4H];       // LSTM gates           (B,4H)
// split-fp16 operands for the scores GEMM (A = Ah + Al, B = fp16 round)
__device__ __half g_Ah[(size_t)BB * TT * HH];  // 128 MB
__device__ __half g_Al[(size_t)BB * TT * HH];  // 128 MB
__device__ __half g_Wh[HH * HH];
// split-bf16 operands for the logits GEMM
__device__ __nv_bfloat16 g_Wouth[(size_t)VV * K2H];   // 102.4 MB
__device__ __nv_bfloat16 g_Woutl[(size_t)VV * K2H];   // 102.4 MB
__device__ __nv_bfloat16 g_Xh[BB * K2H];              // [h_new, ctx] hi
__device__ __nv_bfloat16 g_Xl[BB * K2H];              // [h_new, ctx] lo

// ---------------- packed f32x2 helpers (FFMA2 path, small GEMMs) ----------------
__device__ __forceinline__ unsigned long long pk2(float lo, float hi) {
    unsigned long long r;
    asm("mov.b64 %0, {%1, %2};" : "=l"(r)
        : "r"(__float_as_uint(lo)), "r"(__float_as_uint(hi)));
    return r;
}
__device__ __forceinline__ unsigned long long pkdup(float v) {
    unsigned long long r;
    asm("mov.b64 %0, {%1, %1};" : "=l"(r) : "r"(__float_as_uint(v)));
    return r;
}
__device__ __forceinline__ void fma2(unsigned long long& d,
                                     unsigned long long a,
                                     unsigned long long b) {
    asm("fma.rn.f32x2 %0, %1, %2, %0;" : "+l"(d) : "l"(a), "l"(b));
}
__device__ __forceinline__ float2 upk2(unsigned long long v) {
    unsigned int lo, hi;
    asm("mov.b64 {%0, %1}, %2;" : "=r"(lo), "=r"(hi) : "l"(v));
    return make_float2(__uint_as_float(lo), __uint_as_float(hi));
}
__device__ __forceinline__ float sigf(float x) { return 1.f / (1.f + expf(-x)); }

// ---------------- smem / async / mma helpers (baseline PTX, sm_80+) ----------------
__device__ __forceinline__ uint32_t smem_u32(const void* p) {
    uint32_t a;
    asm("{ .reg .u64 t; cvta.to.shared.u64 t, %1; cvt.u32.u64 %0, t; }"
        : "=r"(a) : "l"(p));
    return a;
}
__device__ __forceinline__ void cpa16(uint32_t dst, const void* src) {
    asm volatile("cp.async.cg.shared.global [%0], [%1], 16;" :: "r"(dst), "l"(src));
}
#define CPA_COMMIT() asm volatile("cp.async.commit_group;" ::: "memory")
#define CPA_WAIT1()  asm volatile("cp.async.wait_group 1;" ::: "memory")
__device__ __forceinline__ uint32_t swz(uint32_t off) { return off ^ ((off >> 3) & 0x70); }

__device__ __forceinline__ void ldm4(uint32_t& r0, uint32_t& r1,
                                     uint32_t& r2, uint32_t& r3, uint32_t addr) {
    asm volatile("ldmatrix.sync.aligned.m8n8.x4.shared.b16 {%0,%1,%2,%3}, [%4];"
        : "=r"(r0), "=r"(r1), "=r"(r2), "=r"(r3) : "r"(addr));
}
__device__ __forceinline__ void mma16816(float* d, const uint32_t* a,
                                         const uint32_t* bf) {
    asm volatile("mma.sync.aligned.m16n8k16.row.col.f32.bf16.bf16.f32 "
        "{%0,%1,%2,%3}, {%4,%5,%6,%7}, {%8,%9}, {%0,%1,%2,%3};"
        : "+f"(d[0]), "+f"(d[1]), "+f"(d[2]), "+f"(d[3])
        : "r"(a[0]), "r"(a[1]), "r"(a[2]), "r"(a[3]), "r"(bf[0]), "r"(bf[1]));
}
__device__ __forceinline__ void mma16816h(float* d, const uint32_t* a,
                                          const uint32_t* bf) {
    asm volatile("mma.sync.aligned.m16n8k16.row.col.f32.f16.f16.f32 "
        "{%0,%1,%2,%3}, {%4,%5,%6,%7}, {%8,%9}, {%0,%1,%2,%3};"
        : "+f"(d[0]), "+f"(d[1]), "+f"(d[2]), "+f"(d[3])
        : "r"(a[0]), "r"(a[1]), "r"(a[2]), "r"(a[3]), "r"(bf[0]), "r"(bf[1]));
}
__device__ __forceinline__ float tanhx(float x) {
    float e2 = __expf(2.f * x);
    return 1.f - __fdividef(2.f, e2 + 1.f);
}

// ================= prep: fp16 weight round / fp16 hi-lo enc split =================
__global__ void k_split_w(const float* __restrict__ W) {
    int i = blockIdx.x * 256 + threadIdx.x;
    if (i < HH * HH) g_Wh[i] = __float2half_rn(W[i]);
}
__global__ void k_split_enc(const float* __restrict__ enc, size_t i0) {
    size_t i = i0 + (size_t)blockIdx.x * 256 + threadIdx.x;  // x4 vectorized
    float4 v = ((const float4*)enc)[i];
    __half h0 = __float2half_rn(v.x), h1 = __float2half_rn(v.y);
    __half h2 = __float2half_rn(v.z), h3 = __float2half_rn(v.w);
    __half2 hp0; hp0.x = h0; hp0.y = h1;
    __half2 hp1; hp1.x = h2; hp1.y = h3;
    ((__half2*)g_Ah)[i * 2 + 0] = hp0;
    ((__half2*)g_Ah)[i * 2 + 1] = hp1;
    __half2 lp0, lp1;
    lp0.x = __float2half_rn(v.x - __half2float(h0));
    lp0.y = __float2half_rn(v.y - __half2float(h1));
    lp1.x = __float2half_rn(v.z - __half2float(h2));
    lp1.y = __float2half_rn(v.w - __half2float(h3));
    ((__half2*)g_Al)[i * 2 + 0] = lp0;
    ((__half2*)g_Al)[i * 2 + 1] = lp1;
}
__global__ void k_split_wout(const float* __restrict__ W) {
    size_t i = (size_t)blockIdx.x * 256 + threadIdx.x;  // x4 vectorized, exact
    float4 v = ((const float4*)W)[i];
    __nv_bfloat16 h0 = __float2bfloat16(v.x), h1 = __float2bfloat16(v.y);
    __nv_bfloat16 h2 = __float2bfloat16(v.z), h3 = __float2bfloat16(v.w);
    __nv_bfloat162 hp0; hp0.x = h0; hp0.y = h1;
    __nv_bfloat162 hp1; hp1.x = h2; hp1.y = h3;
    ((__nv_bfloat162*)g_Wouth)[i * 2 + 0] = hp0;
    ((__nv_bfloat162*)g_Wouth)[i * 2 + 1] = hp1;
    __nv_bfloat162 lp0, lp1;
    lp0.x = __float2bfloat16(v.x - __bfloat162float(h0));
    lp0.y = __float2bfloat16(v.y - __bfloat162float(h1));
    lp1.x = __float2bfloat16(v.z - __bfloat162float(h2));
    lp1.y = __float2bfloat16(v.w - __bfloat162float(h3));
    ((__nv_bfloat162*)g_Woutl)[i * 2 + 0] = lp0;
    ((__nv_bfloat162*)g_Woutl)[i * 2 + 1] = lp1;
}

// ================= K1: dec = h @ W_dec.T  (one warp per output) =================
__global__ void k_dec(const float* __restrict__ hid,
                      const float* __restrict__ Wdec) {
    __shared__ float hs[HH];
    const int b = blockIdx.y;
    const int tid = threadIdx.x, wid = tid >> 5, lane = tid & 31;
    for (int i = tid; i < HH; i += 256) hs[i] = hid[b * HH + i];
    __syncthreads();
#pragma unroll
    for (int j = 0; j < 8; ++j) {                 // 8 warps x 8 h each
        int h = blockIdx.x * 64 + wid * 8 + j;
        const float4* w = (const float4*)(Wdec + (size_t)h * HH);
        float s = 0.f;
#pragma unroll
        for (int i = 0; i < 4; ++i) {
            int k4 = lane + i * 32;
            float4 wv = w[k4];
            s += wv.x * hs[k4 * 4 + 0] + wv.y * hs[k4 * 4 + 1]
               + wv.z * hs[k4 * 4 + 2] + wv.w * hs[k4 * 4 + 3];
        }
#pragma unroll
        for (int m = 16; m >= 1; m >>= 1)
            s += __shfl_xor_sync(0xffffffffu, s, m);
        if (lane == 0) g_dec[b * HH + h] = s;
    }
}

// ================= K2: scores via mma.sync (HMMA) split-fp16 =================
// D = Ah·Wh^T + Al·Wh^T  (2 products, K'=1024 in 16 chunks of 64)
#define SC_SA   0                      // A stages: 2 x 16384
#define SC_SB   32768                  // B stages: 2 x 16384
#define SC_DEC  65536                  // dec row  (2048 B)
#define SC_V    67584                  // v_attn   (2048 B)
#define SC_SC   69632                  // score buf 2x128 floats (1024 B)
#define SC_TOT  70656

__global__ void __launch_bounds__(256, 2)
k_scores_mma(const float* __restrict__ vat, int boff) {
    extern __shared__ __align__(1024) char smem[];
    const uint32_t sb = smem_u32(smem);
    float* decs = (float*)(smem + SC_DEC);
    float* vs   = (float*)(smem + SC_V);
    float* sbuf = (float*)(smem + SC_SC);
    const int tid = threadIdx.x, lane = tid & 31, wid = tid >> 5;
    const int wm = wid & 3, wn = wid >> 2;       // warp tile (32 m) x (64 n)
    const int b = (blockIdx.x >> 4) + boff;
    const int t0 = (blockIdx.x & 15) * 128;

    for (int i = tid; i < HH; i += 256) {
        decs[i] = g_dec[b * HH + i];
        vs[i]   = vat[i];
    }
    __syncthreads();

    auto fill = [&](int st, int it, int n0) {
        const int part = it >> 3, kbase = (it & 7) * 64;
        const __half* As = (part ? g_Al : g_Ah) +
            ((size_t)(b * TT + t0)) * HH + kbase;
        const __half* Bs = g_Wh + (size_t)n0 * HH + kbase;
#pragma unroll
        for (int l = 0; l < 4; ++l) {            // A: 128 rows x 8 segs
            int idx = tid + l * 256;
            int r = idx >> 3, sg = idx & 7;
            cpa16(sb + SC_SA + st * 16384 + swz(r * 128 + sg * 16),
                  (const char*)(As + (size_t)r * HH) + sg * 16);
        }
#pragma unroll
        for (int l = 0; l < 4; ++l) {            // B: 128 h-cols x 8 segs
            int idx = tid + l * 256;
            int r = idx >> 3, sg = idx & 7;
            cpa16(sb + SC_SB + st * 16384 + swz(r * 128 + sg * 16),
                  (const char*)(Bs + (size_t)r * HH) + sg * 16);
        }
    };

    float rsc[4] = {0.f, 0.f, 0.f, 0.f};         // 4 owned rows (i x h)

    for (int n = 0; n < 4; ++n) {
        const int n0 = n * 128;
        float d[2][8][4];
#pragma unroll
        for (int i = 0; i < 2; ++i)
#pragma unroll
            for (int j = 0; j < 8; ++j)
#pragma unroll
                for (int q = 0; q < 4; ++q) d[i][j][q] = 0.f;

        fill(0, 0, n0); CPA_COMMIT();
        fill(1, 1, n0); CPA_COMMIT();

        for (int it = 0; it < 16; ++it) {
            const int st = it & 1;
            CPA_WAIT1();
            __syncthreads();
            const uint32_t abase = sb + SC_SA + st * 16384;
            const uint32_t bbase = sb + SC_SB + st * 16384;
#pragma unroll
            for (int ks = 0; ks < 4; ++ks) {     // 4 x k16 per 64-chunk
                uint32_t a[2][4];
#pragma unroll
                for (int i = 0; i < 2; ++i) {
                    int row = wm * 32 + i * 16 + (lane & 15);
                    int off = row * 128 + ks * 32 + (lane >> 4) * 16;
                    ldm4(a[i][0], a[i][1], a[i][2], a[i][3], abase + swz(off));
                }
                uint32_t bf[4][4];
#pragma unroll
                for (int p = 0; p < 4; ++p) {    // 2 n8-tiles per ldmatrix.x4
                    int row = wn * 64 + p * 16 + (lane & 7) + (lane >> 4) * 8;
                    int off = row * 128 + ks * 32 + ((lane >> 3) & 1) * 16;
                    ldm4(bf[p][0], bf[p][1], bf[p][2], bf[p][3], bbase + swz(off));
                }
#pragma unroll
                for (int i = 0; i < 2; ++i)
#pragma unroll
                    for (int j = 0; j < 8; ++j)
                        mma16816h(d[i][j], a[i], &bf[j >> 1][(j & 1) * 2]);
            }
            __syncthreads();
            if (it + 2 < 16) fill(st, it + 2, n0);
            CPA_COMMIT();
        }
        // epilogue: tanh(+dec)·v into per-row partials
#pragma unroll
        for (int i = 0; i < 2; ++i)
#pragma unroll
            for (int j = 0; j < 8; ++j) {
                int c = n0 + wn * 64 + j * 8 + (lane & 3) * 2;
                float v0 = vs[c], v1 = vs[c + 1];
                float dc0 = decs[c], dc1 = decs[c + 1];
                rsc[i * 2 + 0] += tanhx(d[i][j][0] + dc0) * v0
                                + tanhx(d[i][j][1] + dc1) * v1;
                rsc[i * 2 + 1] += tanhx(d[i][j][2] + dc0) * v0
                                + tanhx(d[i][j][3] + dc1) * v1;
            }
    }

    // reduce over the 4 lanes of each quad (they share rows, own disjoint cols)
#pragma unroll
    for (int r = 0; r < 4; ++r) {
        rsc[r] += __shfl_xor_sync(0xffffffffu, rsc[r], 1);
        rsc[r] += __shfl_xor_sync(0xffffffffu, rsc[r], 2);
    }
    if ((lane & 3) == 0) {
        int g = lane >> 2;
#pragma unroll
        for (int i = 0; i < 2; ++i)
#pragma unroll
            for (int h = 0; h < 2; ++h)
                sbuf[wn * 128 + wm * 32 + i * 16 + h * 8 + g] = rsc[i * 2 + h];
    }
    __syncthreads();
    if (tid < 128)
        g_scores[b * TT + t0 + tid] = sbuf[tid] + sbuf[128 + tid];
}

// ================= K3: softmax over T per batch =================
__global__ void k_softmax(float* __restrict__ attn_out, int boff) {
    __shared__ float red[256];
    int b = blockIdx.x + boff, tid = threadIdx.x;
    const float* s = g_scores + b * TT;
    float m = -3.4e38f;
    for (int i = tid; i < TT; i += 256) m = fmaxf(m, s[i]);
    red[tid] = m; __syncthreads();
    for (int st = 128; st > 0; st >>= 1) {
        if (tid < st) red[tid] = fmaxf(red[tid], red[tid + st]);
        __syncthreads();
    }
    float M = red[0]; __syncthreads();
    float sum = 0.f;
    for (int i = tid; i < TT; i += 256) {
        float e = expf(s[i] - M);
        g_attn[b * TT + i] = e;
        sum += e;
    }
    red[tid] = sum; __syncthreads();
    for (int st = 128; st > 0; st >>= 1) {
        if (tid < st) red[tid] += red[tid + st];
        __syncthreads();
    }
    float inv = 1.f / red[0];
    for (int i = tid; i < TT; i += 256) {
        float a = g_attn[b * TT + i] * inv;
        g_attn[b * TT + i] = a;
        if (attn_out) attn_out[b * TT + i] = a;
    }
}

// ================= K4: context partials (split-8 over T) =================
__global__ void k_ctx(const float* __restrict__ enc, int boff) {
    __shared__ float as_[256];
    int s = blockIdx.x, b = blockIdx.y + boff;
    int h = threadIdx.x;  // 512 threads
    if (h < 256) as_[h] = g_attn[b * TT + s * 256 + h];
    __syncthreads();
    const float* ep = enc + ((size_t)b * TT + s * 256) * HH + h;
    float a0 = 0.f, a1 = 0.f, a2 = 0.f, a3 = 0.f;
#pragma unroll 4
    for (int t = 0; t < 256; t += 4) {
        a0 += as_[t + 0] * ep[(size_t)(t + 0) * HH];
        a1 += as_[t + 1] * ep[(size_t)(t + 1) * HH];
        a2 += as_[t + 2] * ep[(size_t)(t + 2) * HH];
        a3 += as_[t + 3] * ep[(size_t)(t + 3) * HH];
    }
    g_ctxp[(s * BB + b) * HH + h] = (a0 + a1) + (a2 + a3);
}

__global__ void k_ctxred() {
    int i = blockIdx.x * blockDim.x + threadIdx.x;  // 32768
    float s = 0.f;
#pragma unroll
    for (int p = 0; p < 8; ++p) s += g_ctxp[p * BB * HH + i];
    g_ctx[i] = s;
}

// ================= K5: gates GEMM =================
__global__ void __launch_bounds__(256) k_gates(const int* __restrict__ tok,
                                               const float* __restrict__ emb,
                                               const float* __restrict__ hid,
                                               const float* __restrict__ Wih,
                                               const float* __restrict__ Whh,
                                               const float* __restrict__ bih,
                                               const float* __restrict__ bhh) {
    __shared__ float Ws[32][68];
    __shared__ float Xs[32][68];
    const int tid = threadIdx.x;
    const int g0 = blockIdx.x * 64;
    const int tx = tid & 15, ty = tid >> 4;
    const int r0 = ty * 4, c0 = tx * 4;
    unsigned long long acc[4][2];
#pragma unroll
    for (int i = 0; i < 4; ++i) { acc[i][0] = 0ull; acc[i][1] = 0ull; }

    for (int kt = 0; kt < 40; ++kt) {
        int kbase = kt * 32;
#pragma unroll
        for (int l = 0; l < 2; ++l) {
            int idx = tid + l * 256;
            int row = idx >> 3, kv = (idx & 7) * 4;
            int k = kbase + kv;
            const float* src = (k < 768)
                ? (Wih + (size_t)(g0 + row) * 768 + k)
                : (Whh + (size_t)(g0 + row) * 512 + (k - 768));
            float4 v = *(const float4*)src;
            Ws[kv + 0][row] = v.x; Ws[kv + 1][row] = v.y;
            Ws[kv + 2][row] = v.z; Ws[kv + 3][row] = v.w;
        }
#pragma unroll
        for (int l = 0; l < 2; ++l) {
            int idx = tid + l * 256;
            int bc = idx >> 3, kv = (idx & 7) * 4;
            int k = kbase + kv;
            const float* src;
            if (k < 256)      src = emb + (size_t)tok[bc] * EE + k;
            else if (k < 768) src = g_ctx + bc * HH + (k - 256);
            else              src = hid + bc * HH + (k - 768);
            float4 v = *(const float4*)src;
            Xs[kv + 0][bc] = v.x; Xs[kv + 1][bc] = v.y;
            Xs[kv + 2][bc] = v.z; Xs[kv + 3][bc] = v.w;
        }
        __syncthreads();
#pragma unroll 8
        for (int kk = 0; kk < 32; ++kk) {
            float4 av = *(const float4*)&Ws[kk][r0];
            float4 xv = *(const float4*)&Xs[kk][c0];
            unsigned long long X0 = pk2(xv.x, xv.y);
            unsigned long long X1 = pk2(xv.z, xv.w);
            unsigned long long Ad0 = pkdup(av.x);
            unsigned long long Ad1 = pkdup(av.y);
            unsigned long long Ad2 = pkdup(av.z);
            unsigned long long Ad3 = pkdup(av.w);
            fma2(acc[0][0], Ad0, X0); fma2(acc[0][1], Ad0, X1);
            fma2(acc[1][0], Ad1, X0); fma2(acc[1][1], Ad1, X1);
            fma2(acc[2][0], Ad2, X0); fma2(acc[2][1], Ad2, X1);
            fma2(acc[3][0], Ad3, X0); fma2(acc[3][1], Ad3, X1);
        }
        __syncthreads();
    }
#pragma unroll
    for (int i = 0; i < 4; ++i) {
        int g = g0 + r0 + i;
        float bias = bih[g] + bhh[g];
#pragma unroll
        for (int p = 0; p < 2; ++p) {
            float2 e = upk2(acc[i][p]);
            int bc = c0 + 2 * p;
            g_gates[bc * G4H + g]       = e.x + bias;
            g_gates[(bc + 1) * G4H + g] = e.y + bias;
        }
    }
}

// ================= K6: LSTM pointwise; emit split-bf16 xout =================
__global__ void k_lstm(const float* __restrict__ cell,
                       float* __restrict__ hout, float* __restrict__ cout) {
    int i = blockIdx.x * blockDim.x + threadIdx.x;  // 32768
    int b = i >> 9, h = i & 511;
    float ig = g_gates[b * G4H + h];
    float fg = g_gates[b * G4H + 512 + h];
    float gg = g_gates[b * G4H + 1024 + h];
    float og = g_gates[b * G4H + 1536 + h];
    float c = sigf(fg) * cell[i] + sigf(ig) * tanhf(gg);
    float hn = sigf(og) * tanhf(c);
    if (hout) { hout[i] = hn; cout[i] = c; }
    float cx = g_ctx[i];
    __nv_bfloat16 hh = __float2bfloat16(hn);
    __nv_bfloat16 ch = __float2bfloat16(cx);
    g_Xh[b * K2H + h]        = hh;
    g_Xl[b * K2H + h]        = __float2bfloat16(hn - __bfloat162float(hh));
    g_Xh[b * K2H + 512 + h]  = ch;
    g_Xl[b * K2H + 512 + h]  = __float2bfloat16(cx - __bfloat162float(ch));
}

// ================= K7: logits via mma.sync (HMMA) split-bf16 =================
#define LG_SA   0                      // Wh/Wl stages: 2 x 32768
#define LG_SB   65536                  // Xh/Xl stages: 2 x 16384
#define LG_TOT  98304

__global__ void __launch_bounds__(256, 2)
k_logits_mma(const float* __restrict__ bout, float* __restrict__ out) {
    extern __shared__ __align__(1024) char smem[];
    const uint32_t sb = smem_u32(smem);
    const int tid = threadIdx.x, lane = tid & 31, wid = tid >> 5;
    const int wm = wid & 3, wn = wid >> 2;       // warp tile (32 m) x (32 n)
    const int v0 = blockIdx.x * 128;

    auto fill = [&](int st, int kt) {
        const int kbase = kt * 64;
#pragma unroll
        for (int l = 0; l < 4; ++l) {            // A: 128 rows x 8 segs (h & l)
            int idx = tid + l * 256;
            int r = idx >> 3, sg = idx & 7;
            int vr = v0 + r; if (vr >= VV) vr = VV - 1;
            uint32_t so = swz(r * 128 + sg * 16);
            cpa16(sb + LG_SA + st * 32768 + so,
                  (const char*)(g_Wouth + (size_t)vr * K2H + kbase) + sg * 16);
            cpa16(sb + LG_SA + st * 32768 + 16384 + so,
                  (const char*)(g_Woutl + (size_t)vr * K2H + kbase) + sg * 16);
        }
#pragma unroll
        for (int l = 0; l < 2; ++l) {            // B: 64 rows x 8 segs (h & l)
            int idx = tid + l * 256;
            int r = idx >> 3, sg = idx & 7;
            uint32_t so = swz(r * 128 + sg * 16);
            cpa16(sb + LG_SB + st * 16384 + so,
                  (const char*)(g_Xh + (size_t)r * K2H + kbase) + sg * 16);
            cpa16(sb + LG_SB + st * 16384 + 8192 + so,
                  (const char*)(g_Xl + (size_t)r * K2H + kbase) + sg * 16);
        }
    };

    float d[2][4][4];
#pragma unroll
    for (int i = 0; i < 2; ++i)
#pragma unroll
        for (int j = 0; j < 4; ++j)
#pragma unroll
            for (int q = 0; q < 4; ++q) d[i][j][q] = 0.f;

    fill(0, 0); CPA_COMMIT();
    fill(1, 1); CPA_COMMIT();

    for (int kt = 0; kt < 16; ++kt) {
        const int st = kt & 1;
        CPA_WAIT1();
        __syncthreads();
        const uint32_t ahb = sb + LG_SA + st * 32768;
        const uint32_t alb = ahb + 16384;
        const uint32_t bhb = sb + LG_SB + st * 16384;
        const uint32_t blb = bhb + 8192;
#pragma unroll
        for (int ks = 0; ks < 4; ++ks) {
            uint32_t ah[2][4], al[2][4];
#pragma unroll
            for (int i = 0; i < 2; ++i) {
                int row = wm * 32 + i * 16 + (lane & 15);
                uint32_t so = swz(row * 128 + ks * 32 + (lane >> 4) * 16);
                ldm4(ah[i][0], ah[i][1], ah[i][2], ah[i][3], ahb + so);
                ldm4(al[i][0], al[i][1], al[i][2], al[i][3], alb + so);
            }
            uint32_t bh[2][4], bl[2][4];
#pragma unroll
            for (int p = 0; p < 2; ++p) {
                int row = wn * 32 + p * 16 + (lane & 7) + (lane >> 4) * 8;
                uint32_t so = swz(row * 128 + ks * 32 + ((lane >> 3) & 1) * 16);
                ldm4(bh[p][0], bh[p][1], bh[p][2], bh[p][3], bhb + so);
                ldm4(bl[p][0], bl[p][1], bl[p][2], bl[p][3], blb + so);
            }
#pragma unroll
            for (int i = 0; i < 2; ++i)
#pragma unroll
                for (int j = 0; j < 4; ++j) {
                    mma16816(d[i][j], ah[i], &bh[j >> 1][(j & 1) * 2]);
                    mma16816(d[i][j], ah[i], &bl[j >> 1][(j & 1) * 2]);
                    mma16816(d[i][j], al[i], &bh[j >> 1][(j & 1) * 2]);
                }
        }
        __syncthreads();
        if (kt + 2 < 16) fill(st, kt + 2);
        CPA_COMMIT();
    }

    // epilogue: transpose through smem (overlays stage A), bias, coalesced write
    __syncthreads();
    float* sbuf = (float*)smem;   // [64][132]
#pragma unroll
    for (int i = 0; i < 2; ++i)
#pragma unroll
        for (int j = 0; j < 4; ++j)
#pragma unroll
            for (int q = 0; q < 4; ++q) {
                int r = wm * 32 + i * 16 + (lane >> 2) + (q >> 1) * 8;
                int c = wn * 32 + j * 8 + (lane & 3) * 2 + (q & 1);
                sbuf[c * 132 + r] = d[i][j][q];
            }
    __syncthreads();
#pragma unroll
    for (int l = 0; l < 32; ++l) {
        int idx = tid + l * 256;
        int bc = idx >> 7, r = idx & 127;
        int v = v0 + r;
        if (v < VV) out[(size_t)bc * VV + v] = sbuf[bc * 132 + r] + bout[v];
    }
}

// ================= host launcher (halved pipeline, static resources) =================
extern "C" void kernel_launch(void* const* d_in, const int* in_sizes, int n_in,
                              void* d_out, int out_size) {
    const int*   tok  = (const int*)d_in[0];
    const float* hid  = (const float*)d_in[1];
    const float* cell = (const float*)d_in[2];
    const float* enc  = (const float*)d_in[3];
    const float* emb  = (const float*)d_in[4];
    const float* Wenc = (const float*)d_in[5];
    const float* Wdec = (const float*)d_in[6];
    const float* vat  = (const float*)d_in[7];
    const float* Wih  = (const float*)d_in[8];
    const float* Whh  = (const float*)d_in[9];
    const float* bih  = (const float*)d_in[10];
    const float* bhh  = (const float*)d_in[11];
    const float* Wout = (const float*)d_in[12];
    const float* bout = (const float*)d_in[13];
    float* out = (float*)d_out;

    const long long full = (long long)BB * VV + 2LL * BB * HH + (long long)BB * TT;
    bool has_aux = ((long long)out_size >= full);
    float* out_h = has_aux ? out + (size_t)BB * VV : nullptr;
    float* out_c = has_aux ? out + (size_t)BB * VV + BB * HH : nullptr;
    float* out_a = has_aux ? out + (size_t)BB * VV + 2 * BB * HH : nullptr;

    // Create streams/events ONCE (before the pre-capture memory baseline is
    // taken) so graph capture/teardown sees no allocation delta.
    static bool s_init = false;
    static cudaStream_t s2, s3;
    static cudaEvent_t evF, evDec, evE1, evW, evS0, evS1, evC;
    if (!s_init) {
        s_init = true;
        cudaStreamCreateWithFlags(&s2, cudaStreamNonBlocking);
        cudaStreamCreateWithFlags(&s3, cudaStreamNonBlocking);
        cudaEventCreateWithFlags(&evF,   cudaEventDisableTiming);
        cudaEventCreateWithFlags(&evDec, cudaEventDisableTiming);
        cudaEventCreateWithFlags(&evE1,  cudaEventDisableTiming);
        cudaEventCreateWithFlags(&evW,   cudaEventDisableTiming);
        cudaEventCreateWithFlags(&evS0,  cudaEventDisableTiming);
        cudaEventCreateWithFlags(&evS1,  cudaEventDisableTiming);
        cudaEventCreateWithFlags(&evC,   cudaEventDisableTiming);
        cudaFuncSetAttribute(k_scores_mma,
                             cudaFuncAttributeMaxDynamicSharedMemorySize, SC_TOT);
        cudaFuncSetAttribute(k_logits_mma,
                             cudaFuncAttributeMaxDynamicSharedMemorySize, LG_TOT);
    }

    const size_t HE = (size_t)32 * TT * HH / 4;     // float4 elems per 32 batches
    const int HG = (int)(HE / 256);                 // split_enc blocks per half

    // fork
    cudaEventRecord(evF, 0);
    cudaStreamWaitEvent(s2, evF, 0);

    // s2: scores prereqs, enc half 1, then Wout split (hidden under scores)
    k_split_w<<<(HH * HH + 255) / 256, 256, 0, s2>>>(Wenc);
    k_dec<<<dim3(8, BB), 256, 0, s2>>>(hid, Wdec);
    cudaEventRecord(evDec, s2);
    k_split_enc<<<HG, 256, 0, s2>>>(enc, HE);       // half 1
    cudaEventRecord(evE1, s2);
    k_split_wout<<<(int)(((size_t)VV * K2H / 4) / 256), 256, 0, s2>>>(Wout);
    cudaEventRecord(evW, s2);

    // stream 0: enc half 0, scores half 0 (512 CTAs)
    k_split_enc<<<HG, 256>>>(enc, 0);               // half 0
    cudaStreamWaitEvent(0, evDec, 0);
    k_scores_mma<<<32 * 16, 256, SC_TOT>>>(vat, 0);
    cudaEventRecord(evS0, 0);

    // s3: scores half 1 — overlaps half 0's drain (continuous CTA pool)
    cudaStreamWaitEvent(s3, evE1, 0);               // implies dec done (s2 order)
    k_scores_mma<<<32 * 16, 256, SC_TOT, s3>>>(vat, 32);
    cudaEventRecord(evS1, s3);

    // s2: softmax + ctx for half 0, hidden under scores half 1
    cudaStreamWaitEvent(s2, evS0, 0);
    k_softmax<<<32, 256, 0, s2>>>(out_a, 0);
    k_ctx<<<dim3(8, 32), 512, 0, s2>>>(enc, 0);
    cudaEventRecord(evC, s2);

    // stream 0: half 1 softmax/ctx + tail
    cudaStreamWaitEvent(0, evS1, 0);
    k_softmax<<<32, 256>>>(out_a, 32);
    k_ctx<<<dim3(8, 32), 512>>>(enc, 32);
    cudaStreamWaitEvent(0, evC, 0);
    k_ctxred<<<32, 1024>>>();
    k_gates<<<G4H / 64, 256>>>(tok, emb, hid, Wih, Whh, bih, bhh);
    k_lstm<<<32, 1024>>>(cell, out_h, out_c);
    cudaStreamWaitEvent(0, evW, 0);
    k_logits_mma<<<(VV + 127) / 128, 256, LG_TOT>>>(bout, out);
}

// round 14
// speedup vs baseline: 1.6511x; 1.2859x over previous
#include <cuda_runtime.h>
#include <cuda_bf16.h>
#include <cuda_fp16.h>
#include <math.h>
#include <stdint.h>

#define BB 64
#define TT 2048
#define HH 512
#define EE 256
#define VV 50000
#define G4H 2048   /* 4*H  */
#define K2H 1024   /* 2*H  */

// ---------------- scratch (device globals; no allocation) ----------------
__device__ float g_dec[BB * HH];          // h @ W_dec.T          (B,H)
__device__ float g_scores[BB * TT];       // attention scores     (B,T)
__device__ float g_attn[BB * TT];         // softmax(scores)      (B,T)
__device__ float g_ctxp[8 * BB * HH];     // context partials     (8,B,H)
__device__ float g_ctx[BB * HH];          // context              (B,H)
__device__ float g_gates[BB * G4H];       // LSTM gates           (B,4H)
// fp16 operands for the scores GEMM (single product: Ah·Wh^T)
__device__ __half g_Ah[(size_t)BB * TT * HH];  // 128 MB
__device__ __half g_Wh[HH * HH];
// split-bf16 operands for the logits GEMM
__device__ __nv_bfloat16 g_Wouth[(size_t)VV * K2H];   // 102.4 MB
__device__ __nv_bfloat16 g_Woutl[(size_t)VV * K2H];   // 102.4 MB
__device__ __nv_bfloat16 g_Xh[BB * K2H];              // [h_new, ctx] hi
__device__ __nv_bfloat16 g_Xl[BB * K2H];              // [h_new, ctx] lo

// ---------------- packed f32x2 helpers (FFMA2 path, small GEMMs) ----------------
__device__ __forceinline__ unsigned long long pk2(float lo, float hi) {
    unsigned long long r;
    asm("mov.b64 %0, {%1, %2};" : "=l"(r)
        : "r"(__float_as_uint(lo)), "r"(__float_as_uint(hi)));
    return r;
}
__device__ __forceinline__ unsigned long long pkdup(float v) {
    unsigned long long r;
    asm("mov.b64 %0, {%1, %1};" : "=l"(r) : "r"(__float_as_uint(v)));
    return r;
}
__device__ __forceinline__ void fma2(unsigned long long& d,
                                     unsigned long long a,
                                     unsigned long long b) {
    asm("fma.rn.f32x2 %0, %1, %2, %0;" : "+l"(d) : "l"(a), "l"(b));
}
__device__ __forceinline__ float2 upk2(unsigned long long v) {
    unsigned int lo, hi;
    asm("mov.b64 {%0, %1}, %2;" : "=r"(lo), "=r"(hi) : "l"(v));
    return make_float2(__uint_as_float(lo), __uint_as_float(hi));
}
__device__ __forceinline__ float sigf(float x) { return 1.f / (1.f + expf(-x)); }

// ---------------- smem / async / mma helpers (baseline PTX, sm_80+) ----------------
__device__ __forceinline__ uint32_t smem_u32(const void* p) {
    uint32_t a;
    asm("{ .reg .u64 t; cvta.to.shared.u64 t, %1; cvt.u32.u64 %0, t; }"
        : "=r"(a) : "l"(p));
    return a;
}
__device__ __forceinline__ void cpa16(uint32_t dst, const void* src) {
    asm volatile("cp.async.cg.shared.global [%0], [%1], 16;" :: "r"(dst), "l"(src));
}
#define CPA_COMMIT() asm volatile("cp.async.commit_group;" ::: "memory")
#define CPA_WAIT1()  asm volatile("cp.async.wait_group 1;" ::: "memory")
__device__ __forceinline__ uint32_t swz(uint32_t off) { return off ^ ((off >> 3) & 0x70); }

__device__ __forceinline__ void ldm4(uint32_t& r0, uint32_t& r1,
                                     uint32_t& r2, uint32_t& r3, uint32_t addr) {
    asm volatile("ldmatrix.sync.aligned.m8n8.x4.shared.b16 {%0,%1,%2,%3}, [%4];"
        : "=r"(r0), "=r"(r1), "=r"(r2), "=r"(r3) : "r"(addr));
}
__device__ __forceinline__ void mma16816(float* d, const uint32_t* a,
                                         const uint32_t* bf) {
    asm volatile("mma.sync.aligned.m16n8k16.row.col.f32.bf16.bf16.f32 "
        "{%0,%1,%2,%3}, {%4,%5,%6,%7}, {%8,%9}, {%0,%1,%2,%3};"
        : "+f"(d[0]), "+f"(d[1]), "+f"(d[2]), "+f"(d[3])
        : "r"(a[0]), "r"(a[1]), "r"(a[2]), "r"(a[3]), "r"(bf[0]), "r"(bf[1]));
}
__device__ __forceinline__ void mma16816h(float* d, const uint32_t* a,
                                          const uint32_t* bf) {
    asm volatile("mma.sync.aligned.m16n8k16.row.col.f32.f16.f16.f32 "
        "{%0,%1,%2,%3}, {%4,%5,%6,%7}, {%8,%9}, {%0,%1,%2,%3};"
        : "+f"(d[0]), "+f"(d[1]), "+f"(d[2]), "+f"(d[3])
        : "r"(a[0]), "r"(a[1]), "r"(a[2]), "r"(a[3]), "r"(bf[0]), "r"(bf[1]));
}
__device__ __forceinline__ float tanhx(float x) {
    float e2 = __expf(2.f * x);
    return 1.f - __fdividef(2.f, e2 + 1.f);
}

// ================= prep: fp16 rounding =================
__global__ void k_split_w(const float* __restrict__ W) {
    int i = blockIdx.x * 256 + threadIdx.x;
    if (i < HH * HH) g_Wh[i] = __float2half_rn(W[i]);
}
__global__ void k_split_enc(const float* __restrict__ enc, size_t i0) {
    size_t i = i0 + (size_t)blockIdx.x * 256 + threadIdx.x;  // x4 vectorized
    float4 v = ((const float4*)enc)[i];
    __half2 hp0; hp0.x = __float2half_rn(v.x); hp0.y = __float2half_rn(v.y);
    __half2 hp1; hp1.x = __float2half_rn(v.z); hp1.y = __float2half_rn(v.w);
    ((__half2*)g_Ah)[i * 2 + 0] = hp0;
    ((__half2*)g_Ah)[i * 2 + 1] = hp1;
}
__global__ void k_split_wout(const float* __restrict__ W) {
    size_t i = (size_t)blockIdx.x * 256 + threadIdx.x;  // x4 vectorized, exact
    float4 v = ((const float4*)W)[i];
    __nv_bfloat16 h0 = __float2bfloat16(v.x), h1 = __float2bfloat16(v.y);
    __nv_bfloat16 h2 = __float2bfloat16(v.z), h3 = __float2bfloat16(v.w);
    __nv_bfloat162 hp0; hp0.x = h0; hp0.y = h1;
    __nv_bfloat162 hp1; hp1.x = h2; hp1.y = h3;
    ((__nv_bfloat162*)g_Wouth)[i * 2 + 0] = hp0;
    ((__nv_bfloat162*)g_Wouth)[i * 2 + 1] = hp1;
    __nv_bfloat162 lp0, lp1;
    lp0.x = __float2bfloat16(v.x - __bfloat162float(h0));
    lp0.y = __float2bfloat16(v.y - __bfloat162float(h1));
    lp1.x = __float2bfloat16(v.z - __bfloat162float(h2));
    lp1.y = __float2bfloat16(v.w - __bfloat162float(h3));
    ((__nv_bfloat162*)g_Woutl)[i * 2 + 0] = lp0;
    ((__nv_bfloat162*)g_Woutl)[i * 2 + 1] = lp1;
}

// ================= K1: dec = h @ W_dec.T  (one warp per output) =================
__global__ void k_dec(const float* __restrict__ hid,
                      const float* __restrict__ Wdec) {
    __shared__ float hs[HH];
    const int b = blockIdx.y;
    const int tid = threadIdx.x, wid = tid >> 5, lane = tid & 31;
    for (int i = tid; i < HH; i += 256) hs[i] = hid[b * HH + i];
    __syncthreads();
#pragma unroll
    for (int j = 0; j < 8; ++j) {                 // 8 warps x 8 h each
        int h = blockIdx.x * 64 + wid * 8 + j;
        const float4* w = (const float4*)(Wdec + (size_t)h * HH);
        float s = 0.f;
#pragma unroll
        for (int i = 0; i < 4; ++i) {
            int k4 = lane + i * 32;
            float4 wv = w[k4];
            s += wv.x * hs[k4 * 4 + 0] + wv.y * hs[k4 * 4 + 1]
               + wv.z * hs[k4 * 4 + 2] + wv.w * hs[k4 * 4 + 3];
        }
#pragma unroll
        for (int m = 16; m >= 1; m >>= 1)
            s += __shfl_xor_sync(0xffffffffu, s, m);
        if (lane == 0) g_dec[b * HH + h] = s;
    }
}

// ================= K2: scores via mma.sync (HMMA) fp16 single-product =================
// D = Ah·Wh^T  (K=512 in 8 chunks of 64)
#define SC_SA   0                      // A stages: 2 x 16384
#define SC_SB   32768                  // B stages: 2 x 16384
#define SC_DEC  65536                  // dec row  (2048 B)
#define SC_V    67584                  // v_attn   (2048 B)
#define SC_SC   69632                  // score buf 2x128 floats (1024 B)
#define SC_TOT  70656

__global__ void __launch_bounds__(256, 2)
k_scores_mma(const float* __restrict__ vat, int boff) {
    extern __shared__ __align__(1024) char smem[];
    const uint32_t sb = smem_u32(smem);
    float* decs = (float*)(smem + SC_DEC);
    float* vs   = (float*)(smem + SC_V);
    float* sbuf = (float*)(smem + SC_SC);
    const int tid = threadIdx.x, lane = tid & 31, wid = tid >> 5;
    const int wm = wid & 3, wn = wid >> 2;       // warp tile (32 m) x (64 n)
    const int b = (blockIdx.x >> 4) + boff;
    const int t0 = (blockIdx.x & 15) * 128;

    for (int i = tid; i < HH; i += 256) {
        decs[i] = g_dec[b * HH + i];
        vs[i]   = vat[i];
    }
    __syncthreads();

    auto fill = [&](int st, int it, int n0) {
        const int kbase = it * 64;
        const __half* As = g_Ah + ((size_t)(b * TT + t0)) * HH + kbase;
        const __half* Bs = g_Wh + (size_t)n0 * HH + kbase;
#pragma unroll
        for (int l = 0; l < 4; ++l) {            // A: 128 rows x 8 segs
            int idx = tid + l * 256;
            int r = idx >> 3, sg = idx & 7;
            cpa16(sb + SC_SA + st * 16384 + swz(r * 128 + sg * 16),
                  (const char*)(As + (size_t)r * HH) + sg * 16);
        }
#pragma unroll
        for (int l = 0; l < 4; ++l) {            // B: 128 h-cols x 8 segs
            int idx = tid + l * 256;
            int r = idx >> 3, sg = idx & 7;
            cpa16(sb + SC_SB + st * 16384 + swz(r * 128 + sg * 16),
                  (const char*)(Bs + (size_t)r * HH) + sg * 16);
        }
    };

    float rsc[4] = {0.f, 0.f, 0.f, 0.f};         // 4 owned rows (i x h)

    for (int n = 0; n < 4; ++n) {
        const int n0 = n * 128;
        float d[2][8][4];
#pragma unroll
        for (int i = 0; i < 2; ++i)
#pragma unroll
            for (int j = 0; j < 8; ++j)
#pragma unroll
                for (int q = 0; q < 4; ++q) d[i][j][q] = 0.f;

        fill(0, 0, n0); CPA_COMMIT();
        fill(1, 1, n0); CPA_COMMIT();

        for (int it = 0; it < 8; ++it) {
            const int st = it & 1;
            CPA_WAIT1();
            __syncthreads();
            const uint32_t abase = sb + SC_SA + st * 16384;
            const uint32_t bbase = sb + SC_SB + st * 16384;
#pragma unroll
            for (int ks = 0; ks < 4; ++ks) {     // 4 x k16 per 64-chunk
                uint32_t a[2][4];
#pragma unroll
                for (int i = 0; i < 2; ++i) {
                    int row = wm * 32 + i * 16 + (lane & 15);
                    int off = row * 128 + ks * 32 + (lane >> 4) * 16;
                    ldm4(a[i][0], a[i][1], a[i][2], a[i][3], abase + swz(off));
                }
                uint32_t bf[4][4];
#pragma unroll
                for (int p = 0; p < 4; ++p) {    // 2 n8-tiles per ldmatrix.x4
                    int row = wn * 64 + p * 16 + (lane & 7) + (lane >> 4) * 8;
                    int off = row * 128 + ks * 32 + ((lane >> 3) & 1) * 16;
                    ldm4(bf[p][0], bf[p][1], bf[p][2], bf[p][3], bbase + swz(off));
                }
#pragma unroll
                for (int i = 0; i < 2; ++i)
#pragma unroll
                    for (int j = 0; j < 8; ++j)
                        mma16816h(d[i][j], a[i], &bf[j >> 1][(j & 1) * 2]);
            }
            __syncthreads();
            if (it + 2 < 8) fill(st, it + 2, n0);
            CPA_COMMIT();
        }
        // epilogue: tanh(+dec)·v into per-row partials
#pragma unroll
        for (int i = 0; i < 2; ++i)
#pragma unroll
            for (int j = 0; j < 8; ++j) {
                int c = n0 + wn * 64 + j * 8 + (lane & 3) * 2;
                float v0 = vs[c], v1 = vs[c + 1];
                float dc0 = decs[c], dc1 = decs[c + 1];
                rsc[i * 2 + 0] += tanhx(d[i][j][0] + dc0) * v0
                                + tanhx(d[i][j][1] + dc1) * v1;
                rsc[i * 2 + 1] += tanhx(d[i][j][2] + dc0) * v0
                                + tanhx(d[i][j][3] + dc1) * v1;
            }
    }

    // reduce over the 4 lanes of each quad (they share rows, own disjoint cols)
#pragma unroll
    for (int r = 0; r < 4; ++r) {
        rsc[r] += __shfl_xor_sync(0xffffffffu, rsc[r], 1);
        rsc[r] += __shfl_xor_sync(0xffffffffu, rsc[r], 2);
    }
    if ((lane & 3) == 0) {
        int g = lane >> 2;
#pragma unroll
        for (int i = 0; i < 2; ++i)
#pragma unroll
            for (int h = 0; h < 2; ++h)
                sbuf[wn * 128 + wm * 32 + i * 16 + h * 8 + g] = rsc[i * 2 + h];
    }
    __syncthreads();
    if (tid < 128)
        g_scores[b * TT + t0 + tid] = sbuf[tid] + sbuf[128 + tid];
}

// ================= K3: softmax over T per batch =================
__global__ void k_softmax(float* __restrict__ attn_out, int boff) {
    __shared__ float red[256];
    int b = blockIdx.x + boff, tid = threadIdx.x;
    const float* s = g_scores + b * TT;
    float m = -3.4e38f;
    for (int i = tid; i < TT; i += 256) m = fmaxf(m, s[i]);
    red[tid] = m; __syncthreads();
    for (int st = 128; st > 0; st >>= 1) {
        if (tid < st) red[tid] = fmaxf(red[tid], red[tid + st]);
        __syncthreads();
    }
    float M = red[0]; __syncthreads();
    float sum = 0.f;
    for (int i = tid; i < TT; i += 256) {
        float e = expf(s[i] - M);
        g_attn[b * TT + i] = e;
        sum += e;
    }
    red[tid] = sum; __syncthreads();
    for (int st = 128; st > 0; st >>= 1) {
        if (tid < st) red[tid] += red[tid + st];
        __syncthreads();
    }
    float inv = 1.f / red[0];
    for (int i = tid; i < TT; i += 256) {
        float a = g_attn[b * TT + i] * inv;
        g_attn[b * TT + i] = a;
        if (attn_out) attn_out[b * TT + i] = a;
    }
}

// ================= K4: context partials (split-8 over T) =================
__global__ void k_ctx(const float* __restrict__ enc, int boff) {
    __shared__ float as_[256];
    int s = blockIdx.x, b = blockIdx.y + boff;
    int h = threadIdx.x;  // 512 threads
    if (h < 256) as_[h] = g_attn[b * TT + s * 256 + h];
    __syncthreads();
    const float* ep = enc + ((size_t)b * TT + s * 256) * HH + h;
    float a0 = 0.f, a1 = 0.f, a2 = 0.f, a3 = 0.f;
#pragma unroll 4
    for (int t = 0; t < 256; t += 4) {
        a0 += as_[t + 0] * ep[(size_t)(t + 0) * HH];
        a1 += as_[t + 1] * ep[(size_t)(t + 1) * HH];
        a2 += as_[t + 2] * ep[(size_t)(t + 2) * HH];
        a3 += as_[t + 3] * ep[(size_t)(t + 3) * HH];
    }
    g_ctxp[(s * BB + b) * HH + h] = (a0 + a1) + (a2 + a3);
}

__global__ void k_ctxred() {
    int i = blockIdx.x * blockDim.x + threadIdx.x;  // 32768
    float s = 0.f;
#pragma unroll
    for (int p = 0; p < 8; ++p) s += g_ctxp[p * BB * HH + i];
    g_ctx[i] = s;
}

// ================= K5: gates GEMM =================
__global__ void __launch_bounds__(256) k_gates(const int* __restrict__ tok,
                                               const float* __restrict__ emb,
                                               const float* __restrict__ hid,
                                               const float* __restrict__ Wih,
                                               const float* __restrict__ Whh,
                                               const float* __restrict__ bih,
                                               const float* __restrict__ bhh) {
    __shared__ float Ws[32][68];
    __shared__ float Xs[32][68];
    const int tid = threadIdx.x;
    const int g0 = blockIdx.x * 64;
    const int tx = tid & 15, ty = tid >> 4;
    const int r0 = ty * 4, c0 = tx * 4;
    unsigned long long acc[4][2];
#pragma unroll
    for (int i = 0; i < 4; ++i) { acc[i][0] = 0ull; acc[i][1] = 0ull; }

    for (int kt = 0; kt < 40; ++kt) {
        int kbase = kt * 32;
#pragma unroll
        for (int l = 0; l < 2; ++l) {
            int idx = tid + l * 256;
            int row = idx >> 3, kv = (idx & 7) * 4;
            int k = kbase + kv;
            const float* src = (k < 768)
                ? (Wih + (size_t)(g0 + row) * 768 + k)
                : (Whh + (size_t)(g0 + row) * 512 + (k - 768));
            float4 v = *(const float4*)src;
            Ws[kv + 0][row] = v.x; Ws[kv + 1][row] = v.y;
            Ws[kv + 2][row] = v.z; Ws[kv + 3][row] = v.w;
        }
#pragma unroll
        for (int l = 0; l < 2; ++l) {
            int idx = tid + l * 256;
            int bc = idx >> 3, kv = (idx & 7) * 4;
            int k = kbase + kv;
            const float* src;
            if (k < 256)      src = emb + (size_t)tok[bc] * EE + k;
            else if (k < 768) src = g_ctx + bc * HH + (k - 256);
            else              src = hid + bc * HH + (k - 768);
            float4 v = *(const float4*)src;
            Xs[kv + 0][bc] = v.x; Xs[kv + 1][bc] = v.y;
            Xs[kv + 2][bc] = v.z; Xs[kv + 3][bc] = v.w;
        }
        __syncthreads();
#pragma unroll 8
        for (int kk = 0; kk < 32; ++kk) {
            float4 av = *(const float4*)&Ws[kk][r0];
            float4 xv = *(const float4*)&Xs[kk][c0];
            unsigned long long X0 = pk2(xv.x, xv.y);
            unsigned long long X1 = pk2(xv.z, xv.w);
            unsigned long long Ad0 = pkdup(av.x);
            unsigned long long Ad1 = pkdup(av.y);
            unsigned long long Ad2 = pkdup(av.z);
            unsigned long long Ad3 = pkdup(av.w);
            fma2(acc[0][0], Ad0, X0); fma2(acc[0][1], Ad0, X1);
            fma2(acc[1][0], Ad1, X0); fma2(acc[1][1], Ad1, X1);
            fma2(acc[2][0], Ad2, X0); fma2(acc[2][1], Ad2, X1);
            fma2(acc[3][0], Ad3, X0); fma2(acc[3][1], Ad3, X1);
        }
        __syncthreads();
    }
#pragma unroll
    for (int i = 0; i < 4; ++i) {
        int g = g0 + r0 + i;
        float bias = bih[g] + bhh[g];
#pragma unroll
        for (int p = 0; p < 2; ++p) {
            float2 e = upk2(acc[i][p]);
            int bc = c0 + 2 * p;
            g_gates[bc * G4H + g]       = e.x + bias;
            g_gates[(bc + 1) * G4H + g] = e.y + bias;
        }
    }
}

// ================= K6: LSTM pointwise; emit split-bf16 xout =================
__global__ void k_lstm(const float* __restrict__ cell,
                       float* __restrict__ hout, float* __restrict__ cout) {
    int i = blockIdx.x * blockDim.x + threadIdx.x;  // 32768
    int b = i >> 9, h = i & 511;
    float ig = g_gates[b * G4H + h];
    float fg = g_gates[b * G4H + 512 + h];
    float gg = g_gates[b * G4H + 1024 + h];
    float og = g_gates[b * G4H + 1536 + h];
    float c = sigf(fg) * cell[i] + sigf(ig) * tanhf(gg);
    float hn = sigf(og) * tanhf(c);
    if (hout) { hout[i] = hn; cout[i] = c; }
    float cx = g_ctx[i];
    __nv_bfloat16 hh = __float2bfloat16(hn);
    __nv_bfloat16 ch = __float2bfloat16(cx);
    g_Xh[b * K2H + h]        = hh;
    g_Xl[b * K2H + h]        = __float2bfloat16(hn - __bfloat162float(hh));
    g_Xh[b * K2H + 512 + h]  = ch;
    g_Xl[b * K2H + 512 + h]  = __float2bfloat16(cx - __bfloat162float(ch));
}

// ================= K7: logits via mma.sync (HMMA) split-bf16 =================
#define LG_SA   0                      // Wh/Wl stages: 2 x 32768
#define LG_SB   65536                  // Xh/Xl stages: 2 x 16384
#define LG_TOT  98304

__global__ void __launch_bounds__(256, 2)
k_logits_mma(const float* __restrict__ bout, float* __restrict__ out) {
    extern __shared__ __align__(1024) char smem[];
    const uint32_t sb = smem_u32(smem);
    const int tid = threadIdx.x, lane = tid & 31, wid = tid >> 5;
    const int wm = wid & 3, wn = wid >> 2;       // warp tile (32 m) x (32 n)
    const int v0 = blockIdx.x * 128;

    auto fill = [&](int st, int kt) {
        const int kbase = kt * 64;
#pragma unroll
        for (int l = 0; l < 4; ++l) {            // A: 128 rows x 8 segs (h & l)
            int idx = tid + l * 256;
            int r = idx >> 3, sg = idx & 7;
            int vr = v0 + r; if (vr >= VV) vr = VV - 1;
            uint32_t so = swz(r * 128 + sg * 16);
            cpa16(sb + LG_SA + st * 32768 + so,
                  (const char*)(g_Wouth + (size_t)vr * K2H + kbase) + sg * 16);
            cpa16(sb + LG_SA + st * 32768 + 16384 + so,
                  (const char*)(g_Woutl + (size_t)vr * K2H + kbase) + sg * 16);
        }
#pragma unroll
        for (int l = 0; l < 2; ++l) {            // B: 64 rows x 8 segs (h & l)
            int idx = tid + l * 256;
            int r = idx >> 3, sg = idx & 7;
            uint32_t so = swz(r * 128 + sg * 16);
            cpa16(sb + LG_SB + st * 16384 + so,
                  (const char*)(g_Xh + (size_t)r * K2H + kbase) + sg * 16);
            cpa16(sb + LG_SB + st * 16384 + 8192 + so,
                  (const char*)(g_Xl + (size_t)r * K2H + kbase) + sg * 16);
        }
    };

    float d[2][4][4];
#pragma unroll
    for (int i = 0; i < 2; ++i)
#pragma unroll
        for (int j = 0; j < 4; ++j)
#pragma unroll
            for (int q = 0; q < 4; ++q) d[i][j][q] = 0.f;

    fill(0, 0); CPA_COMMIT();
    fill(1, 1); CPA_COMMIT();

    for (int kt = 0; kt < 16; ++kt) {
        const int st = kt & 1;
        CPA_WAIT1();
        __syncthreads();
        const uint32_t ahb = sb + LG_SA + st * 32768;
        const uint32_t alb = ahb + 16384;
        const uint32_t bhb = sb + LG_SB + st * 16384;
        const uint32_t blb = bhb + 8192;
#pragma unroll
        for (int ks = 0; ks < 4; ++ks) {
            uint32_t ah[2][4], al[2][4];
#pragma unroll
            for (int i = 0; i < 2; ++i) {
                int row = wm * 32 + i * 16 + (lane & 15);
                uint32_t so = swz(row * 128 + ks * 32 + (lane >> 4) * 16);
                ldm4(ah[i][0], ah[i][1], ah[i][2], ah[i][3], ahb + so);
                ldm4(al[i][0], al[i][1], al[i][2], al[i][3], alb + so);
            }
            uint32_t bh[2][4], bl[2][4];
#pragma unroll
            for (int p = 0; p < 2; ++p) {
                int row = wn * 32 + p * 16 + (lane & 7) + (lane >> 4) * 8;
                uint32_t so = swz(row * 128 + ks * 32 + ((lane >> 3) & 1) * 16);
                ldm4(bh[p][0], bh[p][1], bh[p][2], bh[p][3], bhb + so);
                ldm4(bl[p][0], bl[p][1], bl[p][2], bl[p][3], blb + so);
            }
#pragma unroll
            for (int i = 0; i < 2; ++i)
#pragma unroll
                for (int j = 0; j < 4; ++j) {
                    mma16816(d[i][j], ah[i], &bh[j >> 1][(j & 1) * 2]);
                    mma16816(d[i][j], ah[i], &bl[j >> 1][(j & 1) * 2]);
                    mma16816(d[i][j], al[i], &bh[j >> 1][(j & 1) * 2]);
                }
        }
        __syncthreads();
        if (kt + 2 < 16) fill(st, kt + 2);
        CPA_COMMIT();
    }

    // epilogue: transpose through smem (overlays stage A), bias, coalesced write
    __syncthreads();
    float* sbuf = (float*)smem;   // [64][132]
#pragma unroll
    for (int i = 0; i < 2; ++i)
#pragma unroll
        for (int j = 0; j < 4; ++j)
#pragma unroll
            for (int q = 0; q < 4; ++q) {
                int r = wm * 32 + i * 16 + (lane >> 2) + (q >> 1) * 8;
                int c = wn * 32 + j * 8 + (lane & 3) * 2 + (q & 1);
                sbuf[c * 132 + r] = d[i][j][q];
            }
    __syncthreads();
#pragma unroll
    for (int l = 0; l < 32; ++l) {
        int idx = tid + l * 256;
        int bc = idx >> 7, r = idx & 127;
        int v = v0 + r;
        if (v < VV) out[(size_t)bc * VV + v] = sbuf[bc * 132 + r] + bout[v];
    }
}

// ================= host launcher (halved pipeline, static resources) =================
extern "C" void kernel_launch(void* const* d_in, const int* in_sizes, int n_in,
                              void* d_out, int out_size) {
    const int*   tok  = (const int*)d_in[0];
    const float* hid  = (const float*)d_in[1];
    const float* cell = (const float*)d_in[2];
    const float* enc  = (const float*)d_in[3];
    const float* emb  = (const float*)d_in[4];
    const float* Wenc = (const float*)d_in[5];
    const float* Wdec = (const float*)d_in[6];
    const float* vat  = (const float*)d_in[7];
    const float* Wih  = (const float*)d_in[8];
    const float* Whh  = (const float*)d_in[9];
    const float* bih  = (const float*)d_in[10];
    const float* bhh  = (const float*)d_in[11];
    const float* Wout = (const float*)d_in[12];
    const float* bout = (const float*)d_in[13];
    float* out = (float*)d_out;

    const long long full = (long long)BB * VV + 2LL * BB * HH + (long long)BB * TT;
    bool has_aux = ((long long)out_size >= full);
    float* out_h = has_aux ? out + (size_t)BB * VV : nullptr;
    float* out_c = has_aux ? out + (size_t)BB * VV + BB * HH : nullptr;
    float* out_a = has_aux ? out + (size_t)BB * VV + 2 * BB * HH : nullptr;

    // Create streams/events ONCE (before the pre-capture memory baseline is
    // taken) so graph capture/teardown sees no allocation delta.
    static bool s_init = false;
    static cudaStream_t s2, s3;
    static cudaEvent_t evF, evDec, evE1, evW, evS0, evS1, evC;
    if (!s_init) {
        s_init = true;
        cudaStreamCreateWithFlags(&s2, cudaStreamNonBlocking);
        cudaStreamCreateWithFlags(&s3, cudaStreamNonBlocking);
        cudaEventCreateWithFlags(&evF,   cudaEventDisableTiming);
        cudaEventCreateWithFlags(&evDec, cudaEventDisableTiming);
        cudaEventCreateWithFlags(&evE1,  cudaEventDisableTiming);
        cudaEventCreateWithFlags(&evW,   cudaEventDisableTiming);
        cudaEventCreateWithFlags(&evS0,  cudaEventDisableTiming);
        cudaEventCreateWithFlags(&evS1,  cudaEventDisableTiming);
        cudaEventCreateWithFlags(&evC,   cudaEventDisableTiming);
        cudaFuncSetAttribute(k_scores_mma,
                             cudaFuncAttributeMaxDynamicSharedMemorySize, SC_TOT);
        cudaFuncSetAttribute(k_logits_mma,
                             cudaFuncAttributeMaxDynamicSharedMemorySize, LG_TOT);
    }

    const size_t HE = (size_t)32 * TT * HH / 4;     // float4 elems per 32 batches
    const int HG = (int)(HE / 256);                 // split_enc blocks per half

    // fork
    cudaEventRecord(evF, 0);
    cudaStreamWaitEvent(s2, evF, 0);

    // s2: scores prereqs, enc half 1, then Wout split (hidden under scores)
    k_split_w<<<(HH * HH + 255) / 256, 256, 0, s2>>>(Wenc);
    k_dec<<<dim3(8, BB), 256, 0, s2>>>(hid, Wdec);
    cudaEventRecord(evDec, s2);
    k_split_enc<<<HG, 256, 0, s2>>>(enc, HE);       // half 1
    cudaEventRecord(evE1, s2);
    k_split_wout<<<(int)(((size_t)VV * K2H / 4) / 256), 256, 0, s2>>>(Wout);
    cudaEventRecord(evW, s2);

    // stream 0: enc half 0, scores half 0 (512 CTAs)
    k_split_enc<<<HG, 256>>>(enc, 0);               // half 0
    cudaStreamWaitEvent(0, evDec, 0);
    k_scores_mma<<<32 * 16, 256, SC_TOT>>>(vat, 0);
    cudaEventRecord(evS0, 0);

    // s3: scores half 1 — overlaps half 0's drain (continuous CTA pool)
    cudaStreamWaitEvent(s3, evE1, 0);               // implies dec done (s2 order)
    k_scores_mma<<<32 * 16, 256, SC_TOT, s3>>>(vat, 32);
    cudaEventRecord(evS1, s3);

    // s2: softmax + ctx for half 0, hidden under scores half 1
    cudaStreamWaitEvent(s2, evS0, 0);
    k_softmax<<<32, 256, 0, s2>>>(out_a, 0);
    k_ctx<<<dim3(8, 32), 512, 0, s2>>>(enc, 0);
    cudaEventRecord(evC, s2);

    // stream 0: half 1 softmax/ctx + tail
    cudaStreamWaitEvent(0, evS1, 0);
    k_softmax<<<32, 256>>>(out_a, 32);
    k_ctx<<<dim3(8, 32), 512>>>(enc, 32);
    cudaStreamWaitEvent(0, evC, 0);
    k_ctxred<<<32, 1024>>>();
    k_gates<<<G4H / 64, 256>>>(tok, emb, hid, Wih, Whh, bih, bhh);
    k_lstm<<<32, 1024>>>(cell, out_h, out_c);
    cudaStreamWaitEvent(0, evW, 0);
    k_logits_mma<<<(VV + 127) / 128, 256, LG_TOT>>>(bout, out);
}

// round 16
// speedup vs baseline: 1.7792x; 1.0776x over previous
#include <cuda_runtime.h>
#include <cuda_bf16.h>
#include <cuda_fp16.h>
#include <math.h>
#include <stdint.h>

#define BB 64
#define TT 2048
#define HH 512
#define EE 256
#define VV 50000
#define G4H 2048   /* 4*H  */
#define K2H 1024   /* 2*H  */

// ---------------- scratch (device globals; no allocation) ----------------
__device__ float g_dec[BB * HH];          // h @ W_dec.T          (B,H)
__device__ float g_scores[BB * TT];       // attention scores     (B,T)
__device__ float g_attn[BB * TT];         // softmax(scores)      (B,T)
__device__ float g_ctxp[8 * BB * HH];     // context partials     (8,B,H)
__device__ float g_ctx[BB * HH];          // context              (B,H)
__device__ float g_gates[BB * G4H];       // LSTM gates           (B,4H)
// fp16 weight for the scores GEMM (enc converted in-kernel)
__device__ __half g_Wh[HH * HH];
// fp16 operands for the logits GEMM (W single, X hi/lo split)
__device__ __half g_Wo16[(size_t)VV * K2H];           // 102.4 MB
__device__ __half g_Xh16[BB * K2H];                   // [h_new, ctx] hi
__device__ __half g_Xl16[BB * K2H];                   // [h_new, ctx] lo

// ---------------- packed f32x2 helpers (FFMA2 path, small GEMMs) ----------------
__device__ __forceinline__ unsigned long long pk2(float lo, float hi) {
    unsigned long long r;
    asm("mov.b64 %0, {%1, %2};" : "=l"(r)
        : "r"(__float_as_uint(lo)), "r"(__float_as_uint(hi)));
    return r;
}
__device__ __forceinline__ unsigned long long pkdup(float v) {
    unsigned long long r;
    asm("mov.b64 %0, {%1, %1};" : "=l"(r) : "r"(__float_as_uint(v)));
    return r;
}
__device__ __forceinline__ void fma2(unsigned long long& d,
                                     unsigned long long a,
                                     unsigned long long b) {
    asm("fma.rn.f32x2 %0, %1, %2, %0;" : "+l"(d) : "l"(a), "l"(b));
}
__device__ __forceinline__ float2 upk2(unsigned long long v) {
    unsigned int lo, hi;
    asm("mov.b64 {%0, %1}, %2;" : "=r"(lo), "=r"(hi) : "l"(v));
    return make_float2(__uint_as_float(lo), __uint_as_float(hi));
}
__device__ __forceinline__ float sigf(float x) { return 1.f / (1.f + expf(-x)); }

// ---------------- smem / async / mma helpers (baseline PTX, sm_80+) ----------------
__device__ __forceinline__ uint32_t smem_u32(const void* p) {
    uint32_t a;
    asm("{ .reg .u64 t; cvta.to.shared.u64 t, %1; cvt.u32.u64 %0, t; }"
        : "=r"(a) : "l"(p));
    return a;
}
__device__ __forceinline__ void cpa16(uint32_t dst, const void* src) {
    asm volatile("cp.async.cg.shared.global [%0], [%1], 16;" :: "r"(dst), "l"(src));
}
#define CPA_COMMIT() asm volatile("cp.async.commit_group;" ::: "memory")
#define CPA_WAIT1()  asm volatile("cp.async.wait_group 1;" ::: "memory")
__device__ __forceinline__ uint32_t swz(uint32_t off) { return off ^ ((off >> 3) & 0x70); }

__device__ __forceinline__ void ldm4(uint32_t& r0, uint32_t& r1,
                                     uint32_t& r2, uint32_t& r3, uint32_t addr) {
    asm volatile("ldmatrix.sync.aligned.m8n8.x4.shared.b16 {%0,%1,%2,%3}, [%4];"
        : "=r"(r0), "=r"(r1), "=r"(r2), "=r"(r3) : "r"(addr));
}
__device__ __forceinline__ void mma16816h(float* d, const uint32_t* a,
                                          const uint32_t* bf) {
    asm volatile("mma.sync.aligned.m16n8k16.row.col.f32.f16.f16.f32 "
        "{%0,%1,%2,%3}, {%4,%5,%6,%7}, {%8,%9}, {%0,%1,%2,%3};"
        : "+f"(d[0]), "+f"(d[1]), "+f"(d[2]), "+f"(d[3])
        : "r"(a[0]), "r"(a[1]), "r"(a[2]), "r"(a[3]), "r"(bf[0]), "r"(bf[1]));
}
__device__ __forceinline__ float tanhx(float x) {
    float e2 = __expf(2.f * x);
    return 1.f - __fdividef(2.f, e2 + 1.f);
}

// ================= prep: fp16 rounding =================
__global__ void k_split_w(const float* __restrict__ W) {
    int i = blockIdx.x * 256 + threadIdx.x;
    if (i < HH * HH) g_Wh[i] = __float2half_rn(W[i]);
}
__global__ void k_split_wout(const float* __restrict__ W) {
    size_t i = (size_t)blockIdx.x * 256 + threadIdx.x;  // x4 vectorized, exact
    float4 v = ((const float4*)W)[i];
    __half2 p0 = __floats2half2_rn(v.x, v.y);
    __half2 p1 = __floats2half2_rn(v.z, v.w);
    ((__half2*)g_Wo16)[i * 2 + 0] = p0;
    ((__half2*)g_Wo16)[i * 2 + 1] = p1;
}

// ================= K1: dec = h @ W_dec.T  (one warp per output) =================
__global__ void k_dec(const float* __restrict__ hid,
                      const float* __restrict__ Wdec) {
    __shared__ float hs[HH];
    const int b = blockIdx.y;
    const int tid = threadIdx.x, wid = tid >> 5, lane = tid & 31;
    for (int i = tid; i < HH; i += 256) hs[i] = hid[b * HH + i];
    __syncthreads();
#pragma unroll
    for (int j = 0; j < 8; ++j) {                 // 8 warps x 8 h each
        int h = blockIdx.x * 64 + wid * 8 + j;
        const float4* w = (const float4*)(Wdec + (size_t)h * HH);
        float s = 0.f;
#pragma unroll
        for (int i = 0; i < 4; ++i) {
            int k4 = lane + i * 32;
            float4 wv = w[k4];
            s += wv.x * hs[k4 * 4 + 0] + wv.y * hs[k4 * 4 + 1]
               + wv.z * hs[k4 * 4 + 2] + wv.w * hs[k4 * 4 + 3];
        }
#pragma unroll
        for (int m = 16; m >= 1; m >>= 1)
            s += __shfl_xor_sync(0xffffffffu, s, m);
        if (lane == 0) g_dec[b * HH + h] = s;
    }
}

// ================= K2: scores — fused fp32->fp16 convert + HMMA =================
// A (128 t-rows x 512) converted from enc fp32 into persistent smem (8 swizzled
// 16KB chunks); B (Wh) double-buffered; D = A·Wh^T per 128-col n-chunk.
#define SC_SA   0                      // persistent A: 8 x 16384 = 131072
#define SC_SB   131072                 // B stages: 2 x 16384
#define SC_DEC  163840                 // dec row  (2048 B)
#define SC_V    165888                 // v_attn   (2048 B)
#define SC_SC   167936                 // score buf 4x128 floats (2048 B)
#define SC_TOT  169984

__global__ void __launch_bounds__(512, 1)
k_scores_mma(const float* __restrict__ enc, const float* __restrict__ vat,
             int boff) {
    extern __shared__ __align__(1024) char smem[];
    const uint32_t sb = smem_u32(smem);
    float* decs = (float*)(smem + SC_DEC);
    float* vs   = (float*)(smem + SC_V);
    float* sbuf = (float*)(smem + SC_SC);
    const int tid = threadIdx.x, lane = tid & 31, wid = tid >> 5;
    const int wm = wid & 3, wn = wid >> 2;       // warp tile 32m x 32n (4x4)
    const int b = (blockIdx.x >> 4) + boff;
    const int t0 = (blockIdx.x & 15) * 128;

    for (int i = tid; i < HH; i += 512) {
        decs[i] = g_dec[b * HH + i];
        vs[i]   = vat[i];
    }

    // convert A: enc fp32 (128 x 512) -> persistent swizzled fp16 smem
    {
        const float4* ep = (const float4*)(enc + ((size_t)(b * TT + t0)) * HH);
        // per row: 128 float4; global f4 index = r*128 + ch*16 + c0
#pragma unroll 8
        for (int idx = tid; idx < 16384; idx += 512) {
            int ch = idx >> 11, rem = idx & 2047;
            int r = rem >> 4, c0 = rem & 15;
            float4 v = ep[r * 128 + ch * 16 + c0];
            __half2 p0 = __floats2half2_rn(v.x, v.y);
            __half2 p1 = __floats2half2_rn(v.z, v.w);
            uint2 u;
            u.x = *(uint32_t*)&p0;
            u.y = *(uint32_t*)&p1;
            *(uint2*)(smem + SC_SA + ch * 16384 + swz(r * 128 + c0 * 8)) = u;
        }
    }
    __syncthreads();

    auto fillB = [&](int st, int it, int n0) {
        const __half* Bs = g_Wh + (size_t)n0 * HH + it * 64;
#pragma unroll
        for (int l = 0; l < 2; ++l) {            // B: 128 h-cols x 8 segs
            int idx = tid + l * 512;
            int r = idx >> 3, sg = idx & 7;
            cpa16(sb + SC_SB + st * 16384 + swz(r * 128 + sg * 16),
                  (const char*)(Bs + (size_t)r * HH) + sg * 16);
        }
    };

    float rsc[4] = {0.f, 0.f, 0.f, 0.f};         // 4 owned rows

    for (int n = 0; n < 4; ++n) {
        const int n0 = n * 128;
        float d[2][4][4];
#pragma unroll
        for (int i = 0; i < 2; ++i)
#pragma unroll
            for (int j = 0; j < 4; ++j)
#pragma unroll
                for (int q = 0; q < 4; ++q) d[i][j][q] = 0.f;

        fillB(0, 0, n0); CPA_COMMIT();
        fillB(1, 1, n0); CPA_COMMIT();

        for (int it = 0; it < 8; ++it) {
            const int st = it & 1;
            CPA_WAIT1();
            __syncthreads();
            const uint32_t abase = sb + SC_SA + it * 16384;   // persistent A chunk
            const uint32_t bbase = sb + SC_SB + st * 16384;
#pragma unroll
            for (int ks = 0; ks < 4; ++ks) {     // 4 x k16 per 64-chunk
                uint32_t a[2][4];
#pragma unroll
                for (int i = 0; i < 2; ++i) {
                    int row = wm * 32 + i * 16 + (lane & 15);
                    int off = row * 128 + ks * 32 + (lane >> 4) * 16;
                    ldm4(a[i][0], a[i][1], a[i][2], a[i][3], abase + swz(off));
                }
                uint32_t bf[2][4];
#pragma unroll
                for (int p = 0; p < 2; ++p) {
                    int row = wn * 32 + p * 16 + (lane & 7) + (lane >> 4) * 8;
                    int off = row * 128 + ks * 32 + ((lane >> 3) & 1) * 16;
                    ldm4(bf[p][0], bf[p][1], bf[p][2], bf[p][3], bbase + swz(off));
                }
#pragma unroll
                for (int i = 0; i < 2; ++i)
#pragma unroll
                    for (int j = 0; j < 4; ++j)
                        mma16816h(d[i][j], a[i], &bf[j >> 1][(j & 1) * 2]);
            }
            __syncthreads();
            if (it + 2 < 8) fillB(st, it + 2, n0);
            CPA_COMMIT();
        }
        // epilogue: tanh(+dec)·v into per-row partials
#pragma unroll
        for (int i = 0; i < 2; ++i)
#pragma unroll
            for (int j = 0; j < 4; ++j) {
                int c = n0 + wn * 32 + j * 8 + (lane & 3) * 2;
                float v0 = vs[c], v1 = vs[c + 1];
                float dc0 = decs[c], dc1 = decs[c + 1];
                rsc[i * 2 + 0] += tanhx(d[i][j][0] + dc0) * v0
                                + tanhx(d[i][j][1] + dc1) * v1;
                rsc[i * 2 + 1] += tanhx(d[i][j][2] + dc0) * v0
                                + tanhx(d[i][j][3] + dc1) * v1;
            }
    }

    // quad reduce (lanes share rows, own disjoint cols)
#pragma unroll
    for (int r = 0; r < 4; ++r) {
        rsc[r] += __shfl_xor_sync(0xffffffffu, rsc[r], 1);
        rsc[r] += __shfl_xor_sync(0xffffffffu, rsc[r], 2);
    }
    if ((lane & 3) == 0) {
        int g = lane >> 2;
#pragma unroll
        for (int i = 0; i < 2; ++i)
#pragma unroll
            for (int h = 0; h < 2; ++h)
                sbuf[wn * 128 + wm * 32 + i * 16 + h * 8 + g] = rsc[i * 2 + h];
    }
    __syncthreads();
    if (tid < 128)
        g_scores[b * TT + t0 + tid] =
            (sbuf[tid] + sbuf[128 + tid]) + (sbuf[256 + tid] + sbuf[384 + tid]);
}

// ================= K3: softmax over T per batch =================
__global__ void k_softmax(float* __restrict__ attn_out, int boff) {
    __shared__ float red[256];
    int b = blockIdx.x + boff, tid = threadIdx.x;
    const float* s = g_scores + b * TT;
    float m = -3.4e38f;
    for (int i = tid; i < TT; i += 256) m = fmaxf(m, s[i]);
    red[tid] = m; __syncthreads();
    for (int st = 128; st > 0; st >>= 1) {
        if (tid < st) red[tid] = fmaxf(red[tid], red[tid + st]);
        __syncthreads();
    }
    float M = red[0]; __syncthreads();
    float sum = 0.f;
    for (int i = tid; i < TT; i += 256) {
        float e = expf(s[i] - M);
        g_attn[b * TT + i] = e;
        sum += e;
    }
    red[tid] = sum; __syncthreads();
    for (int st = 128; st > 0; st >>= 1) {
        if (tid < st) red[tid] += red[tid + st];
        __syncthreads();
    }
    float inv = 1.f / red[0];
    for (int i = tid; i < TT; i += 256) {
        float a = g_attn[b * TT + i] * inv;
        g_attn[b * TT + i] = a;
        if (attn_out) attn_out[b * TT + i] = a;
    }
}

// ================= K4: context partials (split-8 over T) =================
__global__ void k_ctx(const float* __restrict__ enc, int boff) {
    __shared__ float as_[256];
    int s = blockIdx.x, b = blockIdx.y + boff;
    int h = threadIdx.x;  // 512 threads
    if (h < 256) as_[h] = g_attn[b * TT + s * 256 + h];
    __syncthreads();
    const float* ep = enc + ((size_t)b * TT + s * 256) * HH + h;
    float a0 = 0.f, a1 = 0.f, a2 = 0.f, a3 = 0.f;
#pragma unroll 4
    for (int t = 0; t < 256; t += 4) {
        a0 += as_[t + 0] * ep[(size_t)(t + 0) * HH];
        a1 += as_[t + 1] * ep[(size_t)(t + 1) * HH];
        a2 += as_[t + 2] * ep[(size_t)(t + 2) * HH];
        a3 += as_[t + 3] * ep[(size_t)(t + 3) * HH];
    }
    g_ctxp[(s * BB + b) * HH + h] = (a0 + a1) + (a2 + a3);
}

__global__ void k_ctxred() {
    int i = blockIdx.x * blockDim.x + threadIdx.x;  // 32768
    float s = 0.f;
#pragma unroll
    for (int p = 0; p < 8; ++p) s += g_ctxp[p * BB * HH + i];
    g_ctx[i] = s;
}

// ================= K5: gates GEMM =================
__global__ void __launch_bounds__(256) k_gates(const int* __restrict__ tok,
                                               const float* __restrict__ emb,
                                               const float* __restrict__ hid,
                                               const float* __restrict__ Wih,
                                               const float* __restrict__ Whh,
                                               const float* __restrict__ bih,
                                               const float* __restrict__ bhh) {
    __shared__ float Ws[32][68];
    __shared__ float Xs[32][68];
    const int tid = threadIdx.x;
    const int g0 = blockIdx.x * 64;
    const int tx = tid & 15, ty = tid >> 4;
    const int r0 = ty * 4, c0 = tx * 4;
    unsigned long long acc[4][2];
#pragma unroll
    for (int i = 0; i < 4; ++i) { acc[i][0] = 0ull; acc[i][1] = 0ull; }

    for (int kt = 0; kt < 40; ++kt) {
        int kbase = kt * 32;
#pragma unroll
        for (int l = 0; l < 2; ++l) {
            int idx = tid + l * 256;
            int row = idx >> 3, kv = (idx & 7) * 4;
            int k = kbase + kv;
            const float* src = (k < 768)
                ? (Wih + (size_t)(g0 + row) * 768 + k)
                : (Whh + (size_t)(g0 + row) * 512 + (k - 768));
            float4 v = *(const float4*)src;
            Ws[kv + 0][row] = v.x; Ws[kv + 1][row] = v.y;
            Ws[kv + 2][row] = v.z; Ws[kv + 3][row] = v.w;
        }
#pragma unroll
        for (int l = 0; l < 2; ++l) {
            int idx = tid + l * 256;
            int bc = idx >> 3, kv = (idx & 7) * 4;
            int k = kbase + kv;
            const float* src;
            if (k < 256)      src = emb + (size_t)tok[bc] * EE + k;
            else if (k < 768) src = g_ctx + bc * HH + (k - 256);
            else              src = hid + bc * HH + (k - 768);
            float4 v = *(const float4*)src;
            Xs[kv + 0][bc] = v.x; Xs[kv + 1][bc] = v.y;
            Xs[kv + 2][bc] = v.z; Xs[kv + 3][bc] = v.w;
        }
        __syncthreads();
#pragma unroll 8
        for (int kk = 0; kk < 32; ++kk) {
            float4 av = *(const float4*)&Ws[kk][r0];
            float4 xv = *(const float4*)&Xs[kk][c0];
            unsigned long long X0 = pk2(xv.x, xv.y);
            unsigned long long X1 = pk2(xv.z, xv.w);
            unsigned long long Ad0 = pkdup(av.x);
            unsigned long long Ad1 = pkdup(av.y);
            unsigned long long Ad2 = pkdup(av.z);
            unsigned long long Ad3 = pkdup(av.w);
            fma2(acc[0][0], Ad0, X0); fma2(acc[0][1], Ad0, X1);
            fma2(acc[1][0], Ad1, X0); fma2(acc[1][1], Ad1, X1);
            fma2(acc[2][0], Ad2, X0); fma2(acc[2][1], Ad2, X1);
            fma2(acc[3][0], Ad3, X0); fma2(acc[3][1], Ad3, X1);
        }
        __syncthreads();
    }
#pragma unroll
    for (int i = 0; i < 4; ++i) {
        int g = g0 + r0 + i;
        float bias = bih[g] + bhh[g];
#pragma unroll
        for (int p = 0; p < 2; ++p) {
            float2 e = upk2(acc[i][p]);
            int bc = c0 + 2 * p;
            g_gates[bc * G4H + g]       = e.x + bias;
            g_gates[(bc + 1) * G4H + g] = e.y + bias;
        }
    }
}

// ================= K6: LSTM pointwise; emit split-fp16 xout =================
__global__ void k_lstm(const float* __restrict__ cell,
                       float* __restrict__ hout, float* __restrict__ cout) {
    int i = blockIdx.x * blockDim.x + threadIdx.x;  // 32768
    int b = i >> 9, h = i & 511;
    float ig = g_gates[b * G4H + h];
    float fg = g_gates[b * G4H + 512 + h];
    float gg = g_gates[b * G4H + 1024 + h];
    float og = g_gates[b * G4H + 1536 + h];
    float c = sigf(fg) * cell[i] + sigf(ig) * tanhf(gg);
    float hn = sigf(og) * tanhf(c);
    if (hout) { hout[i] = hn; cout[i] = c; }
    float cx = g_ctx[i];
    __half hh = __float2half_rn(hn);
    __half ch = __float2half_rn(cx);
    g_Xh16[b * K2H + h]       = hh;
    g_Xl16[b * K2H + h]       = __float2half_rn(hn - __half2float(hh));
    g_Xh16[b * K2H + 512 + h] = ch;
    g_Xl16[b * K2H + 512 + h] = __float2half_rn(cx - __half2float(ch));
}

// ================= K7: logits via HMMA fp16 (W single, X hi/lo) =================
#define LG_SA   0                      // Wo stages: 2 x 16384
#define LG_SB   32768                  // Xh/Xl stages: 2 x 16384
#define LG_TOT  65536

__global__ void __launch_bounds__(256, 2)
k_logits_mma(const float* __restrict__ bout, float* __restrict__ out) {
    extern __shared__ __align__(1024) char smem[];
    const uint32_t sb = smem_u32(smem);
    const int tid = threadIdx.x, lane = tid & 31, wid = tid >> 5;
    const int wm = wid & 3, wn = wid >> 2;       // warp tile (32 m) x (32 n)
    const int v0 = blockIdx.x * 128;

    auto fill = [&](int st, int kt) {
        const int kbase = kt * 64;
#pragma unroll
        for (int l = 0; l < 4; ++l) {            // A: 128 rows x 8 segs
            int idx = tid + l * 256;
            int r = idx >> 3, sg = idx & 7;
            int vr = v0 + r; if (vr >= VV) vr = VV - 1;
            cpa16(sb + LG_SA + st * 16384 + swz(r * 128 + sg * 16),
                  (const char*)(g_Wo16 + (size_t)vr * K2H + kbase) + sg * 16);
        }
#pragma unroll
        for (int l = 0; l < 2; ++l) {            // B: 64 rows x 8 segs (h & l)
            int idx = tid + l * 256;
            int r = idx >> 3, sg = idx & 7;
            uint32_t so = swz(r * 128 + sg * 16);
            cpa16(sb + LG_SB + st * 16384 + so,
                  (const char*)(g_Xh16 + (size_t)r * K2H + kbase) + sg * 16);
            cpa16(sb + LG_SB + st * 16384 + 8192 + so,
                  (const char*)(g_Xl16 + (size_t)r * K2H + kbase) + sg * 16);
        }
    };

    float d[2][4][4];
#pragma unroll
    for (int i = 0; i < 2; ++i)
#pragma unroll
        for (int j = 0; j < 4; ++j)
#pragma unroll
            for (int q = 0; q < 4; ++q) d[i][j][q] = 0.f;

    fill(0, 0); CPA_COMMIT();
    fill(1, 1); CPA_COMMIT();

    for (int kt = 0; kt < 16; ++kt) {
        const int st = kt & 1;
        CPA_WAIT1();
        __syncthreads();
        const uint32_t ab  = sb + LG_SA + st * 16384;
        const uint32_t bhb = sb + LG_SB + st * 16384;
        const uint32_t blb = bhb + 8192;
#pragma unroll
        for (int ks = 0; ks < 4; ++ks) {
            uint32_t a[2][4];
#pragma unroll
            for (int i = 0; i < 2; ++i) {
                int row = wm * 32 + i * 16 + (lane & 15);
                uint32_t so = swz(row * 128 + ks * 32 + (lane >> 4) * 16);
                ldm4(a[i][0], a[i][1], a[i][2], a[i][3], ab + so);
            }
            uint32_t bh[2][4], bl[2][4];
#pragma unroll
            for (int p = 0; p < 2; ++p) {
                int row = wn * 32 + p * 16 + (lane & 7) + (lane >> 4) * 8;
                uint32_t so = swz(row * 128 + ks * 32 + ((lane >> 3) & 1) * 16);
                ldm4(bh[p][0], bh[p][1], bh[p][2], bh[p][3], bhb + so);
                ldm4(bl[p][0], bl[p][1], bl[p][2], bl[p][3], blb + so);
            }
#pragma unroll
            for (int i = 0; i < 2; ++i)
#pragma unroll
                for (int j = 0; j < 4; ++j) {
                    mma16816h(d[i][j], a[i], &bh[j >> 1][(j & 1) * 2]);
                    mma16816h(d[i][j], a[i], &bl[j >> 1][(j & 1) * 2]);
                }
        }
        __syncthreads();
        if (kt + 2 < 16) fill(st, kt + 2);
        CPA_COMMIT();
    }

    // epilogue: transpose through smem (overlays stages), bias, coalesced write
    __syncthreads();
    float* sbuf = (float*)smem;   // [64][132]
#pragma unroll
    for (int i = 0; i < 2; ++i)
#pragma unroll
        for (int j = 0; j < 4; ++j)
#pragma unroll
            for (int q = 0; q < 4; ++q) {
                int r = wm * 32 + i * 16 + (lane >> 2) + (q >> 1) * 8;
                int c = wn * 32 + j * 8 + (lane & 3) * 2 + (q & 1);
                sbuf[c * 132 + r] = d[i][j][q];
            }
    __syncthreads();
#pragma unroll
    for (int l = 0; l < 32; ++l) {
        int idx = tid + l * 256;
        int bc = idx >> 7, r = idx & 127;
        int v = v0 + r;
        if (v < VV) out[(size_t)bc * VV + v] = sbuf[bc * 132 + r] + bout[v];
    }
}

// ================= host launcher (fused-convert pipeline, static resources) =================
extern "C" void kernel_launch(void* const* d_in, const int* in_sizes, int n_in,
                              void* d_out, int out_size) {
    const int*   tok  = (const int*)d_in[0];
    const float* hid  = (const float*)d_in[1];
    const float* cell = (const float*)d_in[2];
    const float* enc  = (const float*)d_in[3];
    const float* emb  = (const float*)d_in[4];
    const float* Wenc = (const float*)d_in[5];
    const float* Wdec = (const float*)d_in[6];
    const float* vat  = (const float*)d_in[7];
    const float* Wih  = (const float*)d_in[8];
    const float* Whh  = (const float*)d_in[9];
    const float* bih  = (const float*)d_in[10];
    const float* bhh  = (const float*)d_in[11];
    const float* Wout = (const float*)d_in[12];
    const float* bout = (const float*)d_in[13];
    float* out = (float*)d_out;

    const long long full = (long long)BB * VV + 2LL * BB * HH + (long long)BB * TT;
    bool has_aux = ((long long)out_size >= full);
    float* out_h = has_aux ? out + (size_t)BB * VV : nullptr;
    float* out_c = has_aux ? out + (size_t)BB * VV + BB * HH : nullptr;
    float* out_a = has_aux ? out + (size_t)BB * VV + 2 * BB * HH : nullptr;

    static bool s_init = false;
    static cudaStream_t s2, s3;
    static cudaEvent_t evF, evDec, evW, evS0, evS1, evC;
    if (!s_init) {
        s_init = true;
        cudaStreamCreateWithFlags(&s2, cudaStreamNonBlocking);
        cudaStreamCreateWithFlags(&s3, cudaStreamNonBlocking);
        cudaEventCreateWithFlags(&evF,   cudaEventDisableTiming);
        cudaEventCreateWithFlags(&evDec, cudaEventDisableTiming);
        cudaEventCreateWithFlags(&evW,   cudaEventDisableTiming);
        cudaEventCreateWithFlags(&evS0,  cudaEventDisableTiming);
        cudaEventCreateWithFlags(&evS1,  cudaEventDisableTiming);
        cudaEventCreateWithFlags(&evC,   cudaEventDisableTiming);
        cudaFuncSetAttribute(k_scores_mma,
                             cudaFuncAttributeMaxDynamicSharedMemorySize, SC_TOT);
        cudaFuncSetAttribute(k_logits_mma,
                             cudaFuncAttributeMaxDynamicSharedMemorySize, LG_TOT);
    }

    // fork
    cudaEventRecord(evF, 0);
    cudaStreamWaitEvent(s2, evF, 0);

    // s2: scores prereqs, then Wout fp16 round (hidden under scores)
    k_split_w<<<(HH * HH + 255) / 256, 256, 0, s2>>>(Wenc);
    k_dec<<<dim3(8, BB), 256, 0, s2>>>(hid, Wdec);
    cudaEventRecord(evDec, s2);
    k_split_wout<<<(int)(((size_t)VV * K2H / 4) / 256), 256, 0, s2>>>(Wout);
    cudaEventRecord(evW, s2);

    // stream 0: scores half 0 (512 CTAs, 512 thr, fused convert)
    cudaStreamWaitEvent(0, evDec, 0);
    k_scores_mma<<<32 * 16, 512, SC_TOT>>>(enc, vat, 0);
    cudaEventRecord(evS0, 0);

    // s3: scores half 1 — concurrent CTA pool with half 0
    cudaStreamWaitEvent(s3, evDec, 0);
    k_scores_mma<<<32 * 16, 512, SC_TOT, s3>>>(enc, vat, 32);
    cudaEventRecord(evS1, s3);

    // s2: softmax + ctx for half 0, overlapped with scores half 1 drain
    cudaStreamWaitEvent(s2, evS0, 0);
    k_softmax<<<32, 256, 0, s2>>>(out_a, 0);
    k_ctx<<<dim3(8, 32), 512, 0, s2>>>(enc, 0);
    cudaEventRecord(evC, s2);

    // stream 0: half 1 softmax/ctx + tail
    cudaStreamWaitEvent(0, evS1, 0);
    k_softmax<<<32, 256>>>(out_a, 32);
    k_ctx<<<dim3(8, 32), 512>>>(enc, 32);
    cudaStreamWaitEvent(0, evC, 0);
    k_ctxred<<<32, 1024>>>();
    k_gates<<<G4H / 64, 256>>>(tok, emb, hid, Wih, Whh, bih, bhh);
    k_lstm<<<32, 1024>>>(cell, out_h, out_c);
    cudaStreamWaitEvent(0, evW, 0);
    k_logits_mma<<<(VV + 127) / 128, 256, LG_TOT>>>(bout, out);
}

// round 17
// speedup vs baseline: 1.8158x; 1.0205x over previous
#include <cuda_runtime.h>
#include <cuda_bf16.h>
#include <cuda_fp16.h>
#include <math.h>
#include <stdint.h>

#define BB 64
#define TT 2048
#define HH 512
#define EE 256
#define VV 50000
#define G4H 2048   /* 4*H  */
#define K2H 1024   /* 2*H  */

// ---------------- scratch (device globals; no allocation) ----------------
__device__ float g_dec[BB * HH];          // h @ W_dec.T          (B,H)
__device__ float g_scores[BB * TT];       // attention scores     (B,T)
__device__ float g_attn[BB * TT];         // softmax(scores)      (B,T)
__device__ float g_ctxp[8 * BB * HH];     // context partials     (8,B,H)
__device__ float g_ctx[BB * HH];          // context              (B,H)
__device__ float g_gates[BB * G4H];       // LSTM gates           (B,4H)
// fp16 weight for the scores GEMM (enc converted in-kernel)
__device__ __half g_Wh[HH * HH];
// fp16 operands for the logits GEMM (W single, X hi/lo split)
__device__ __half g_Wo16[(size_t)VV * K2H];           // 102.4 MB
__device__ __half g_Xh16[BB * K2H];                   // [h_new, ctx] hi
__device__ __half g_Xl16[BB * K2H];                   // [h_new, ctx] lo

// ---------------- packed f32x2 helpers (FFMA2 path, small GEMMs) ----------------
__device__ __forceinline__ unsigned long long pk2(float lo, float hi) {
    unsigned long long r;
    asm("mov.b64 %0, {%1, %2};" : "=l"(r)
        : "r"(__float_as_uint(lo)), "r"(__float_as_uint(hi)));
    return r;
}
__device__ __forceinline__ unsigned long long pkdup(float v) {
    unsigned long long r;
    asm("mov.b64 %0, {%1, %1};" : "=l"(r) : "r"(__float_as_uint(v)));
    return r;
}
__device__ __forceinline__ void fma2(unsigned long long& d,
                                     unsigned long long a,
                                     unsigned long long b) {
    asm("fma.rn.f32x2 %0, %1, %2, %0;" : "+l"(d) : "l"(a), "l"(b));
}
__device__ __forceinline__ float2 upk2(unsigned long long v) {
    unsigned int lo, hi;
    asm("mov.b64 {%0, %1}, %2;" : "=r"(lo), "=r"(hi) : "l"(v));
    return make_float2(__uint_as_float(lo), __uint_as_float(hi));
}
__device__ __forceinline__ float sigf(float x) { return 1.f / (1.f + expf(-x)); }

// ---------------- smem / async / mma helpers (baseline PTX, sm_80+) ----------------
__device__ __forceinline__ uint32_t smem_u32(const void* p) {
    uint32_t a;
    asm("{ .reg .u64 t; cvta.to.shared.u64 t, %1; cvt.u32.u64 %0, t; }"
        : "=r"(a) : "l"(p));
    return a;
}
__device__ __forceinline__ void cpa16(uint32_t dst, const void* src) {
    asm volatile("cp.async.cg.shared.global [%0], [%1], 16;" :: "r"(dst), "l"(src));
}
#define CPA_COMMIT() asm volatile("cp.async.commit_group;" ::: "memory")
#define CPA_WAIT1()  asm volatile("cp.async.wait_group 1;" ::: "memory")
__device__ __forceinline__ uint32_t swz(uint32_t off) { return off ^ ((off >> 3) & 0x70); }

__device__ __forceinline__ void ldm4(uint32_t& r0, uint32_t& r1,
                                     uint32_t& r2, uint32_t& r3, uint32_t addr) {
    asm volatile("ldmatrix.sync.aligned.m8n8.x4.shared.b16 {%0,%1,%2,%3}, [%4];"
        : "=r"(r0), "=r"(r1), "=r"(r2), "=r"(r3) : "r"(addr));
}
__device__ __forceinline__ void mma16816h(float* d, const uint32_t* a,
                                          const uint32_t* bf) {
    asm volatile("mma.sync.aligned.m16n8k16.row.col.f32.f16.f16.f32 "
        "{%0,%1,%2,%3}, {%4,%5,%6,%7}, {%8,%9}, {%0,%1,%2,%3};"
        : "+f"(d[0]), "+f"(d[1]), "+f"(d[2]), "+f"(d[3])
        : "r"(a[0]), "r"(a[1]), "r"(a[2]), "r"(a[3]), "r"(bf[0]), "r"(bf[1]));
}
__device__ __forceinline__ float tanhx(float x) {
    float e2 = __expf(2.f * x);
    return 1.f - __fdividef(2.f, e2 + 1.f);
}

// ================= prep: fp16 rounding =================
__global__ void k_split_w(const float* __restrict__ W) {
    int i = blockIdx.x * 256 + threadIdx.x;
    if (i < HH * HH) g_Wh[i] = __float2half_rn(W[i]);
}
__global__ void k_split_wout(const float* __restrict__ W) {
    size_t i = (size_t)blockIdx.x * 256 + threadIdx.x;  // x4 vectorized, exact
    float4 v = ((const float4*)W)[i];
    __half2 p0 = __floats2half2_rn(v.x, v.y);
    __half2 p1 = __floats2half2_rn(v.z, v.w);
    ((__half2*)g_Wo16)[i * 2 + 0] = p0;
    ((__half2*)g_Wo16)[i * 2 + 1] = p1;
}

// ================= K1: dec = h @ W_dec.T  (one warp per output) =================
__global__ void k_dec(const float* __restrict__ hid,
                      const float* __restrict__ Wdec) {
    __shared__ float hs[HH];
    const int b = blockIdx.y;
    const int tid = threadIdx.x, wid = tid >> 5, lane = tid & 31;
    for (int i = tid; i < HH; i += 256) hs[i] = hid[b * HH + i];
    __syncthreads();
#pragma unroll
    for (int j = 0; j < 8; ++j) {                 // 8 warps x 8 h each
        int h = blockIdx.x * 64 + wid * 8 + j;
        const float4* w = (const float4*)(Wdec + (size_t)h * HH);
        float s = 0.f;
#pragma unroll
        for (int i = 0; i < 4; ++i) {
            int k4 = lane + i * 32;
            float4 wv = w[k4];
            s += wv.x * hs[k4 * 4 + 0] + wv.y * hs[k4 * 4 + 1]
               + wv.z * hs[k4 * 4 + 2] + wv.w * hs[k4 * 4 + 3];
        }
#pragma unroll
        for (int m = 16; m >= 1; m >>= 1)
            s += __shfl_xor_sync(0xffffffffu, s, m);
        if (lane == 0) g_dec[b * HH + h] = s;
    }
}

// ================= K2: scores — fused convert + HMMA, 2 CTA/SM =================
// Per CTA: 64 t-rows. A (64x512 fp16) persistent in smem (8 swizzled 8KB
// chunks, converted from enc fp32 at start); B (Wh) double-buffered 16KB
// stages; D = A·Wh^T per 128-col n-chunk. 256 thr, warp tile 32m x 32n (2x4).
#define SC_SA   0                      // persistent A: 8 x 8192 = 65536
#define SC_SB   65536                  // B stages: 2 x 16384
#define SC_DEC  98304                  // dec row  (2048 B)
#define SC_V    100352                 // v_attn   (2048 B)
#define SC_SC   102400                 // score buf 4x64 floats (1024 B)
#define SC_TOT  103424

__global__ void __launch_bounds__(256, 2)
k_scores_mma(const float* __restrict__ enc, const float* __restrict__ vat,
             int boff) {
    extern __shared__ __align__(1024) char smem[];
    const uint32_t sb = smem_u32(smem);
    float* decs = (float*)(smem + SC_DEC);
    float* vs   = (float*)(smem + SC_V);
    float* sbuf = (float*)(smem + SC_SC);
    const int tid = threadIdx.x, lane = tid & 31, wid = tid >> 5;
    const int wm = wid & 1, wn = wid >> 1;       // warp tile 32m x 32n (2x4)
    const int b = (blockIdx.x >> 5) + boff;
    const int t0 = (blockIdx.x & 31) * 64;

    for (int i = tid; i < HH; i += 256) {
        decs[i] = g_dec[b * HH + i];
        vs[i]   = vat[i];
    }

    // convert A: enc fp32 (64 x 512) -> persistent swizzled fp16 smem
    {
        const float4* ep = (const float4*)(enc + ((size_t)(b * TT + t0)) * HH);
        // chunk ch holds cols [ch*64, ch*64+64); 1024 f4 per chunk
#pragma unroll 8
        for (int idx = tid; idx < 8192; idx += 256) {
            int ch = idx >> 10, rem = idx & 1023;
            int r = rem >> 4, c0 = rem & 15;
            float4 v = ep[r * 128 + ch * 16 + c0];
            __half2 p0 = __floats2half2_rn(v.x, v.y);
            __half2 p1 = __floats2half2_rn(v.z, v.w);
            uint2 u;
            u.x = *(uint32_t*)&p0;
            u.y = *(uint32_t*)&p1;
            *(uint2*)(smem + SC_SA + ch * 8192 + swz(r * 128 + c0 * 8)) = u;
        }
    }
    __syncthreads();

    auto fillB = [&](int st, int it, int n0) {
        const __half* Bs = g_Wh + (size_t)n0 * HH + it * 64;
#pragma unroll
        for (int l = 0; l < 4; ++l) {            // B: 128 h-cols x 8 segs
            int idx = tid + l * 256;
            int r = idx >> 3, sg = idx & 7;
            cpa16(sb + SC_SB + st * 16384 + swz(r * 128 + sg * 16),
                  (const char*)(Bs + (size_t)r * HH) + sg * 16);
        }
    };

    float rsc[4] = {0.f, 0.f, 0.f, 0.f};         // 4 owned rows

    for (int n = 0; n < 4; ++n) {
        const int n0 = n * 128;
        float d[2][4][4];
#pragma unroll
        for (int i = 0; i < 2; ++i)
#pragma unroll
            for (int j = 0; j < 4; ++j)
#pragma unroll
                for (int q = 0; q < 4; ++q) d[i][j][q] = 0.f;

        fillB(0, 0, n0); CPA_COMMIT();
        fillB(1, 1, n0); CPA_COMMIT();

        for (int it = 0; it < 8; ++it) {
            const int st = it & 1;
            CPA_WAIT1();
            __syncthreads();
            const uint32_t abase = sb + SC_SA + it * 8192;    // persistent A chunk
            const uint32_t bbase = sb + SC_SB + st * 16384;
#pragma unroll
            for (int ks = 0; ks < 4; ++ks) {     // 4 x k16 per 64-chunk
                uint32_t a[2][4];
#pragma unroll
                for (int i = 0; i < 2; ++i) {
                    int row = wm * 32 + i * 16 + (lane & 15);
                    int off = row * 128 + ks * 32 + (lane >> 4) * 16;
                    ldm4(a[i][0], a[i][1], a[i][2], a[i][3], abase + swz(off));
                }
                uint32_t bf[2][4];
#pragma unroll
                for (int p = 0; p < 2; ++p) {
                    int row = wn * 32 + p * 16 + (lane & 7) + (lane >> 4) * 8;
                    int off = row * 128 + ks * 32 + ((lane >> 3) & 1) * 16;
                    ldm4(bf[p][0], bf[p][1], bf[p][2], bf[p][3], bbase + swz(off));
                }
#pragma unroll
                for (int i = 0; i < 2; ++i)
#pragma unroll
                    for (int j = 0; j < 4; ++j)
                        mma16816h(d[i][j], a[i], &bf[j >> 1][(j & 1) * 2]);
            }
            __syncthreads();
            if (it + 2 < 8) fillB(st, it + 2, n0);
            CPA_COMMIT();
        }
        // epilogue: tanh(+dec)·v into per-row partials
#pragma unroll
        for (int i = 0; i < 2; ++i)
#pragma unroll
            for (int j = 0; j < 4; ++j) {
                int c = n0 + wn * 32 + j * 8 + (lane & 3) * 2;
                float v0 = vs[c], v1 = vs[c + 1];
                float dc0 = decs[c], dc1 = decs[c + 1];
                rsc[i * 2 + 0] += tanhx(d[i][j][0] + dc0) * v0
                                + tanhx(d[i][j][1] + dc1) * v1;
                rsc[i * 2 + 1] += tanhx(d[i][j][2] + dc0) * v0
                                + tanhx(d[i][j][3] + dc1) * v1;
            }
    }

    // quad reduce (lanes share rows, own disjoint cols)
#pragma unroll
    for (int r = 0; r < 4; ++r) {
        rsc[r] += __shfl_xor_sync(0xffffffffu, rsc[r], 1);
        rsc[r] += __shfl_xor_sync(0xffffffffu, rsc[r], 2);
    }
    if ((lane & 3) == 0) {
        int g = lane >> 2;
#pragma unroll
        for (int i = 0; i < 2; ++i)
#pragma unroll
            for (int h = 0; h < 2; ++h)
                sbuf[wn * 64 + wm * 32 + i * 16 + h * 8 + g] = rsc[i * 2 + h];
    }
    __syncthreads();
    if (tid < 64)
        g_scores[b * TT + t0 + tid] =
            (sbuf[tid] + sbuf[64 + tid]) + (sbuf[128 + tid] + sbuf[192 + tid]);
}

// ================= K3: softmax over T per batch =================
__global__ void k_softmax(float* __restrict__ attn_out, int boff) {
    __shared__ float red[256];
    int b = blockIdx.x + boff, tid = threadIdx.x;
    const float* s = g_scores + b * TT;
    float m = -3.4e38f;
    for (int i = tid; i < TT; i += 256) m = fmaxf(m, s[i]);
    red[tid] = m; __syncthreads();
    for (int st = 128; st > 0; st >>= 1) {
        if (tid < st) red[tid] = fmaxf(red[tid], red[tid + st]);
        __syncthreads();
    }
    float M = red[0]; __syncthreads();
    float sum = 0.f;
    for (int i = tid; i < TT; i += 256) {
        float e = expf(s[i] - M);
        g_attn[b * TT + i] = e;
        sum += e;
    }
    red[tid] = sum; __syncthreads();
    for (int st = 128; st > 0; st >>= 1) {
        if (tid < st) red[tid] += red[tid + st];
        __syncthreads();
    }
    float inv = 1.f / red[0];
    for (int i = tid; i < TT; i += 256) {
        float a = g_attn[b * TT + i] * inv;
        g_attn[b * TT + i] = a;
        if (attn_out) attn_out[b * TT + i] = a;
    }
}

// ================= K4: context partials (split-8 over T) =================
__global__ void k_ctx(const float* __restrict__ enc, int boff) {
    __shared__ float as_[256];
    int s = blockIdx.x, b = blockIdx.y + boff;
    int h = threadIdx.x;  // 512 threads
    if (h < 256) as_[h] = g_attn[b * TT + s * 256 + h];
    __syncthreads();
    const float* ep = enc + ((size_t)b * TT + s * 256) * HH + h;
    float a0 = 0.f, a1 = 0.f, a2 = 0.f, a3 = 0.f;
#pragma unroll 4
    for (int t = 0; t < 256; t += 4) {
        a0 += as_[t + 0] * ep[(size_t)(t + 0) * HH];
        a1 += as_[t + 1] * ep[(size_t)(t + 1) * HH];
        a2 += as_[t + 2] * ep[(size_t)(t + 2) * HH];
        a3 += as_[t + 3] * ep[(size_t)(t + 3) * HH];
    }
    g_ctxp[(s * BB + b) * HH + h] = (a0 + a1) + (a2 + a3);
}

__global__ void k_ctxred() {
    int i = blockIdx.x * blockDim.x + threadIdx.x;  // 32768
    float s = 0.f;
#pragma unroll
    for (int p = 0; p < 8; ++p) s += g_ctxp[p * BB * HH + i];
    g_ctx[i] = s;
}

// ================= K5: gates GEMM =================
__global__ void __launch_bounds__(256) k_gates(const int* __restrict__ tok,
                                               const float* __restrict__ emb,
                                               const float* __restrict__ hid,
                                               const float* __restrict__ Wih,
                                               const float* __restrict__ Whh,
                                               const float* __restrict__ bih,
                                               const float* __restrict__ bhh) {
    __shared__ float Ws[32][68];
    __shared__ float Xs[32][68];
    const int tid = threadIdx.x;
    const int g0 = blockIdx.x * 64;
    const int tx = tid & 15, ty = tid >> 4;
    const int r0 = ty * 4, c0 = tx * 4;
    unsigned long long acc[4][2];
#pragma unroll
    for (int i = 0; i < 4; ++i) { acc[i][0] = 0ull; acc[i][1] = 0ull; }

    for (int kt = 0; kt < 40; ++kt) {
        int kbase = kt * 32;
#pragma unroll
        for (int l = 0; l < 2; ++l) {
            int idx = tid + l * 256;
            int row = idx >> 3, kv = (idx & 7) * 4;
            int k = kbase + kv;
            const float* src = (k < 768)
                ? (Wih + (size_t)(g0 + row) * 768 + k)
                : (Whh + (size_t)(g0 + row) * 512 + (k - 768));
            float4 v = *(const float4*)src;
            Ws[kv + 0][row] = v.x; Ws[kv + 1][row] = v.y;
            Ws[kv + 2][row] = v.z; Ws[kv + 3][row] = v.w;
        }
#pragma unroll
        for (int l = 0; l < 2; ++l) {
            int idx = tid + l * 256;
            int bc = idx >> 3, kv = (idx & 7) * 4;
            int k = kbase + kv;
            const float* src;
            if (k < 256)      src = emb + (size_t)tok[bc] * EE + k;
            else if (k < 768) src = g_ctx + bc * HH + (k - 256);
            else              src = hid + bc * HH + (k - 768);
            float4 v = *(const float4*)src;
            Xs[kv + 0][bc] = v.x; Xs[kv + 1][bc] = v.y;
            Xs[kv + 2][bc] = v.z; Xs[kv + 3][bc] = v.w;
        }
        __syncthreads();
#pragma unroll 8
        for (int kk = 0; kk < 32; ++kk) {
            float4 av = *(const float4*)&Ws[kk][r0];
            float4 xv = *(const float4*)&Xs[kk][c0];
            unsigned long long X0 = pk2(xv.x, xv.y);
            unsigned long long X1 = pk2(xv.z, xv.w);
            unsigned long long Ad0 = pkdup(av.x);
            unsigned long long Ad1 = pkdup(av.y);
            unsigned long long Ad2 = pkdup(av.z);
            unsigned long long Ad3 = pkdup(av.w);
            fma2(acc[0][0], Ad0, X0); fma2(acc[0][1], Ad0, X1);
            fma2(acc[1][0], Ad1, X0); fma2(acc[1][1], Ad1, X1);
            fma2(acc[2][0], Ad2, X0); fma2(acc[2][1], Ad2, X1);
            fma2(acc[3][0], Ad3, X0); fma2(acc[3][1], Ad3, X1);
        }
        __syncthreads();
    }
#pragma unroll
    for (int i = 0; i < 4; ++i) {
        int g = g0 + r0 + i;
        float bias = bih[g] + bhh[g];
#pragma unroll
        for (int p = 0; p < 2; ++p) {
            float2 e = upk2(acc[i][p]);
            int bc = c0 + 2 * p;
            g_gates[bc * G4H + g]       = e.x + bias;
            g_gates[(bc + 1) * G4H + g] = e.y + bias;
        }
    }
}

// ================= K6: LSTM pointwise; emit split-fp16 xout =================
__global__ void k_lstm(const float* __restrict__ cell,
                       float* __restrict__ hout, float* __restrict__ cout) {
    int i = blockIdx.x * blockDim.x + threadIdx.x;  // 32768
    int b = i >> 9, h = i & 511;
    float ig = g_gates[b * G4H + h];
    float fg = g_gates[b * G4H + 512 + h];
    float gg = g_gates[b * G4H + 1024 + h];
    float og = g_gates[b * G4H + 1536 + h];
    float c = sigf(fg) * cell[i] + sigf(ig) * tanhf(gg);
    float hn = sigf(og) * tanhf(c);
    if (hout) { hout[i] = hn; cout[i] = c; }
    float cx = g_ctx[i];
    __half hh = __float2half_rn(hn);
    __half ch = __float2half_rn(cx);
    g_Xh16[b * K2H + h]       = hh;
    g_Xl16[b * K2H + h]       = __float2half_rn(hn - __half2float(hh));
    g_Xh16[b * K2H + 512 + h] = ch;
    g_Xl16[b * K2H + 512 + h] = __float2half_rn(cx - __half2float(ch));
}

// ================= K7: logits via HMMA fp16 (W single, X hi/lo) =================
#define LG_SA   0                      // Wo stages: 2 x 16384
#define LG_SB   32768                  // Xh/Xl stages: 2 x 16384
#define LG_TOT  65536

__global__ void __launch_bounds__(256, 2)
k_logits_mma(const float* __restrict__ bout, float* __restrict__ out) {
    extern __shared__ __align__(1024) char smem[];
    const uint32_t sb = smem_u32(smem);
    const int tid = threadIdx.x, lane = tid & 31, wid = tid >> 5;
    const int wm = wid & 3, wn = wid >> 2;       // warp tile (32 m) x (32 n)
    const int v0 = blockIdx.x * 128;

    auto fill = [&](int st, int kt) {
        const int kbase = kt * 64;
#pragma unroll
        for (int l = 0; l < 4; ++l) {            // A: 128 rows x 8 segs
            int idx = tid + l * 256;
            int r = idx >> 3, sg = idx & 7;
            int vr = v0 + r; if (vr >= VV) vr = VV - 1;
            cpa16(sb + LG_SA + st * 16384 + swz(r * 128 + sg * 16),
                  (const char*)(g_Wo16 + (size_t)vr * K2H + kbase) + sg * 16);
        }
#pragma unroll
        for (int l = 0; l < 2; ++l) {            // B: 64 rows x 8 segs (h & l)
            int idx = tid + l * 256;
            int r = idx >> 3, sg = idx & 7;
            uint32_t so = swz(r * 128 + sg * 16);
            cpa16(sb + LG_SB + st * 16384 + so,
                  (const char*)(g_Xh16 + (size_t)r * K2H + kbase) + sg * 16);
            cpa16(sb + LG_SB + st * 16384 + 8192 + so,
                  (const char*)(g_Xl16 + (size_t)r * K2H + kbase) + sg * 16);
        }
    };

    float d[2][4][4];
#pragma unroll
    for (int i = 0; i < 2; ++i)
#pragma unroll
        for (int j = 0; j < 4; ++j)
#pragma unroll
            for (int q = 0; q < 4; ++q) d[i][j][q] = 0.f;

    fill(0, 0); CPA_COMMIT();
    fill(1, 1); CPA_COMMIT();

    for (int kt = 0; kt < 16; ++kt) {
        const int st = kt & 1;
        CPA_WAIT1();
        __syncthreads();
        const uint32_t ab  = sb + LG_SA + st * 16384;
        const uint32_t bhb = sb + LG_SB + st * 16384;
        const uint32_t blb = bhb + 8192;
#pragma unroll
        for (int ks = 0; ks < 4; ++ks) {
            uint32_t a[2][4];
#pragma unroll
            for (int i = 0; i < 2; ++i) {
                int row = wm * 32 + i * 16 + (lane & 15);
                uint32_t so = swz(row * 128 + ks * 32 + (lane >> 4) * 16);
                ldm4(a[i][0], a[i][1], a[i][2], a[i][3], ab + so);
            }
            uint32_t bh[2][4], bl[2][4];
#pragma unroll
            for (int p = 0; p < 2; ++p) {
                int row = wn * 32 + p * 16 + (lane & 7) + (lane >> 4) * 8;
                uint32_t so = swz(row * 128 + ks * 32 + ((lane >> 3) & 1) * 16);
                ldm4(bh[p][0], bh[p][1], bh[p][2], bh[p][3], bhb + so);
                ldm4(bl[p][0], bl[p][1], bl[p][2], bl[p][3], blb + so);
            }
#pragma unroll
            for (int i = 0; i < 2; ++i)
#pragma unroll
                for (int j = 0; j < 4; ++j) {
                    mma16816h(d[i][j], a[i], &bh[j >> 1][(j & 1) * 2]);
                    mma16816h(d[i][j], a[i], &bl[j >> 1][(j & 1) * 2]);
                }
        }
        __syncthreads();
        if (kt + 2 < 16) fill(st, kt + 2);
        CPA_COMMIT();
    }

    // epilogue: transpose through smem (overlays stages), bias, coalesced write
    __syncthreads();
    float* sbuf = (float*)smem;   // [64][132]
#pragma unroll
    for (int i = 0; i < 2; ++i)
#pragma unroll
        for (int j = 0; j < 4; ++j)
#pragma unroll
            for (int q = 0; q < 4; ++q) {
                int r = wm * 32 + i * 16 + (lane >> 2) + (q >> 1) * 8;
                int c = wn * 32 + j * 8 + (lane & 3) * 2 + (q & 1);
                sbuf[c * 132 + r] = d[i][j][q];
            }
    __syncthreads();
#pragma unroll
    for (int l = 0; l < 32; ++l) {
        int idx = tid + l * 256;
        int bc = idx >> 7, r = idx & 127;
        int v = v0 + r;
        if (v < VV) out[(size_t)bc * VV + v] = sbuf[bc * 132 + r] + bout[v];
    }
}

// ================= host launcher (fused-convert pipeline, static resources) =================
extern "C" void kernel_launch(void* const* d_in, const int* in_sizes, int n_in,
                              void* d_out, int out_size) {
    const int*   tok  = (const int*)d_in[0];
    const float* hid  = (const float*)d_in[1];
    const float* cell = (const float*)d_in[2];
    const float* enc  = (const float*)d_in[3];
    const float* emb  = (const float*)d_in[4];
    const float* Wenc = (const float*)d_in[5];
    const float* Wdec = (const float*)d_in[6];
    const float* vat  = (const float*)d_in[7];
    const float* Wih  = (const float*)d_in[8];
    const float* Whh  = (const float*)d_in[9];
    const float* bih  = (const float*)d_in[10];
    const float* bhh  = (const float*)d_in[11];
    const float* Wout = (const float*)d_in[12];
    const float* bout = (const float*)d_in[13];
    float* out = (float*)d_out;

    const long long full = (long long)BB * VV + 2LL * BB * HH + (long long)BB * TT;
    bool has_aux = ((long long)out_size >= full);
    float* out_h = has_aux ? out + (size_t)BB * VV : nullptr;
    float* out_c = has_aux ? out + (size_t)BB * VV + BB * HH : nullptr;
    float* out_a = has_aux ? out + (size_t)BB * VV + 2 * BB * HH : nullptr;

    static bool s_init = false;
    static cudaStream_t s2, s3;
    static cudaEvent_t evF, evDec, evW, evS0, evS1, evC;
    if (!s_init) {
        s_init = true;
        cudaStreamCreateWithFlags(&s2, cudaStreamNonBlocking);
        cudaStreamCreateWithFlags(&s3, cudaStreamNonBlocking);
        cudaEventCreateWithFlags(&evF,   cudaEventDisableTiming);
        cudaEventCreateWithFlags(&evDec, cudaEventDisableTiming);
        cudaEventCreateWithFlags(&evW,   cudaEventDisableTiming);
        cudaEventCreateWithFlags(&evS0,  cudaEventDisableTiming);
        cudaEventCreateWithFlags(&evS1,  cudaEventDisableTiming);
        cudaEventCreateWithFlags(&evC,   cudaEventDisableTiming);
        cudaFuncSetAttribute(k_scores_mma,
                             cudaFuncAttributeMaxDynamicSharedMemorySize, SC_TOT);
        cudaFuncSetAttribute(k_logits_mma,
                             cudaFuncAttributeMaxDynamicSharedMemorySize, LG_TOT);
    }

    // fork
    cudaEventRecord(evF, 0);
    cudaStreamWaitEvent(s2, evF, 0);

    // s2: scores prereqs, then Wout fp16 round (hidden under scores)
    k_split_w<<<(HH * HH + 255) / 256, 256, 0, s2>>>(Wenc);
    k_dec<<<dim3(8, BB), 256, 0, s2>>>(hid, Wdec);
    cudaEventRecord(evDec, s2);
    k_split_wout<<<(int)(((size_t)VV * K2H / 4) / 256), 256, 0, s2>>>(Wout);
    cudaEventRecord(evW, s2);

    // stream 0: scores half 0 (1024 CTAs, 256 thr, 2 CTA/SM)
    cudaStreamWaitEvent(0, evDec, 0);
    k_scores_mma<<<32 * 32, 256, SC_TOT>>>(enc, vat, 0);
    cudaEventRecord(evS0, 0);

    // s3: scores half 1 — concurrent CTA pool with half 0
    cudaStreamWaitEvent(s3, evDec, 0);
    k_scores_mma<<<32 * 32, 256, SC_TOT, s3>>>(enc, vat, 32);
    cudaEventRecord(evS1, s3);

    // s2: softmax + ctx for half 0, overlapped with scores half 1 drain
    cudaStreamWaitEvent(s2, evS0, 0);
    k_softmax<<<32, 256, 0, s2>>>(out_a, 0);
    k_ctx<<<dim3(8, 32), 512, 0, s2>>>(enc, 0);
    cudaEventRecord(evC, s2);

    // stream 0: half 1 softmax/ctx + tail
    cudaStreamWaitEvent(0, evS1, 0);
    k_softmax<<<32, 256>>>(out_a, 32);
    k_ctx<<<dim3(8, 32), 512>>>(enc, 32);
    cudaStreamWaitEvent(0, evC, 0);
    k_ctxred<<<32, 1024>>>();
    k_gates<<<G4H / 64, 256>>>(tok, emb, hid, Wih, Whh, bih, bhh);
    k_lstm<<<32, 1024>>>(cell, out_h, out_c);
    cudaStreamWaitEvent(0, evW, 0);
    k_logits_mma<<<(VV + 127) / 128, 256, LG_TOT>>>(bout, out);
}